// round 9
// baseline (speedup 1.0000x reference)
#include <cuda_runtime.h>
#include <cuda_bf16.h>
#include <cstdint>
#include <math.h>

// Problem constants (static per reference)
#define NBATCH 8
#define LQ     5440
#define TTOK   (NBATCH*LQ)      // 43520
#define DIM    256
#define NHEAD  8
#define HD     32
#define NLVL   4
#define NPT    4
#define DFF    1024

// Scratch (device globals; no runtime allocation)
__device__ __nv_bfloat16 g_srcb [(size_t)TTOK*DIM];
__device__ __nv_bfloat16 g_qb   [(size_t)TTOK*DIM];
__device__ __nv_bfloat16 g_valbf[(size_t)TTOK*DIM];
__device__ float         g_offattn[(size_t)TTOK*384];
__device__ __nv_bfloat16 g_sampb[(size_t)TTOK*DIM];
__device__ float         g_src2 [(size_t)TTOK*DIM];
__device__ float         g_x    [(size_t)TTOK*DIM];
__device__ __nv_bfloat16 g_xb   [(size_t)TTOK*DIM];
__device__ __nv_bfloat16 g_hidb [(size_t)TTOK*DFF];
__device__ float         g_ffn  [(size_t)TTOK*DIM];
// Transposed ([N][K]) bf16 weights
__device__ __nv_bfloat16 g_wtv  [256*256];
__device__ __nv_bfloat16 g_wtoa [384*256];
__device__ __nv_bfloat16 g_wtout[256*256];
__device__ __nv_bfloat16 g_wt1  [1024*256];
__device__ __nv_bfloat16 g_wt2  [256*1024];
__device__ float         g_boa  [384];

// ---------------------------------------------------------------------------
// Helpers
// ---------------------------------------------------------------------------
__device__ __forceinline__ uint32_t smem_u32(const void* p) {
    uint32_t a;
    asm("{ .reg .u64 t; cvta.to.shared.u64 t, %1; cvt.u32.u64 %0, t; }" : "=r"(a) : "l"(p));
    return a;
}
__device__ __forceinline__ void cpasync16(uint32_t dst, const void* src) {
    asm volatile("cp.async.cg.shared.global [%0], [%1], 16;" :: "r"(dst), "l"(src));
}
#define CP_COMMIT() asm volatile("cp.async.commit_group;" ::: "memory")
#define CP_WAIT1()  asm volatile("cp.async.wait_group 1;" ::: "memory")

__device__ __forceinline__ void ldmx4(uint32_t& f0, uint32_t& f1, uint32_t& f2, uint32_t& f3,
                                      uint32_t addr) {
    asm volatile("ldmatrix.sync.aligned.m8n8.x4.shared.b16 {%0,%1,%2,%3}, [%4];"
                 : "=r"(f0), "=r"(f1), "=r"(f2), "=r"(f3) : "r"(addr));
}
__device__ __forceinline__ void mma_bf16(float* c, uint32_t a0, uint32_t a1,
                                         uint32_t a2, uint32_t a3,
                                         uint32_t b0, uint32_t b1) {
    asm volatile(
        "mma.sync.aligned.m16n8k16.row.col.f32.bf16.bf16.f32 "
        "{%0,%1,%2,%3}, {%4,%5,%6,%7}, {%8,%9}, {%0,%1,%2,%3};"
        : "+f"(c[0]), "+f"(c[1]), "+f"(c[2]), "+f"(c[3])
        : "r"(a0), "r"(a1), "r"(a2), "r"(a3), "r"(b0), "r"(b1));
}

// ---------------------------------------------------------------------------
// One-shot prep: weight transposes (fp32 [K][N] -> bf16 [N][K]), bias concat,
// src/q bf16 conversion. Single launch.
// ---------------------------------------------------------------------------
#define PREP_WBLK 2944
#define PREP_ABLK 10880
__global__ void prep_kernel(const float* __restrict__ Wv, const float* __restrict__ Wo,
                            const float* __restrict__ Wa, const float* __restrict__ Wout,
                            const float* __restrict__ W1, const float* __restrict__ W2,
                            const float* __restrict__ bo, const float* __restrict__ ba,
                            const float4* __restrict__ src, const float4* __restrict__ pos,
                            __nv_bfloat16* __restrict__ wtv, __nv_bfloat16* __restrict__ wtoa,
                            __nv_bfloat16* __restrict__ wtout, __nv_bfloat16* __restrict__ wt1,
                            __nv_bfloat16* __restrict__ wt2, float* __restrict__ boa,
                            __nv_bfloat16* __restrict__ srcb, __nv_bfloat16* __restrict__ qb)
{
    int b = blockIdx.x;
    if (b < PREP_WBLK) {
        int idx = b * 256 + threadIdx.x;  // 0..753663
        float v; __nv_bfloat16* dst;
        if (idx < 65536) {                       // Wv [256,256]
            int n = idx >> 8, k = idx & 255; v = Wv[k * 256 + n]; dst = wtv + idx;
        } else if (idx < 163840) {               // Woa [384,256] = [Wo|Wa]
            int j = idx - 65536; int n = j >> 8, k = j & 255;
            v = (n < 256) ? Wo[k * 256 + n] : Wa[k * 128 + (n - 256)]; dst = wtoa + j;
        } else if (idx < 229376) {               // Wout [256,256]
            int j = idx - 163840; int n = j >> 8, k = j & 255; v = Wout[k * 256 + n]; dst = wtout + j;
        } else if (idx < 491520) {               // W1 [1024,256]
            int j = idx - 229376; int n = j >> 8, k = j & 255; v = W1[k * 1024 + n]; dst = wt1 + j;
        } else {                                 // W2 [256,1024]
            int j = idx - 491520; int n = j >> 10, k = j & 1023; v = W2[k * 256 + n]; dst = wt2 + j;
        }
        *dst = __float2bfloat16(v);
    } else if (b < PREP_WBLK + PREP_ABLK) {
        int idx = (b - PREP_WBLK) * 256 + threadIdx.x;   // float4 index
        float4 s = src[idx], p = pos[idx];
        __nv_bfloat162 s01 = __float22bfloat162_rn(make_float2(s.x, s.y));
        __nv_bfloat162 s23 = __float22bfloat162_rn(make_float2(s.z, s.w));
        __nv_bfloat162 q01 = __float22bfloat162_rn(make_float2(s.x + p.x, s.y + p.y));
        __nv_bfloat162 q23 = __float22bfloat162_rn(make_float2(s.z + p.z, s.w + p.w));
        ((uint2*)srcb)[idx] = make_uint2(*(uint32_t*)&s01, *(uint32_t*)&s23);
        ((uint2*)qb)[idx]   = make_uint2(*(uint32_t*)&q01, *(uint32_t*)&q23);
    } else {
        int i = threadIdx.x;
        if (i < 384) boa[i] = (i < 256) ? bo[i] : ba[i - 256];
    }
}

// ---------------------------------------------------------------------------
// bf16 tensor GEMM (128x128 tile), cp.async 3-stage + ldmatrix.
// ---------------------------------------------------------------------------
#define BK 64
template<int ACT, int OBF>
__global__ void __launch_bounds__(256, 2)
mma_gemm(const __nv_bfloat16* __restrict__ A, const __nv_bfloat16* __restrict__ Wt,
         const float* __restrict__ bias, float* __restrict__ C,
         __nv_bfloat16* __restrict__ C16, int K, int Nc, int mtiles)
{
    extern __shared__ char smem[];
    const uint32_t sbase = smem_u32(smem);

    const int tid = threadIdx.x;
    const int wid = tid >> 5, lane = tid & 31;
    const int g = lane >> 2, tg = lane & 3;
    const int wm = wid & 1, wn = wid >> 1;
    const int mt = blockIdx.x % mtiles;
    const int nt = blockIdx.x / mtiles;
    const int row0 = mt * 128, col0 = nt * 128;

    const int a_r  = (lane & 7) + ((lane >> 3) & 1) * 8;
    const int a_kh = (lane >> 4) & 1;
    const int b_r  = (lane & 7) + ((lane >> 4) << 3);
    const int b_kh = (lane >> 3) & 1;

    float acc[4][4][4];
#pragma unroll
    for (int i = 0; i < 4; i++)
#pragma unroll
        for (int j = 0; j < 4; j++)
#pragma unroll
            for (int k = 0; k < 4; k++) acc[i][j][k] = 0.f;

    auto load_chunk = [&](int k0, int st) {
#pragma unroll
        for (int i = 0; i < 4; i++) {
            int idx = tid + i * 256;
            int r = idx >> 3, gc = idx & 7;
            uint32_t so = (uint32_t)(r * 128 + ((gc ^ (r & 7)) << 4));
            cpasync16(sbase + st * 16384 + so, A + (size_t)(row0 + r) * K + k0 + gc * 8);
            cpasync16(sbase + 49152 + st * 16384 + so, Wt + (size_t)(col0 + r) * K + k0 + gc * 8);
        }
    };

    const int nchunk = K / BK;
    load_chunk(0, 0);
    CP_COMMIT();
    if (nchunk > 1) load_chunk(BK, 1);
    CP_COMMIT();

    for (int ch = 0; ch < nchunk; ch++) {
        CP_WAIT1();
        __syncthreads();
        if (ch + 2 < nchunk) load_chunk((ch + 2) * BK, (ch + 2) % 3);
        CP_COMMIT();

        const uint32_t Ab = sbase + (ch % 3) * 16384;
        const uint32_t Bb = sbase + 49152 + (ch % 3) * 16384;
#pragma unroll
        for (int ks = 0; ks < 4; ks++) {
            uint32_t bf[4][2];
#pragma unroll
            for (int np = 0; np < 2; np++) {
                int r = wn * 32 + np * 16 + b_r;
                uint32_t addr = Bb + r * 128 + (((ks * 2 + b_kh) ^ (r & 7)) << 4);
                ldmx4(bf[np * 2][0], bf[np * 2][1], bf[np * 2 + 1][0], bf[np * 2 + 1][1], addr);
            }
#pragma unroll
            for (int mf = 0; mf < 4; mf++) {
                int r = wm * 64 + mf * 16 + a_r;
                uint32_t addr = Ab + r * 128 + (((ks * 2 + a_kh) ^ (r & 7)) << 4);
                uint32_t a0, a1, a2, a3;
                ldmx4(a0, a1, a2, a3, addr);
#pragma unroll
                for (int nf = 0; nf < 4; nf++)
                    mma_bf16(acc[mf][nf], a0, a1, a2, a3, bf[nf][0], bf[nf][1]);
            }
        }
    }

#pragma unroll
    for (int mf = 0; mf < 4; mf++) {
#pragma unroll
        for (int nf = 0; nf < 4; nf++) {
            int row = row0 + wm * 64 + mf * 16 + g;
            int col = col0 + wn * 32 + nf * 8 + tg * 2;
            float b0 = bias[col], b1 = bias[col + 1];
            float o[4];
            o[0] = acc[mf][nf][0] + b0; o[1] = acc[mf][nf][1] + b1;
            o[2] = acc[mf][nf][2] + b0; o[3] = acc[mf][nf][3] + b1;
            if (ACT) {
#pragma unroll
                for (int i = 0; i < 4; i++) o[i] = fmaxf(o[i], 0.f);
            }
            if (OBF) {
                *(__nv_bfloat162*)(&C16[(size_t)row * Nc + col]) =
                    __float22bfloat162_rn(make_float2(o[0], o[1]));
                *(__nv_bfloat162*)(&C16[(size_t)(row + 8) * Nc + col]) =
                    __float22bfloat162_rn(make_float2(o[2], o[3]));
            } else {
                *(float2*)(&C[(size_t)row * Nc + col]) = make_float2(o[0], o[1]);
                *(float2*)(&C[(size_t)(row + 8) * Nc + col]) = make_float2(o[2], o[3]);
            }
        }
    }
}

// ---------------------------------------------------------------------------
// Deformable sampling, two-phase per warp-token:
//  Phase 1: stage offattn row (coalesced).
//  Phase 2 (plan): lane j -> head j>>2, level j&3 owns 4 points. Softmax via
//    4-lane shfl. Emits per point: 4 softmax-weighted corner weights + 4
//    precomputed byte offsets (invalid -> off 0 / cw 0, branchless).
//  Phase 3 (gather): lane (h, d8) reads plan via broadcast LDS, 4 LDG.128
//    gathers + FMA accumulation per point.
// ---------------------------------------------------------------------------
__global__ void __launch_bounds__(256)
sample_kernel(const __nv_bfloat16* __restrict__ valbf,
              const float* __restrict__ offattn,
              const float* __restrict__ ref,
              __nv_bfloat16* __restrict__ sampb)
{
    __shared__ float  sh[8][384];
    __shared__ float4 cws[8][8][16];
    __shared__ int4   ofs[8][8][16];

    const int w = threadIdx.x >> 5;
    const int t = blockIdx.x * 8 + w;
    const int lane = threadIdx.x & 31;
    const int n = t / LQ;

    // Phase 1: stage offattn row (1536B, coalesced).
    {
        const float4* rowp4 = (const float4*)(offattn + (size_t)t * 384);
        float4* sh4 = (float4*)sh[w];
#pragma unroll
        for (int i = 0; i < 3; i++) sh4[i * 32 + lane] = rowp4[i * 32 + lane];
    }
    __syncwarp();

    // Phase 2: plan. lane -> (hh = lane>>2, l = lane&3), 4 points of level l.
    {
        const int hh = lane >> 2;
        const int l  = lane & 3;
        const int Hs_[4] = {64, 32, 16, 8};
        const int St_[4] = {0, 4096, 5120, 5376};
        const float* lp = sh[w] + 256 + hh * 16;

        float myl[4];
#pragma unroll
        for (int k = 0; k < 4; k++) myl[k] = lp[l * 4 + k];
        float mx = fmaxf(fmaxf(myl[0], myl[1]), fmaxf(myl[2], myl[3]));
        mx = fmaxf(mx, __shfl_xor_sync(0xffffffffu, mx, 1));
        mx = fmaxf(mx, __shfl_xor_sync(0xffffffffu, mx, 2));
        float e[4], s = 0.f;
#pragma unroll
        for (int k = 0; k < 4; k++) { e[k] = expf(myl[k] - mx); s += e[k]; }
        s += __shfl_xor_sync(0xffffffffu, s, 1);
        s += __shfl_xor_sync(0xffffffffu, s, 2);
        const float inv = 1.f / s;

        const int HW = Hs_[l];
        const float fHW = (float)HW;
        const float invHW = 1.f / fHW;
        const float refx = ref[((size_t)t * NLVL + l) * 2 + 0];
        const float refy = ref[((size_t)t * NLVL + l) * 2 + 1];
        const float* op = sh[w] + hh * 32 + l * 8;
        // element base (bytes) for (n, level start, head)
        const int ebase = (n * LQ + St_[l]) * DIM + hh * HD;

#pragma unroll
        for (int k = 0; k < 4; k++) {
            float ox = op[k * 2 + 0];
            float oy = op[k * 2 + 1];
            float xf = (refx + ox * invHW) * fHW - 0.5f;
            float yf = (refy + oy * invHW) * fHW - 0.5f;
            float x0f = floorf(xf), y0f = floorf(yf);
            int x0 = (int)x0f, y0 = (int)y0f;
            float wx1 = xf - x0f, wy1 = yf - y0f;
            float wx0 = 1.f - wx1, wy0 = 1.f - wy1;
            float wgt = e[k] * inv;

            bool xin0 = (x0 >= 0) & (x0 < HW);
            bool xin1 = (x0 + 1 >= 0) & (x0 + 1 < HW);
            bool yin0 = (y0 >= 0) & (y0 < HW);
            bool yin1 = (y0 + 1 >= 0) & (y0 + 1 < HW);

            float4 cw;
            cw.x = (yin0 && xin0) ? wgt * wy0 * wx0 : 0.f;
            cw.y = (yin0 && xin1) ? wgt * wy0 * wx1 : 0.f;
            cw.z = (yin1 && xin0) ? wgt * wy1 * wx0 : 0.f;
            cw.w = (yin1 && xin1) ? wgt * wy1 * wx1 : 0.f;
            int line = y0 * HW + x0;
            int4 off;
            off.x = (yin0 && xin0) ? (ebase + line * DIM) * 2 : 0;
            off.y = (yin0 && xin1) ? (ebase + (line + 1) * DIM) * 2 : 0;
            off.z = (yin1 && xin0) ? (ebase + (line + HW) * DIM) * 2 : 0;
            off.w = (yin1 && xin1) ? (ebase + (line + HW + 1) * DIM) * 2 : 0;
            cws[w][hh][l * 4 + k] = cw;
            ofs[w][hh][l * 4 + k] = off;
        }
    }
    __syncwarp();

    // Phase 3: gather. lane -> (h = lane>>2, d8 = lane&3).
    const int h = lane >> 2;
    const int d8 = lane & 3;
    const char* vbase = (const char*)valbf + d8 * 16;

    float acc[8];
#pragma unroll
    for (int i = 0; i < 8; i++) acc[i] = 0.f;

#pragma unroll 4
    for (int p = 0; p < 16; p++) {
        float4 cw = cws[w][h][p];
        int4 off = ofs[w][h][p];
        const int o4[4] = { off.x, off.y, off.z, off.w };
        const float c4[4] = { cw.x, cw.y, cw.z, cw.w };
#pragma unroll
        for (int cnr = 0; cnr < 4; cnr++) {
            uint4 u = *(const uint4*)(vbase + o4[cnr]);
            const __nv_bfloat162* q2 = (const __nv_bfloat162*)&u;
            float c = c4[cnr];
#pragma unroll
            for (int j = 0; j < 4; j++) {
                float2 f = __bfloat1622float2(q2[j]);
                acc[2 * j + 0] = fmaf(f.x, c, acc[2 * j + 0]);
                acc[2 * j + 1] = fmaf(f.y, c, acc[2 * j + 1]);
            }
        }
    }
    __nv_bfloat162 ob[4];
#pragma unroll
    for (int j = 0; j < 4; j++)
        ob[j] = __float22bfloat162_rn(make_float2(acc[2 * j], acc[2 * j + 1]));
    *(uint4*)(sampb + (size_t)t * DIM + h * HD + d8 * 8) = *(uint4*)ob;
}

// ---------------------------------------------------------------------------
// LayerNorm over 256: out = LN(a + b) * g + beta. One warp per token.
// Optional bf16 secondary output.
// ---------------------------------------------------------------------------
__global__ void ln_kernel(const float* __restrict__ a, const float* __restrict__ b,
                          const float* __restrict__ g, const float* __restrict__ beta,
                          float* __restrict__ out, __nv_bfloat16* __restrict__ out_b)
{
    const int t = blockIdx.x * 4 + (threadIdx.x >> 5);
    const int lane = threadIdx.x & 31;
    const float* pa = a + (size_t)t * DIM;
    const float* pb = b + (size_t)t * DIM;

    float v[8];
    float s = 0.f;
#pragma unroll
    for (int i = 0; i < 8; i++) {
        int c = lane + i * 32;
        v[i] = pa[c] + pb[c];
        s += v[i];
    }
#pragma unroll
    for (int o = 16; o; o >>= 1) s += __shfl_xor_sync(0xffffffffu, s, o);
    const float mean = s * (1.f / 256.f);
    float var = 0.f;
#pragma unroll
    for (int i = 0; i < 8; i++) { float dd = v[i] - mean; var += dd * dd; }
#pragma unroll
    for (int o = 16; o; o >>= 1) var += __shfl_xor_sync(0xffffffffu, var, o);
    const float rstd = rsqrtf(var * (1.f / 256.f) + 1e-5f);
#pragma unroll
    for (int i = 0; i < 8; i++) {
        int c = lane + i * 32;
        float y = (v[i] - mean) * rstd * g[c] + beta[c];
        out[(size_t)t * DIM + c] = y;
        if (out_b) out_b[(size_t)t * DIM + c] = __float2bfloat16(y);
    }
}

// ---------------------------------------------------------------------------
extern "C" void kernel_launch(void* const* d_in, const int* in_sizes, int n_in,
                              void* d_out, int out_size)
{
    const float* src  = (const float*)d_in[0];
    const float* pos  = (const float*)d_in[1];
    const float* refp = (const float*)d_in[2];
    const float* Wv   = (const float*)d_in[4];
    const float* bv   = (const float*)d_in[5];
    const float* Wo   = (const float*)d_in[6];
    const float* bo   = (const float*)d_in[7];
    const float* Wa   = (const float*)d_in[8];
    const float* ba   = (const float*)d_in[9];
    const float* Wout = (const float*)d_in[10];
    const float* bout = (const float*)d_in[11];
    const float* g1   = (const float*)d_in[12];
    const float* be1  = (const float*)d_in[13];
    const float* W1   = (const float*)d_in[14];
    const float* b1   = (const float*)d_in[15];
    const float* W2   = (const float*)d_in[16];
    const float* b2   = (const float*)d_in[17];
    const float* g2   = (const float*)d_in[18];
    const float* be2  = (const float*)d_in[19];
    float* out = (float*)d_out;

    __nv_bfloat16 *psrcb, *pqb, *pvb, *psampb, *pxb, *phidb;
    __nv_bfloat16 *wtv, *wtoa, *wtout, *wt1, *wt2;
    float *poa, *psrc2, *px, *pffn, *pboa;
    cudaGetSymbolAddress((void**)&psrcb, g_srcb);
    cudaGetSymbolAddress((void**)&pqb,   g_qb);
    cudaGetSymbolAddress((void**)&pvb,   g_valbf);
    cudaGetSymbolAddress((void**)&poa,   g_offattn);
    cudaGetSymbolAddress((void**)&psampb,g_sampb);
    cudaGetSymbolAddress((void**)&psrc2, g_src2);
    cudaGetSymbolAddress((void**)&px,    g_x);
    cudaGetSymbolAddress((void**)&pxb,   g_xb);
    cudaGetSymbolAddress((void**)&phidb, g_hidb);
    cudaGetSymbolAddress((void**)&pffn,  g_ffn);
    cudaGetSymbolAddress((void**)&wtv,   g_wtv);
    cudaGetSymbolAddress((void**)&wtoa,  g_wtoa);
    cudaGetSymbolAddress((void**)&wtout, g_wtout);
    cudaGetSymbolAddress((void**)&wt1,   g_wt1);
    cudaGetSymbolAddress((void**)&wt2,   g_wt2);
    cudaGetSymbolAddress((void**)&pboa,  g_boa);

    const int DSM = 98304;  // 3 stages x (16KB A + 16KB B)
    cudaFuncSetAttribute(mma_gemm<0,0>, cudaFuncAttributeMaxDynamicSharedMemorySize, DSM);
    cudaFuncSetAttribute(mma_gemm<0,1>, cudaFuncAttributeMaxDynamicSharedMemorySize, DSM);
    cudaFuncSetAttribute(mma_gemm<1,1>, cudaFuncAttributeMaxDynamicSharedMemorySize, DSM);

    // One-shot prep
    prep_kernel<<<PREP_WBLK + PREP_ABLK + 1, 256>>>(
        Wv, Wo, Wa, Wout, W1, W2, bo, ba,
        (const float4*)src, (const float4*)pos,
        wtv, wtoa, wtout, wt1, wt2, pboa, psrcb, pqb);

    const int MT = TTOK / 128;  // 340 M-tiles

    // value (bf16) = src @ Wv + bv
    mma_gemm<0,1><<<MT * 2, 256, DSM>>>(psrcb, wtv, bv, nullptr, pvb, 256, 256, MT);
    // offsets|logits (fp32) = q @ [Woff|Wattn] + [boff|battn]
    mma_gemm<0,0><<<MT * 3, 256, DSM>>>(pqb, wtoa, pboa, poa, nullptr, 256, 384, MT);
    // deformable sampling (softmax fused; bf16 out)
    sample_kernel<<<TTOK / 8, 256>>>(pvb, poa, refp, psampb);
    // src2 (fp32) = samp @ Wout + bout
    mma_gemm<0,0><<<MT * 2, 256, DSM>>>(psampb, wtout, bout, psrc2, nullptr, 256, 256, MT);
    // x = LN1(src + src2)  (fp32 + bf16 copies)
    ln_kernel<<<TTOK / 4, 128>>>(src, psrc2, g1, be1, px, pxb);
    // hid (bf16) = relu(x @ W1 + b1)
    mma_gemm<1,1><<<MT * 8, 256, DSM>>>(pxb, wt1, b1, nullptr, phidb, 256, 1024, MT);
    // ffn (fp32) = hid @ W2 + b2
    mma_gemm<0,0><<<MT * 2, 256, DSM>>>(phidb, wt2, b2, pffn, nullptr, 1024, 256, MT);
    // out = LN2(x + ffn)
    ln_kernel<<<TTOK / 4, 128>>>(px, pffn, g2, be2, out, nullptr);
}

// round 10
// speedup vs baseline: 1.1159x; 1.1159x over previous
#include <cuda_runtime.h>
#include <cuda_bf16.h>
#include <cstdint>
#include <math.h>

// Problem constants (static per reference)
#define NBATCH 8
#define LQ     5440
#define TTOK   (NBATCH*LQ)      // 43520
#define DIM    256
#define NHEAD  8
#define HD     32
#define NLVL   4
#define NPT    4
#define DFF    1024

// Scratch (device globals; no runtime allocation)
__device__ __nv_bfloat16 g_srcb [(size_t)TTOK*DIM];
__device__ __nv_bfloat16 g_qb   [(size_t)TTOK*DIM];
__device__ __nv_bfloat16 g_valbf[(size_t)TTOK*DIM];
__device__ float         g_offattn[(size_t)TTOK*384];
__device__ __nv_bfloat16 g_sampb[(size_t)TTOK*DIM];
__device__ float         g_src2 [(size_t)TTOK*DIM];
__device__ float         g_x    [(size_t)TTOK*DIM];
__device__ __nv_bfloat16 g_xb   [(size_t)TTOK*DIM];
__device__ __nv_bfloat16 g_hidb [(size_t)TTOK*DFF];
__device__ float         g_ffn  [(size_t)TTOK*DIM];
// Transposed ([N][K]) bf16 weights
__device__ __nv_bfloat16 g_wtv  [256*256];
__device__ __nv_bfloat16 g_wtoa [384*256];
__device__ __nv_bfloat16 g_wtout[256*256];
__device__ __nv_bfloat16 g_wt1  [1024*256];
__device__ __nv_bfloat16 g_wt2  [256*1024];
__device__ float         g_boa  [384];

// ---------------------------------------------------------------------------
// Helpers
// ---------------------------------------------------------------------------
__device__ __forceinline__ uint32_t smem_u32(const void* p) {
    uint32_t a;
    asm("{ .reg .u64 t; cvta.to.shared.u64 t, %1; cvt.u32.u64 %0, t; }" : "=r"(a) : "l"(p));
    return a;
}
__device__ __forceinline__ void cpasync16(uint32_t dst, const void* src) {
    asm volatile("cp.async.cg.shared.global [%0], [%1], 16;" :: "r"(dst), "l"(src));
}
#define CP_COMMIT() asm volatile("cp.async.commit_group;" ::: "memory")
#define CP_WAIT1()  asm volatile("cp.async.wait_group 1;" ::: "memory")

__device__ __forceinline__ void ldmx4(uint32_t& f0, uint32_t& f1, uint32_t& f2, uint32_t& f3,
                                      uint32_t addr) {
    asm volatile("ldmatrix.sync.aligned.m8n8.x4.shared.b16 {%0,%1,%2,%3}, [%4];"
                 : "=r"(f0), "=r"(f1), "=r"(f2), "=r"(f3) : "r"(addr));
}
__device__ __forceinline__ void mma_bf16(float* c, uint32_t a0, uint32_t a1,
                                         uint32_t a2, uint32_t a3,
                                         uint32_t b0, uint32_t b1) {
    asm volatile(
        "mma.sync.aligned.m16n8k16.row.col.f32.bf16.bf16.f32 "
        "{%0,%1,%2,%3}, {%4,%5,%6,%7}, {%8,%9}, {%0,%1,%2,%3};"
        : "+f"(c[0]), "+f"(c[1]), "+f"(c[2]), "+f"(c[3])
        : "r"(a0), "r"(a1), "r"(a2), "r"(a3), "r"(b0), "r"(b1));
}

// ---------------------------------------------------------------------------
// One-shot prep: weight transposes (fp32 [K][N] -> bf16 [N][K]), bias concat,
// src/q bf16 conversion. Single launch.
// ---------------------------------------------------------------------------
#define PREP_WBLK 2944
#define PREP_ABLK 10880
__global__ void prep_kernel(const float* __restrict__ Wv, const float* __restrict__ Wo,
                            const float* __restrict__ Wa, const float* __restrict__ Wout,
                            const float* __restrict__ W1, const float* __restrict__ W2,
                            const float* __restrict__ bo, const float* __restrict__ ba,
                            const float4* __restrict__ src, const float4* __restrict__ pos,
                            __nv_bfloat16* __restrict__ wtv, __nv_bfloat16* __restrict__ wtoa,
                            __nv_bfloat16* __restrict__ wtout, __nv_bfloat16* __restrict__ wt1,
                            __nv_bfloat16* __restrict__ wt2, float* __restrict__ boa,
                            __nv_bfloat16* __restrict__ srcb, __nv_bfloat16* __restrict__ qb)
{
    int b = blockIdx.x;
    if (b < PREP_WBLK) {
        int idx = b * 256 + threadIdx.x;  // 0..753663
        float v; __nv_bfloat16* dst;
        if (idx < 65536) {                       // Wv [256,256]
            int n = idx >> 8, k = idx & 255; v = Wv[k * 256 + n]; dst = wtv + idx;
        } else if (idx < 163840) {               // Woa [384,256] = [Wo|Wa]
            int j = idx - 65536; int n = j >> 8, k = j & 255;
            v = (n < 256) ? Wo[k * 256 + n] : Wa[k * 128 + (n - 256)]; dst = wtoa + j;
        } else if (idx < 229376) {               // Wout [256,256]
            int j = idx - 163840; int n = j >> 8, k = j & 255; v = Wout[k * 256 + n]; dst = wtout + j;
        } else if (idx < 491520) {               // W1 [1024,256]
            int j = idx - 229376; int n = j >> 8, k = j & 255; v = W1[k * 1024 + n]; dst = wt1 + j;
        } else {                                 // W2 [256,1024]
            int j = idx - 491520; int n = j >> 10, k = j & 1023; v = W2[k * 256 + n]; dst = wt2 + j;
        }
        *dst = __float2bfloat16(v);
    } else if (b < PREP_WBLK + PREP_ABLK) {
        int idx = (b - PREP_WBLK) * 256 + threadIdx.x;   // float4 index
        float4 s = src[idx], p = pos[idx];
        __nv_bfloat162 s01 = __float22bfloat162_rn(make_float2(s.x, s.y));
        __nv_bfloat162 s23 = __float22bfloat162_rn(make_float2(s.z, s.w));
        __nv_bfloat162 q01 = __float22bfloat162_rn(make_float2(s.x + p.x, s.y + p.y));
        __nv_bfloat162 q23 = __float22bfloat162_rn(make_float2(s.z + p.z, s.w + p.w));
        ((uint2*)srcb)[idx] = make_uint2(*(uint32_t*)&s01, *(uint32_t*)&s23);
        ((uint2*)qb)[idx]   = make_uint2(*(uint32_t*)&q01, *(uint32_t*)&q23);
    } else {
        int i = threadIdx.x;
        if (i < 384) boa[i] = (i < 256) ? bo[i] : ba[i - 256];
    }
}

// ---------------------------------------------------------------------------
// bf16 tensor GEMM (128x128 tile), cp.async 3-stage + ldmatrix.
// ---------------------------------------------------------------------------
#define BK 64
template<int ACT, int OBF>
__global__ void __launch_bounds__(256, 2)
mma_gemm(const __nv_bfloat16* __restrict__ A, const __nv_bfloat16* __restrict__ Wt,
         const float* __restrict__ bias, float* __restrict__ C,
         __nv_bfloat16* __restrict__ C16, int K, int Nc, int mtiles)
{
    extern __shared__ char smem[];
    const uint32_t sbase = smem_u32(smem);

    const int tid = threadIdx.x;
    const int wid = tid >> 5, lane = tid & 31;
    const int g = lane >> 2, tg = lane & 3;
    const int wm = wid & 1, wn = wid >> 1;
    const int mt = blockIdx.x % mtiles;
    const int nt = blockIdx.x / mtiles;
    const int row0 = mt * 128, col0 = nt * 128;

    const int a_r  = (lane & 7) + ((lane >> 3) & 1) * 8;
    const int a_kh = (lane >> 4) & 1;
    const int b_r  = (lane & 7) + ((lane >> 4) << 3);
    const int b_kh = (lane >> 3) & 1;

    float acc[4][4][4];
#pragma unroll
    for (int i = 0; i < 4; i++)
#pragma unroll
        for (int j = 0; j < 4; j++)
#pragma unroll
            for (int k = 0; k < 4; k++) acc[i][j][k] = 0.f;

    auto load_chunk = [&](int k0, int st) {
#pragma unroll
        for (int i = 0; i < 4; i++) {
            int idx = tid + i * 256;
            int r = idx >> 3, gc = idx & 7;
            uint32_t so = (uint32_t)(r * 128 + ((gc ^ (r & 7)) << 4));
            cpasync16(sbase + st * 16384 + so, A + (size_t)(row0 + r) * K + k0 + gc * 8);
            cpasync16(sbase + 49152 + st * 16384 + so, Wt + (size_t)(col0 + r) * K + k0 + gc * 8);
        }
    };

    const int nchunk = K / BK;
    load_chunk(0, 0);
    CP_COMMIT();
    if (nchunk > 1) load_chunk(BK, 1);
    CP_COMMIT();

    for (int ch = 0; ch < nchunk; ch++) {
        CP_WAIT1();
        __syncthreads();
        if (ch + 2 < nchunk) load_chunk((ch + 2) * BK, (ch + 2) % 3);
        CP_COMMIT();

        const uint32_t Ab = sbase + (ch % 3) * 16384;
        const uint32_t Bb = sbase + 49152 + (ch % 3) * 16384;
#pragma unroll
        for (int ks = 0; ks < 4; ks++) {
            uint32_t bf[4][2];
#pragma unroll
            for (int np = 0; np < 2; np++) {
                int r = wn * 32 + np * 16 + b_r;
                uint32_t addr = Bb + r * 128 + (((ks * 2 + b_kh) ^ (r & 7)) << 4);
                ldmx4(bf[np * 2][0], bf[np * 2][1], bf[np * 2 + 1][0], bf[np * 2 + 1][1], addr);
            }
#pragma unroll
            for (int mf = 0; mf < 4; mf++) {
                int r = wm * 64 + mf * 16 + a_r;
                uint32_t addr = Ab + r * 128 + (((ks * 2 + a_kh) ^ (r & 7)) << 4);
                uint32_t a0, a1, a2, a3;
                ldmx4(a0, a1, a2, a3, addr);
#pragma unroll
                for (int nf = 0; nf < 4; nf++)
                    mma_bf16(acc[mf][nf], a0, a1, a2, a3, bf[nf][0], bf[nf][1]);
            }
        }
    }

#pragma unroll
    for (int mf = 0; mf < 4; mf++) {
#pragma unroll
        for (int nf = 0; nf < 4; nf++) {
            int row = row0 + wm * 64 + mf * 16 + g;
            int col = col0 + wn * 32 + nf * 8 + tg * 2;
            float b0 = bias[col], b1 = bias[col + 1];
            float o[4];
            o[0] = acc[mf][nf][0] + b0; o[1] = acc[mf][nf][1] + b1;
            o[2] = acc[mf][nf][2] + b0; o[3] = acc[mf][nf][3] + b1;
            if (ACT) {
#pragma unroll
                for (int i = 0; i < 4; i++) o[i] = fmaxf(o[i], 0.f);
            }
            if (OBF) {
                *(__nv_bfloat162*)(&C16[(size_t)row * Nc + col]) =
                    __float22bfloat162_rn(make_float2(o[0], o[1]));
                *(__nv_bfloat162*)(&C16[(size_t)(row + 8) * Nc + col]) =
                    __float22bfloat162_rn(make_float2(o[2], o[3]));
            } else {
                *(float2*)(&C[(size_t)row * Nc + col]) = make_float2(o[0], o[1]);
                *(float2*)(&C[(size_t)(row + 8) * Nc + col]) = make_float2(o[2], o[3]);
            }
        }
    }
}

// ---------------------------------------------------------------------------
// Deformable sampling, plan+gather per warp-token.
//  Plan arrays padded to [17] so the gather phase's per-point reads across
//  the 8 heads land on distinct bank groups (head stride 272B -> word offset
//  4h mod 32) -- the R9 layout (stride 256B) was an 8-way conflict.
// ---------------------------------------------------------------------------
__global__ void __launch_bounds__(256)
sample_kernel(const __nv_bfloat16* __restrict__ valbf,
              const float* __restrict__ offattn,
              const float* __restrict__ ref,
              __nv_bfloat16* __restrict__ sampb)
{
    __shared__ float  sh[8][384];
    __shared__ float4 cws[8][8][17];
    __shared__ int4   ofs[8][8][17];

    const int w = threadIdx.x >> 5;
    const int t = blockIdx.x * 8 + w;
    const int lane = threadIdx.x & 31;
    const int n = t / LQ;

    // Phase 1: stage offattn row (1536B, coalesced).
    {
        const float4* rowp4 = (const float4*)(offattn + (size_t)t * 384);
        float4* sh4 = (float4*)sh[w];
#pragma unroll
        for (int i = 0; i < 3; i++) sh4[i * 32 + lane] = rowp4[i * 32 + lane];
    }
    __syncwarp();

    // Phase 2: plan. lane -> (hh = lane>>2, l = lane&3), 4 points of level l.
    {
        const int hh = lane >> 2;
        const int l  = lane & 3;
        const int Hs_[4] = {64, 32, 16, 8};
        const int St_[4] = {0, 4096, 5120, 5376};
        const float* lp = sh[w] + 256 + hh * 16;

        float myl[4];
#pragma unroll
        for (int k = 0; k < 4; k++) myl[k] = lp[l * 4 + k];
        float mx = fmaxf(fmaxf(myl[0], myl[1]), fmaxf(myl[2], myl[3]));
        mx = fmaxf(mx, __shfl_xor_sync(0xffffffffu, mx, 1));
        mx = fmaxf(mx, __shfl_xor_sync(0xffffffffu, mx, 2));
        float e[4], s = 0.f;
#pragma unroll
        for (int k = 0; k < 4; k++) { e[k] = expf(myl[k] - mx); s += e[k]; }
        s += __shfl_xor_sync(0xffffffffu, s, 1);
        s += __shfl_xor_sync(0xffffffffu, s, 2);
        const float inv = 1.f / s;

        const int HW = Hs_[l];
        const float fHW = (float)HW;
        const float invHW = 1.f / fHW;
        const float refx = ref[((size_t)t * NLVL + l) * 2 + 0];
        const float refy = ref[((size_t)t * NLVL + l) * 2 + 1];
        const float* op = sh[w] + hh * 32 + l * 8;
        // element base for (n, level start, head)
        const int ebase = (n * LQ + St_[l]) * DIM + hh * HD;

#pragma unroll
        for (int k = 0; k < 4; k++) {
            float ox = op[k * 2 + 0];
            float oy = op[k * 2 + 1];
            float xf = (refx + ox * invHW) * fHW - 0.5f;
            float yf = (refy + oy * invHW) * fHW - 0.5f;
            float x0f = floorf(xf), y0f = floorf(yf);
            int x0 = (int)x0f, y0 = (int)y0f;
            float wx1 = xf - x0f, wy1 = yf - y0f;
            float wx0 = 1.f - wx1, wy0 = 1.f - wy1;
            float wgt = e[k] * inv;

            bool xin0 = (x0 >= 0) & (x0 < HW);
            bool xin1 = (x0 + 1 >= 0) & (x0 + 1 < HW);
            bool yin0 = (y0 >= 0) & (y0 < HW);
            bool yin1 = (y0 + 1 >= 0) & (y0 + 1 < HW);

            float4 cw;
            cw.x = (yin0 && xin0) ? wgt * wy0 * wx0 : 0.f;
            cw.y = (yin0 && xin1) ? wgt * wy0 * wx1 : 0.f;
            cw.z = (yin1 && xin0) ? wgt * wy1 * wx0 : 0.f;
            cw.w = (yin1 && xin1) ? wgt * wy1 * wx1 : 0.f;
            int line = y0 * HW + x0;
            int4 off;
            off.x = (yin0 && xin0) ? (ebase + line * DIM) * 2 : 0;
            off.y = (yin0 && xin1) ? (ebase + (line + 1) * DIM) * 2 : 0;
            off.z = (yin1 && xin0) ? (ebase + (line + HW) * DIM) * 2 : 0;
            off.w = (yin1 && xin1) ? (ebase + (line + HW + 1) * DIM) * 2 : 0;
            cws[w][hh][l * 4 + k] = cw;
            ofs[w][hh][l * 4 + k] = off;
        }
    }
    __syncwarp();

    // Phase 3: gather. lane -> (h = lane>>2, d8 = lane&3).
    const int h = lane >> 2;
    const int d8 = lane & 3;
    const char* vbase = (const char*)valbf + d8 * 16;

    float acc[8];
#pragma unroll
    for (int i = 0; i < 8; i++) acc[i] = 0.f;

#pragma unroll 4
    for (int p = 0; p < 16; p++) {
        float4 cw = cws[w][h][p];
        int4 off = ofs[w][h][p];
        const int o4[4] = { off.x, off.y, off.z, off.w };
        const float c4[4] = { cw.x, cw.y, cw.z, cw.w };
#pragma unroll
        for (int cnr = 0; cnr < 4; cnr++) {
            uint4 u = *(const uint4*)(vbase + o4[cnr]);
            const __nv_bfloat162* q2 = (const __nv_bfloat162*)&u;
            float c = c4[cnr];
#pragma unroll
            for (int j = 0; j < 4; j++) {
                float2 f = __bfloat1622float2(q2[j]);
                acc[2 * j + 0] = fmaf(f.x, c, acc[2 * j + 0]);
                acc[2 * j + 1] = fmaf(f.y, c, acc[2 * j + 1]);
            }
        }
    }
    __nv_bfloat162 ob[4];
#pragma unroll
    for (int j = 0; j < 4; j++)
        ob[j] = __float22bfloat162_rn(make_float2(acc[2 * j], acc[2 * j + 1]));
    *(uint4*)(sampb + (size_t)t * DIM + h * HD + d8 * 8) = *(uint4*)ob;
}

// ---------------------------------------------------------------------------
// LayerNorm over 256: out = LN(a + b) * g + beta. One warp per token.
// Optional bf16 secondary output.
// ---------------------------------------------------------------------------
__global__ void ln_kernel(const float* __restrict__ a, const float* __restrict__ b,
                          const float* __restrict__ g, const float* __restrict__ beta,
                          float* __restrict__ out, __nv_bfloat16* __restrict__ out_b)
{
    const int t = blockIdx.x * 4 + (threadIdx.x >> 5);
    const int lane = threadIdx.x & 31;
    const float* pa = a + (size_t)t * DIM;
    const float* pb = b + (size_t)t * DIM;

    float v[8];
    float s = 0.f;
#pragma unroll
    for (int i = 0; i < 8; i++) {
        int c = lane + i * 32;
        v[i] = pa[c] + pb[c];
        s += v[i];
    }
#pragma unroll
    for (int o = 16; o; o >>= 1) s += __shfl_xor_sync(0xffffffffu, s, o);
    const float mean = s * (1.f / 256.f);
    float var = 0.f;
#pragma unroll
    for (int i = 0; i < 8; i++) { float dd = v[i] - mean; var += dd * dd; }
#pragma unroll
    for (int o = 16; o; o >>= 1) var += __shfl_xor_sync(0xffffffffu, var, o);
    const float rstd = rsqrtf(var * (1.f / 256.f) + 1e-5f);
#pragma unroll
    for (int i = 0; i < 8; i++) {
        int c = lane + i * 32;
        float y = (v[i] - mean) * rstd * g[c] + beta[c];
        out[(size_t)t * DIM + c] = y;
        if (out_b) out_b[(size_t)t * DIM + c] = __float2bfloat16(y);
    }
}

// ---------------------------------------------------------------------------
extern "C" void kernel_launch(void* const* d_in, const int* in_sizes, int n_in,
                              void* d_out, int out_size)
{
    const float* src  = (const float*)d_in[0];
    const float* pos  = (const float*)d_in[1];
    const float* refp = (const float*)d_in[2];
    const float* Wv   = (const float*)d_in[4];
    const float* bv   = (const float*)d_in[5];
    const float* Wo   = (const float*)d_in[6];
    const float* bo   = (const float*)d_in[7];
    const float* Wa   = (const float*)d_in[8];
    const float* ba   = (const float*)d_in[9];
    const float* Wout = (const float*)d_in[10];
    const float* bout = (const float*)d_in[11];
    const float* g1   = (const float*)d_in[12];
    const float* be1  = (const float*)d_in[13];
    const float* W1   = (const float*)d_in[14];
    const float* b1   = (const float*)d_in[15];
    const float* W2   = (const float*)d_in[16];
    const float* b2   = (const float*)d_in[17];
    const float* g2   = (const float*)d_in[18];
    const float* be2  = (const float*)d_in[19];
    float* out = (float*)d_out;

    __nv_bfloat16 *psrcb, *pqb, *pvb, *psampb, *pxb, *phidb;
    __nv_bfloat16 *wtv, *wtoa, *wtout, *wt1, *wt2;
    float *poa, *psrc2, *px, *pffn, *pboa;
    cudaGetSymbolAddress((void**)&psrcb, g_srcb);
    cudaGetSymbolAddress((void**)&pqb,   g_qb);
    cudaGetSymbolAddress((void**)&pvb,   g_valbf);
    cudaGetSymbolAddress((void**)&poa,   g_offattn);
    cudaGetSymbolAddress((void**)&psampb,g_sampb);
    cudaGetSymbolAddress((void**)&psrc2, g_src2);
    cudaGetSymbolAddress((void**)&px,    g_x);
    cudaGetSymbolAddress((void**)&pxb,   g_xb);
    cudaGetSymbolAddress((void**)&phidb, g_hidb);
    cudaGetSymbolAddress((void**)&pffn,  g_ffn);
    cudaGetSymbolAddress((void**)&wtv,   g_wtv);
    cudaGetSymbolAddress((void**)&wtoa,  g_wtoa);
    cudaGetSymbolAddress((void**)&wtout, g_wtout);
    cudaGetSymbolAddress((void**)&wt1,   g_wt1);
    cudaGetSymbolAddress((void**)&wt2,   g_wt2);
    cudaGetSymbolAddress((void**)&pboa,  g_boa);

    const int DSM = 98304;  // 3 stages x (16KB A + 16KB B)
    cudaFuncSetAttribute(mma_gemm<0,0>, cudaFuncAttributeMaxDynamicSharedMemorySize, DSM);
    cudaFuncSetAttribute(mma_gemm<0,1>, cudaFuncAttributeMaxDynamicSharedMemorySize, DSM);
    cudaFuncSetAttribute(mma_gemm<1,1>, cudaFuncAttributeMaxDynamicSharedMemorySize, DSM);

    // One-shot prep
    prep_kernel<<<PREP_WBLK + PREP_ABLK + 1, 256>>>(
        Wv, Wo, Wa, Wout, W1, W2, bo, ba,
        (const float4*)src, (const float4*)pos,
        wtv, wtoa, wtout, wt1, wt2, pboa, psrcb, pqb);

    const int MT = TTOK / 128;  // 340 M-tiles

    // value (bf16) = src @ Wv + bv
    mma_gemm<0,1><<<MT * 2, 256, DSM>>>(psrcb, wtv, bv, nullptr, pvb, 256, 256, MT);
    // offsets|logits (fp32) = q @ [Woff|Wattn] + [boff|battn]
    mma_gemm<0,0><<<MT * 3, 256, DSM>>>(pqb, wtoa, pboa, poa, nullptr, 256, 384, MT);
    // deformable sampling (softmax fused; bf16 out)
    sample_kernel<<<TTOK / 8, 256>>>(pvb, poa, refp, psampb);
    // src2 (fp32) = samp @ Wout + bout
    mma_gemm<0,0><<<MT * 2, 256, DSM>>>(psampb, wtout, bout, psrc2, nullptr, 256, 256, MT);
    // x = LN1(src + src2)  (fp32 + bf16 copies)
    ln_kernel<<<TTOK / 4, 128>>>(src, psrc2, g1, be1, px, pxb);
    // hid (bf16) = relu(x @ W1 + b1)
    mma_gemm<1,1><<<MT * 8, 256, DSM>>>(pxb, wt1, b1, nullptr, phidb, 256, 1024, MT);
    // ffn (fp32) = hid @ W2 + b2
    mma_gemm<0,0><<<MT * 2, 256, DSM>>>(phidb, wt2, b2, pffn, nullptr, 1024, 256, MT);
    // out = LN2(x + ffn)
    ln_kernel<<<TTOK / 4, 128>>>(px, pffn, g2, be2, out, nullptr);
}

// round 11
// speedup vs baseline: 1.1299x; 1.0125x over previous
#include <cuda_runtime.h>
#include <cuda_bf16.h>
#include <cstdint>
#include <math.h>

// Problem constants (static per reference)
#define NBATCH 8
#define LQ     5440
#define TTOK   (NBATCH*LQ)      // 43520
#define DIM    256
#define NHEAD  8
#define HD     32
#define NLVL   4
#define NPT    4
#define DFF    1024

// Scratch (device globals; no runtime allocation)
__device__ __nv_bfloat16 g_srcb [(size_t)TTOK*DIM];
__device__ __nv_bfloat16 g_qb   [(size_t)TTOK*DIM];
__device__ __nv_bfloat16 g_valbf[(size_t)TTOK*DIM];
__device__ float         g_offattn[(size_t)TTOK*384];
__device__ __nv_bfloat16 g_sampb[(size_t)TTOK*DIM];
__device__ __nv_bfloat16 g_src2b[(size_t)TTOK*DIM];
__device__ float         g_x    [(size_t)TTOK*DIM];
__device__ __nv_bfloat16 g_xb   [(size_t)TTOK*DIM];
__device__ __nv_bfloat16 g_hidb [(size_t)TTOK*DFF];
__device__ __nv_bfloat16 g_ffnb [(size_t)TTOK*DIM];
// Transposed ([N][K]) bf16 weights
__device__ __nv_bfloat16 g_wtv  [256*256];
__device__ __nv_bfloat16 g_wtoa [384*256];
__device__ __nv_bfloat16 g_wtout[256*256];
__device__ __nv_bfloat16 g_wt1  [1024*256];
__device__ __nv_bfloat16 g_wt2  [256*1024];
__device__ float         g_boa  [384];

// ---------------------------------------------------------------------------
// Helpers
// ---------------------------------------------------------------------------
__device__ __forceinline__ uint32_t smem_u32(const void* p) {
    uint32_t a;
    asm("{ .reg .u64 t; cvta.to.shared.u64 t, %1; cvt.u32.u64 %0, t; }" : "=r"(a) : "l"(p));
    return a;
}
__device__ __forceinline__ void cpasync16(uint32_t dst, const void* src) {
    asm volatile("cp.async.cg.shared.global [%0], [%1], 16;" :: "r"(dst), "l"(src));
}
#define CP_COMMIT() asm volatile("cp.async.commit_group;" ::: "memory")
#define CP_WAIT1()  asm volatile("cp.async.wait_group 1;" ::: "memory")

__device__ __forceinline__ void ldmx4(uint32_t& f0, uint32_t& f1, uint32_t& f2, uint32_t& f3,
                                      uint32_t addr) {
    asm volatile("ldmatrix.sync.aligned.m8n8.x4.shared.b16 {%0,%1,%2,%3}, [%4];"
                 : "=r"(f0), "=r"(f1), "=r"(f2), "=r"(f3) : "r"(addr));
}
__device__ __forceinline__ void mma_bf16(float* c, uint32_t a0, uint32_t a1,
                                         uint32_t a2, uint32_t a3,
                                         uint32_t b0, uint32_t b1) {
    asm volatile(
        "mma.sync.aligned.m16n8k16.row.col.f32.bf16.bf16.f32 "
        "{%0,%1,%2,%3}, {%4,%5,%6,%7}, {%8,%9}, {%0,%1,%2,%3};"
        : "+f"(c[0]), "+f"(c[1]), "+f"(c[2]), "+f"(c[3])
        : "r"(a0), "r"(a1), "r"(a2), "r"(a3), "r"(b0), "r"(b1));
}

// ---------------------------------------------------------------------------
// One-shot prep: weight transposes (fp32 [K][N] -> bf16 [N][K]), bias concat,
// src/q bf16 conversion. Single launch.
// ---------------------------------------------------------------------------
#define PREP_WBLK 2944
#define PREP_ABLK 10880
__global__ void prep_kernel(const float* __restrict__ Wv, const float* __restrict__ Wo,
                            const float* __restrict__ Wa, const float* __restrict__ Wout,
                            const float* __restrict__ W1, const float* __restrict__ W2,
                            const float* __restrict__ bo, const float* __restrict__ ba,
                            const float4* __restrict__ src, const float4* __restrict__ pos,
                            __nv_bfloat16* __restrict__ wtv, __nv_bfloat16* __restrict__ wtoa,
                            __nv_bfloat16* __restrict__ wtout, __nv_bfloat16* __restrict__ wt1,
                            __nv_bfloat16* __restrict__ wt2, float* __restrict__ boa,
                            __nv_bfloat16* __restrict__ srcb, __nv_bfloat16* __restrict__ qb)
{
    int b = blockIdx.x;
    if (b < PREP_WBLK) {
        int idx = b * 256 + threadIdx.x;  // 0..753663
        float v; __nv_bfloat16* dst;
        if (idx < 65536) {                       // Wv [256,256]
            int n = idx >> 8, k = idx & 255; v = Wv[k * 256 + n]; dst = wtv + idx;
        } else if (idx < 163840) {               // Woa [384,256] = [Wo|Wa]
            int j = idx - 65536; int n = j >> 8, k = j & 255;
            v = (n < 256) ? Wo[k * 256 + n] : Wa[k * 128 + (n - 256)]; dst = wtoa + j;
        } else if (idx < 229376) {               // Wout [256,256]
            int j = idx - 163840; int n = j >> 8, k = j & 255; v = Wout[k * 256 + n]; dst = wtout + j;
        } else if (idx < 491520) {               // W1 [1024,256]
            int j = idx - 229376; int n = j >> 8, k = j & 255; v = W1[k * 1024 + n]; dst = wt1 + j;
        } else {                                 // W2 [256,1024]
            int j = idx - 491520; int n = j >> 10, k = j & 1023; v = W2[k * 256 + n]; dst = wt2 + j;
        }
        *dst = __float2bfloat16(v);
    } else if (b < PREP_WBLK + PREP_ABLK) {
        int idx = (b - PREP_WBLK) * 256 + threadIdx.x;   // float4 index
        float4 s = src[idx], p = pos[idx];
        __nv_bfloat162 s01 = __float22bfloat162_rn(make_float2(s.x, s.y));
        __nv_bfloat162 s23 = __float22bfloat162_rn(make_float2(s.z, s.w));
        __nv_bfloat162 q01 = __float22bfloat162_rn(make_float2(s.x + p.x, s.y + p.y));
        __nv_bfloat162 q23 = __float22bfloat162_rn(make_float2(s.z + p.z, s.w + p.w));
        ((uint2*)srcb)[idx] = make_uint2(*(uint32_t*)&s01, *(uint32_t*)&s23);
        ((uint2*)qb)[idx]   = make_uint2(*(uint32_t*)&q01, *(uint32_t*)&q23);
    } else {
        int i = threadIdx.x;
        if (i < 384) boa[i] = (i < 256) ? bo[i] : ba[i - 256];
    }
}

// ---------------------------------------------------------------------------
// bf16 tensor GEMM (128x128 tile), cp.async 3-stage + ldmatrix.
// ---------------------------------------------------------------------------
#define BK 64
template<int ACT, int OBF>
__global__ void __launch_bounds__(256, 2)
mma_gemm(const __nv_bfloat16* __restrict__ A, const __nv_bfloat16* __restrict__ Wt,
         const float* __restrict__ bias, float* __restrict__ C,
         __nv_bfloat16* __restrict__ C16, int K, int Nc, int mtiles)
{
    extern __shared__ char smem[];
    const uint32_t sbase = smem_u32(smem);

    const int tid = threadIdx.x;
    const int wid = tid >> 5, lane = tid & 31;
    const int g = lane >> 2, tg = lane & 3;
    const int wm = wid & 1, wn = wid >> 1;
    const int mt = blockIdx.x % mtiles;
    const int nt = blockIdx.x / mtiles;
    const int row0 = mt * 128, col0 = nt * 128;

    const int a_r  = (lane & 7) + ((lane >> 3) & 1) * 8;
    const int a_kh = (lane >> 4) & 1;
    const int b_r  = (lane & 7) + ((lane >> 4) << 3);
    const int b_kh = (lane >> 3) & 1;

    float acc[4][4][4];
#pragma unroll
    for (int i = 0; i < 4; i++)
#pragma unroll
        for (int j = 0; j < 4; j++)
#pragma unroll
            for (int k = 0; k < 4; k++) acc[i][j][k] = 0.f;

    auto load_chunk = [&](int k0, int st) {
#pragma unroll
        for (int i = 0; i < 4; i++) {
            int idx = tid + i * 256;
            int r = idx >> 3, gc = idx & 7;
            uint32_t so = (uint32_t)(r * 128 + ((gc ^ (r & 7)) << 4));
            cpasync16(sbase + st * 16384 + so, A + (size_t)(row0 + r) * K + k0 + gc * 8);
            cpasync16(sbase + 49152 + st * 16384 + so, Wt + (size_t)(col0 + r) * K + k0 + gc * 8);
        }
    };

    const int nchunk = K / BK;
    load_chunk(0, 0);
    CP_COMMIT();
    if (nchunk > 1) load_chunk(BK, 1);
    CP_COMMIT();

    for (int ch = 0; ch < nchunk; ch++) {
        CP_WAIT1();
        __syncthreads();
        if (ch + 2 < nchunk) load_chunk((ch + 2) * BK, (ch + 2) % 3);
        CP_COMMIT();

        const uint32_t Ab = sbase + (ch % 3) * 16384;
        const uint32_t Bb = sbase + 49152 + (ch % 3) * 16384;
#pragma unroll
        for (int ks = 0; ks < 4; ks++) {
            uint32_t bf[4][2];
#pragma unroll
            for (int np = 0; np < 2; np++) {
                int r = wn * 32 + np * 16 + b_r;
                uint32_t addr = Bb + r * 128 + (((ks * 2 + b_kh) ^ (r & 7)) << 4);
                ldmx4(bf[np * 2][0], bf[np * 2][1], bf[np * 2 + 1][0], bf[np * 2 + 1][1], addr);
            }
#pragma unroll
            for (int mf = 0; mf < 4; mf++) {
                int r = wm * 64 + mf * 16 + a_r;
                uint32_t addr = Ab + r * 128 + (((ks * 2 + a_kh) ^ (r & 7)) << 4);
                uint32_t a0, a1, a2, a3;
                ldmx4(a0, a1, a2, a3, addr);
#pragma unroll
                for (int nf = 0; nf < 4; nf++)
                    mma_bf16(acc[mf][nf], a0, a1, a2, a3, bf[nf][0], bf[nf][1]);
            }
        }
    }

#pragma unroll
    for (int mf = 0; mf < 4; mf++) {
#pragma unroll
        for (int nf = 0; nf < 4; nf++) {
            int row = row0 + wm * 64 + mf * 16 + g;
            int col = col0 + wn * 32 + nf * 8 + tg * 2;
            float b0 = bias[col], b1 = bias[col + 1];
            float o[4];
            o[0] = acc[mf][nf][0] + b0; o[1] = acc[mf][nf][1] + b1;
            o[2] = acc[mf][nf][2] + b0; o[3] = acc[mf][nf][3] + b1;
            if (ACT) {
#pragma unroll
                for (int i = 0; i < 4; i++) o[i] = fmaxf(o[i], 0.f);
            }
            if (OBF) {
                *(__nv_bfloat162*)(&C16[(size_t)row * Nc + col]) =
                    __float22bfloat162_rn(make_float2(o[0], o[1]));
                *(__nv_bfloat162*)(&C16[(size_t)(row + 8) * Nc + col]) =
                    __float22bfloat162_rn(make_float2(o[2], o[3]));
            } else {
                *(float2*)(&C[(size_t)row * Nc + col]) = make_float2(o[0], o[1]);
                *(float2*)(&C[(size_t)(row + 8) * Nc + col]) = make_float2(o[2], o[3]);
            }
        }
    }
}

// ---------------------------------------------------------------------------
// Deformable sampling, plan+gather per warp-token (R10 layout, conflict-free).
// ---------------------------------------------------------------------------
__global__ void __launch_bounds__(256)
sample_kernel(const __nv_bfloat16* __restrict__ valbf,
              const float* __restrict__ offattn,
              const float* __restrict__ ref,
              __nv_bfloat16* __restrict__ sampb)
{
    __shared__ float  sh[8][384];
    __shared__ float4 cws[8][8][17];
    __shared__ int4   ofs[8][8][17];

    const int w = threadIdx.x >> 5;
    const int t = blockIdx.x * 8 + w;
    const int lane = threadIdx.x & 31;
    const int n = t / LQ;

    // Phase 1: stage offattn row (1536B, coalesced).
    {
        const float4* rowp4 = (const float4*)(offattn + (size_t)t * 384);
        float4* sh4 = (float4*)sh[w];
#pragma unroll
        for (int i = 0; i < 3; i++) sh4[i * 32 + lane] = rowp4[i * 32 + lane];
    }
    __syncwarp();

    // Phase 2: plan. lane -> (hh = lane>>2, l = lane&3), 4 points of level l.
    {
        const int hh = lane >> 2;
        const int l  = lane & 3;
        const int Hs_[4] = {64, 32, 16, 8};
        const int St_[4] = {0, 4096, 5120, 5376};
        const float* lp = sh[w] + 256 + hh * 16;

        float myl[4];
#pragma unroll
        for (int k = 0; k < 4; k++) myl[k] = lp[l * 4 + k];
        float mx = fmaxf(fmaxf(myl[0], myl[1]), fmaxf(myl[2], myl[3]));
        mx = fmaxf(mx, __shfl_xor_sync(0xffffffffu, mx, 1));
        mx = fmaxf(mx, __shfl_xor_sync(0xffffffffu, mx, 2));
        float e[4], s = 0.f;
#pragma unroll
        for (int k = 0; k < 4; k++) { e[k] = expf(myl[k] - mx); s += e[k]; }
        s += __shfl_xor_sync(0xffffffffu, s, 1);
        s += __shfl_xor_sync(0xffffffffu, s, 2);
        const float inv = 1.f / s;

        const int HW = Hs_[l];
        const float fHW = (float)HW;
        const float invHW = 1.f / fHW;
        const float refx = ref[((size_t)t * NLVL + l) * 2 + 0];
        const float refy = ref[((size_t)t * NLVL + l) * 2 + 1];
        const float* op = sh[w] + hh * 32 + l * 8;
        const int ebase = (n * LQ + St_[l]) * DIM + hh * HD;

#pragma unroll
        for (int k = 0; k < 4; k++) {
            float ox = op[k * 2 + 0];
            float oy = op[k * 2 + 1];
            float xf = (refx + ox * invHW) * fHW - 0.5f;
            float yf = (refy + oy * invHW) * fHW - 0.5f;
            float x0f = floorf(xf), y0f = floorf(yf);
            int x0 = (int)x0f, y0 = (int)y0f;
            float wx1 = xf - x0f, wy1 = yf - y0f;
            float wx0 = 1.f - wx1, wy0 = 1.f - wy1;
            float wgt = e[k] * inv;

            bool xin0 = (x0 >= 0) & (x0 < HW);
            bool xin1 = (x0 + 1 >= 0) & (x0 + 1 < HW);
            bool yin0 = (y0 >= 0) & (y0 < HW);
            bool yin1 = (y0 + 1 >= 0) & (y0 + 1 < HW);

            float4 cw;
            cw.x = (yin0 && xin0) ? wgt * wy0 * wx0 : 0.f;
            cw.y = (yin0 && xin1) ? wgt * wy0 * wx1 : 0.f;
            cw.z = (yin1 && xin0) ? wgt * wy1 * wx0 : 0.f;
            cw.w = (yin1 && xin1) ? wgt * wy1 * wx1 : 0.f;
            int line = y0 * HW + x0;
            int4 off;
            off.x = (yin0 && xin0) ? (ebase + line * DIM) * 2 : 0;
            off.y = (yin0 && xin1) ? (ebase + (line + 1) * DIM) * 2 : 0;
            off.z = (yin1 && xin0) ? (ebase + (line + HW) * DIM) * 2 : 0;
            off.w = (yin1 && xin1) ? (ebase + (line + HW + 1) * DIM) * 2 : 0;
            cws[w][hh][l * 4 + k] = cw;
            ofs[w][hh][l * 4 + k] = off;
        }
    }
    __syncwarp();

    // Phase 3: gather. lane -> (h = lane>>2, d8 = lane&3).
    const int h = lane >> 2;
    const int d8 = lane & 3;
    const char* vbase = (const char*)valbf + d8 * 16;

    float acc[8];
#pragma unroll
    for (int i = 0; i < 8; i++) acc[i] = 0.f;

#pragma unroll 4
    for (int p = 0; p < 16; p++) {
        float4 cw = cws[w][h][p];
        int4 off = ofs[w][h][p];
        const int o4[4] = { off.x, off.y, off.z, off.w };
        const float c4[4] = { cw.x, cw.y, cw.z, cw.w };
#pragma unroll
        for (int cnr = 0; cnr < 4; cnr++) {
            uint4 u = *(const uint4*)(vbase + o4[cnr]);
            const __nv_bfloat162* q2 = (const __nv_bfloat162*)&u;
            float c = c4[cnr];
#pragma unroll
            for (int j = 0; j < 4; j++) {
                float2 f = __bfloat1622float2(q2[j]);
                acc[2 * j + 0] = fmaf(f.x, c, acc[2 * j + 0]);
                acc[2 * j + 1] = fmaf(f.y, c, acc[2 * j + 1]);
            }
        }
    }
    __nv_bfloat162 ob[4];
#pragma unroll
    for (int j = 0; j < 4; j++)
        ob[j] = __float22bfloat162_rn(make_float2(acc[2 * j], acc[2 * j + 1]));
    *(uint4*)(sampb + (size_t)t * DIM + h * HD + d8 * 8) = *(uint4*)ob;
}

// ---------------------------------------------------------------------------
// LayerNorm over 256: out = LN(a + b) * g + beta. One warp per token.
// b is bf16 (GEMM epilogues emit bf16 to halve LN traffic).
// Optional bf16 secondary output.
// ---------------------------------------------------------------------------
__global__ void ln_kernel(const float* __restrict__ a, const __nv_bfloat16* __restrict__ b,
                          const float* __restrict__ g, const float* __restrict__ beta,
                          float* __restrict__ out, __nv_bfloat16* __restrict__ out_b)
{
    const int t = blockIdx.x * 4 + (threadIdx.x >> 5);
    const int lane = threadIdx.x & 31;
    const float* pa = a + (size_t)t * DIM;
    const __nv_bfloat16* pb = b + (size_t)t * DIM;

    float v[8];
    float s = 0.f;
#pragma unroll
    for (int i = 0; i < 8; i++) {
        int c = lane + i * 32;
        v[i] = pa[c] + __bfloat162float(pb[c]);
        s += v[i];
    }
#pragma unroll
    for (int o = 16; o; o >>= 1) s += __shfl_xor_sync(0xffffffffu, s, o);
    const float mean = s * (1.f / 256.f);
    float var = 0.f;
#pragma unroll
    for (int i = 0; i < 8; i++) { float dd = v[i] - mean; var += dd * dd; }
#pragma unroll
    for (int o = 16; o; o >>= 1) var += __shfl_xor_sync(0xffffffffu, var, o);
    const float rstd = rsqrtf(var * (1.f / 256.f) + 1e-5f);
#pragma unroll
    for (int i = 0; i < 8; i++) {
        int c = lane + i * 32;
        float y = (v[i] - mean) * rstd * g[c] + beta[c];
        out[(size_t)t * DIM + c] = y;
        if (out_b) out_b[(size_t)t * DIM + c] = __float2bfloat16(y);
    }
}

// ---------------------------------------------------------------------------
extern "C" void kernel_launch(void* const* d_in, const int* in_sizes, int n_in,
                              void* d_out, int out_size)
{
    const float* src  = (const float*)d_in[0];
    const float* pos  = (const float*)d_in[1];
    const float* refp = (const float*)d_in[2];
    const float* Wv   = (const float*)d_in[4];
    const float* bv   = (const float*)d_in[5];
    const float* Wo   = (const float*)d_in[6];
    const float* bo   = (const float*)d_in[7];
    const float* Wa   = (const float*)d_in[8];
    const float* ba   = (const float*)d_in[9];
    const float* Wout = (const float*)d_in[10];
    const float* bout = (const float*)d_in[11];
    const float* g1   = (const float*)d_in[12];
    const float* be1  = (const float*)d_in[13];
    const float* W1   = (const float*)d_in[14];
    const float* b1   = (const float*)d_in[15];
    const float* W2   = (const float*)d_in[16];
    const float* b2   = (const float*)d_in[17];
    const float* g2   = (const float*)d_in[18];
    const float* be2  = (const float*)d_in[19];
    float* out = (float*)d_out;

    __nv_bfloat16 *psrcb, *pqb, *pvb, *psampb, *psrc2b, *pxb, *phidb, *pffnb;
    __nv_bfloat16 *wtv, *wtoa, *wtout, *wt1, *wt2;
    float *poa, *px, *pboa;
    cudaGetSymbolAddress((void**)&psrcb, g_srcb);
    cudaGetSymbolAddress((void**)&pqb,   g_qb);
    cudaGetSymbolAddress((void**)&pvb,   g_valbf);
    cudaGetSymbolAddress((void**)&poa,   g_offattn);
    cudaGetSymbolAddress((void**)&psampb,g_sampb);
    cudaGetSymbolAddress((void**)&psrc2b,g_src2b);
    cudaGetSymbolAddress((void**)&px,    g_x);
    cudaGetSymbolAddress((void**)&pxb,   g_xb);
    cudaGetSymbolAddress((void**)&phidb, g_hidb);
    cudaGetSymbolAddress((void**)&pffnb, g_ffnb);
    cudaGetSymbolAddress((void**)&wtv,   g_wtv);
    cudaGetSymbolAddress((void**)&wtoa,  g_wtoa);
    cudaGetSymbolAddress((void**)&wtout, g_wtout);
    cudaGetSymbolAddress((void**)&wt1,   g_wt1);
    cudaGetSymbolAddress((void**)&wt2,   g_wt2);
    cudaGetSymbolAddress((void**)&pboa,  g_boa);

    const int DSM = 98304;  // 3 stages x (16KB A + 16KB B)
    cudaFuncSetAttribute(mma_gemm<0,0>, cudaFuncAttributeMaxDynamicSharedMemorySize, DSM);
    cudaFuncSetAttribute(mma_gemm<0,1>, cudaFuncAttributeMaxDynamicSharedMemorySize, DSM);
    cudaFuncSetAttribute(mma_gemm<1,1>, cudaFuncAttributeMaxDynamicSharedMemorySize, DSM);

    // One-shot prep
    prep_kernel<<<PREP_WBLK + PREP_ABLK + 1, 256>>>(
        Wv, Wo, Wa, Wout, W1, W2, bo, ba,
        (const float4*)src, (const float4*)pos,
        wtv, wtoa, wtout, wt1, wt2, pboa, psrcb, pqb);

    const int MT = TTOK / 128;  // 340 M-tiles

    // value (bf16) = src @ Wv + bv
    mma_gemm<0,1><<<MT * 2, 256, DSM>>>(psrcb, wtv, bv, nullptr, pvb, 256, 256, MT);
    // offsets|logits (fp32) = q @ [Woff|Wattn] + [boff|battn]
    mma_gemm<0,0><<<MT * 3, 256, DSM>>>(pqb, wtoa, pboa, poa, nullptr, 256, 384, MT);
    // deformable sampling (softmax fused; bf16 out)
    sample_kernel<<<TTOK / 8, 256>>>(pvb, poa, refp, psampb);
    // src2 (bf16) = samp @ Wout + bout
    mma_gemm<0,1><<<MT * 2, 256, DSM>>>(psampb, wtout, bout, nullptr, psrc2b, 256, 256, MT);
    // x = LN1(src + src2)  (fp32 + bf16 copies)
    ln_kernel<<<TTOK / 4, 128>>>(src, psrc2b, g1, be1, px, pxb);
    // hid (bf16) = relu(x @ W1 + b1)
    mma_gemm<1,1><<<MT * 8, 256, DSM>>>(pxb, wt1, b1, nullptr, phidb, 256, 1024, MT);
    // ffn (bf16) = hid @ W2 + b2
    mma_gemm<0,1><<<MT * 2, 256, DSM>>>(phidb, wt2, b2, nullptr, pffnb, 1024, 256, MT);
    // out = LN2(x + ffn)
    ln_kernel<<<TTOK / 4, 128>>>(px, pffnb, g2, be2, out, nullptr);
}

// round 12
// speedup vs baseline: 1.1510x; 1.0186x over previous
#include <cuda_runtime.h>
#include <cuda_bf16.h>
#include <cstdint>
#include <math.h>

// Problem constants (static per reference)
#define NBATCH 8
#define LQ     5440
#define TTOK   (NBATCH*LQ)      // 43520
#define DIM    256
#define NHEAD  8
#define HD     32
#define NLVL   4
#define NPT    4
#define DFF    1024

// Scratch (device globals; no runtime allocation)
__device__ __nv_bfloat16 g_srcb [(size_t)TTOK*DIM];
__device__ __nv_bfloat16 g_qb   [(size_t)TTOK*DIM];
__device__ __nv_bfloat16 g_valbf[(size_t)TTOK*DIM];
__device__ float         g_offattn[(size_t)TTOK*384];
__device__ __nv_bfloat16 g_sampb[(size_t)TTOK*DIM];
__device__ __nv_bfloat16 g_src2b[(size_t)TTOK*DIM];
__device__ float         g_x    [(size_t)TTOK*DIM];
__device__ __nv_bfloat16 g_xb   [(size_t)TTOK*DIM];
__device__ __nv_bfloat16 g_hidb [(size_t)TTOK*DFF];
__device__ __nv_bfloat16 g_ffnb [(size_t)TTOK*DIM];
// Transposed ([N][K]) bf16 weights
__device__ __nv_bfloat16 g_wtv  [256*256];
__device__ __nv_bfloat16 g_wtoa [384*256];
__device__ __nv_bfloat16 g_wtout[256*256];
__device__ __nv_bfloat16 g_wt1  [1024*256];
__device__ __nv_bfloat16 g_wt2  [256*1024];
__device__ float         g_boa  [384];

// ---------------------------------------------------------------------------
// Helpers
// ---------------------------------------------------------------------------
__device__ __forceinline__ uint32_t smem_u32(const void* p) {
    uint32_t a;
    asm("{ .reg .u64 t; cvta.to.shared.u64 t, %1; cvt.u32.u64 %0, t; }" : "=r"(a) : "l"(p));
    return a;
}
__device__ __forceinline__ void cpasync16(uint32_t dst, const void* src) {
    asm volatile("cp.async.cg.shared.global [%0], [%1], 16;" :: "r"(dst), "l"(src));
}
#define CP_COMMIT() asm volatile("cp.async.commit_group;" ::: "memory")
#define CP_WAIT1()  asm volatile("cp.async.wait_group 1;" ::: "memory")

__device__ __forceinline__ void ldmx4(uint32_t& f0, uint32_t& f1, uint32_t& f2, uint32_t& f3,
                                      uint32_t addr) {
    asm volatile("ldmatrix.sync.aligned.m8n8.x4.shared.b16 {%0,%1,%2,%3}, [%4];"
                 : "=r"(f0), "=r"(f1), "=r"(f2), "=r"(f3) : "r"(addr));
}
__device__ __forceinline__ void mma_bf16(float* c, uint32_t a0, uint32_t a1,
                                         uint32_t a2, uint32_t a3,
                                         uint32_t b0, uint32_t b1) {
    asm volatile(
        "mma.sync.aligned.m16n8k16.row.col.f32.bf16.bf16.f32 "
        "{%0,%1,%2,%3}, {%4,%5,%6,%7}, {%8,%9}, {%0,%1,%2,%3};"
        : "+f"(c[0]), "+f"(c[1]), "+f"(c[2]), "+f"(c[3])
        : "r"(a0), "r"(a1), "r"(a2), "r"(a3), "r"(b0), "r"(b1));
}

// ---------------------------------------------------------------------------
// One-shot prep: weight transposes (fp32 [K][N] -> bf16 [N][K]), bias concat,
// src/q bf16 conversion. Single launch.
// ---------------------------------------------------------------------------
#define PREP_WBLK 2944
#define PREP_ABLK 10880
__global__ void prep_kernel(const float* __restrict__ Wv, const float* __restrict__ Wo,
                            const float* __restrict__ Wa, const float* __restrict__ Wout,
                            const float* __restrict__ W1, const float* __restrict__ W2,
                            const float* __restrict__ bo, const float* __restrict__ ba,
                            const float4* __restrict__ src, const float4* __restrict__ pos,
                            __nv_bfloat16* __restrict__ wtv, __nv_bfloat16* __restrict__ wtoa,
                            __nv_bfloat16* __restrict__ wtout, __nv_bfloat16* __restrict__ wt1,
                            __nv_bfloat16* __restrict__ wt2, float* __restrict__ boa,
                            __nv_bfloat16* __restrict__ srcb, __nv_bfloat16* __restrict__ qb)
{
    int b = blockIdx.x;
    if (b < PREP_WBLK) {
        int idx = b * 256 + threadIdx.x;  // 0..753663
        float v; __nv_bfloat16* dst;
        if (idx < 65536) {                       // Wv [256,256]
            int n = idx >> 8, k = idx & 255; v = Wv[k * 256 + n]; dst = wtv + idx;
        } else if (idx < 163840) {               // Woa [384,256] = [Wo|Wa]
            int j = idx - 65536; int n = j >> 8, k = j & 255;
            v = (n < 256) ? Wo[k * 256 + n] : Wa[k * 128 + (n - 256)]; dst = wtoa + j;
        } else if (idx < 229376) {               // Wout [256,256]
            int j = idx - 163840; int n = j >> 8, k = j & 255; v = Wout[k * 256 + n]; dst = wtout + j;
        } else if (idx < 491520) {               // W1 [1024,256]
            int j = idx - 229376; int n = j >> 8, k = j & 255; v = W1[k * 1024 + n]; dst = wt1 + j;
        } else {                                 // W2 [256,1024]
            int j = idx - 491520; int n = j >> 10, k = j & 1023; v = W2[k * 256 + n]; dst = wt2 + j;
        }
        *dst = __float2bfloat16(v);
    } else if (b < PREP_WBLK + PREP_ABLK) {
        int idx = (b - PREP_WBLK) * 256 + threadIdx.x;   // float4 index
        float4 s = src[idx], p = pos[idx];
        __nv_bfloat162 s01 = __float22bfloat162_rn(make_float2(s.x, s.y));
        __nv_bfloat162 s23 = __float22bfloat162_rn(make_float2(s.z, s.w));
        __nv_bfloat162 q01 = __float22bfloat162_rn(make_float2(s.x + p.x, s.y + p.y));
        __nv_bfloat162 q23 = __float22bfloat162_rn(make_float2(s.z + p.z, s.w + p.w));
        ((uint2*)srcb)[idx] = make_uint2(*(uint32_t*)&s01, *(uint32_t*)&s23);
        ((uint2*)qb)[idx]   = make_uint2(*(uint32_t*)&q01, *(uint32_t*)&q23);
    } else {
        int i = threadIdx.x;
        if (i < 384) boa[i] = (i < 256) ? bo[i] : ba[i - 256];
    }
}

// ---------------------------------------------------------------------------
// Shared bf16 GEMM mainloop (128x128 tile, cp.async 3-stage + ldmatrix),
// parameterized by runtime operands; acc left in registers for the caller's
// epilogue.
// ---------------------------------------------------------------------------
#define BK 64

struct GemmCtx {
    int tid, wid, lane, g, tg, wm, wn, row0, col0;
    uint32_t sbase;
    int a_r, a_kh, b_r, b_kh;
};

__device__ __forceinline__ void gemm_mainloop(
    GemmCtx& c, const __nv_bfloat16* __restrict__ A,
    const __nv_bfloat16* __restrict__ Wt, int K, float acc[4][4][4])
{
#pragma unroll
    for (int i = 0; i < 4; i++)
#pragma unroll
        for (int j = 0; j < 4; j++)
#pragma unroll
            for (int k = 0; k < 4; k++) acc[i][j][k] = 0.f;

    auto load_chunk = [&](int k0, int st) {
#pragma unroll
        for (int i = 0; i < 4; i++) {
            int idx = c.tid + i * 256;
            int r = idx >> 3, gc = idx & 7;
            uint32_t so = (uint32_t)(r * 128 + ((gc ^ (r & 7)) << 4));
            cpasync16(c.sbase + st * 16384 + so, A + (size_t)(c.row0 + r) * K + k0 + gc * 8);
            cpasync16(c.sbase + 49152 + st * 16384 + so, Wt + (size_t)(c.col0 + r) * K + k0 + gc * 8);
        }
    };

    const int nchunk = K / BK;
    load_chunk(0, 0);
    CP_COMMIT();
    if (nchunk > 1) load_chunk(BK, 1);
    CP_COMMIT();

    for (int ch = 0; ch < nchunk; ch++) {
        CP_WAIT1();
        __syncthreads();
        if (ch + 2 < nchunk) load_chunk((ch + 2) * BK, (ch + 2) % 3);
        CP_COMMIT();

        const uint32_t Ab = c.sbase + (ch % 3) * 16384;
        const uint32_t Bb = c.sbase + 49152 + (ch % 3) * 16384;
#pragma unroll
        for (int ks = 0; ks < 4; ks++) {
            uint32_t bf[4][2];
#pragma unroll
            for (int np = 0; np < 2; np++) {
                int r = c.wn * 32 + np * 16 + c.b_r;
                uint32_t addr = Bb + r * 128 + (((ks * 2 + c.b_kh) ^ (r & 7)) << 4);
                ldmx4(bf[np * 2][0], bf[np * 2][1], bf[np * 2 + 1][0], bf[np * 2 + 1][1], addr);
            }
#pragma unroll
            for (int mf = 0; mf < 4; mf++) {
                int r = c.wm * 64 + mf * 16 + c.a_r;
                uint32_t addr = Ab + r * 128 + (((ks * 2 + c.a_kh) ^ (r & 7)) << 4);
                uint32_t a0, a1, a2, a3;
                ldmx4(a0, a1, a2, a3, addr);
#pragma unroll
                for (int nf = 0; nf < 4; nf++)
                    mma_bf16(acc[mf][nf], a0, a1, a2, a3, bf[nf][0], bf[nf][1]);
            }
        }
    }
}

__device__ __forceinline__ void gemm_init_ctx(GemmCtx& c, char* smem, int mt, int nt) {
    c.tid = threadIdx.x;
    c.wid = c.tid >> 5; c.lane = c.tid & 31;
    c.g = c.lane >> 2;  c.tg = c.lane & 3;
    c.wm = c.wid & 1;   c.wn = c.wid >> 1;
    c.row0 = mt * 128;  c.col0 = nt * 128;
    c.sbase = smem_u32(smem);
    c.a_r  = (c.lane & 7) + ((c.lane >> 3) & 1) * 8;
    c.a_kh = (c.lane >> 4) & 1;
    c.b_r  = (c.lane & 7) + ((c.lane >> 4) << 3);
    c.b_kh = (c.lane >> 3) & 1;
}

// ---------------------------------------------------------------------------
// Generic GEMM kernel (template epilogue), used for out-proj / ffn1 / ffn2.
// ---------------------------------------------------------------------------
template<int ACT, int OBF>
__global__ void __launch_bounds__(256, 2)
mma_gemm(const __nv_bfloat16* __restrict__ A, const __nv_bfloat16* __restrict__ Wt,
         const float* __restrict__ bias, float* __restrict__ C,
         __nv_bfloat16* __restrict__ C16, int K, int Nc, int mtiles)
{
    extern __shared__ char smem[];
    GemmCtx c;
    gemm_init_ctx(c, smem, blockIdx.x % mtiles, blockIdx.x / mtiles);
    float acc[4][4][4];
    gemm_mainloop(c, A, Wt, K, acc);

#pragma unroll
    for (int mf = 0; mf < 4; mf++) {
#pragma unroll
        for (int nf = 0; nf < 4; nf++) {
            int row = c.row0 + c.wm * 64 + mf * 16 + c.g;
            int col = c.col0 + c.wn * 32 + nf * 8 + c.tg * 2;
            float b0 = bias[col], b1 = bias[col + 1];
            float o[4];
            o[0] = acc[mf][nf][0] + b0; o[1] = acc[mf][nf][1] + b1;
            o[2] = acc[mf][nf][2] + b0; o[3] = acc[mf][nf][3] + b1;
            if (ACT) {
#pragma unroll
                for (int i = 0; i < 4; i++) o[i] = fmaxf(o[i], 0.f);
            }
            if (OBF) {
                *(__nv_bfloat162*)(&C16[(size_t)row * Nc + col]) =
                    __float22bfloat162_rn(make_float2(o[0], o[1]));
                *(__nv_bfloat162*)(&C16[(size_t)(row + 8) * Nc + col]) =
                    __float22bfloat162_rn(make_float2(o[2], o[3]));
            } else {
                *(float2*)(&C[(size_t)row * Nc + col]) = make_float2(o[0], o[1]);
                *(float2*)(&C[(size_t)(row + 8) * Nc + col]) = make_float2(o[2], o[3]);
            }
        }
    }
}

// ---------------------------------------------------------------------------
// Dual GEMM: value (bf16 out, Nc=256) + offattn (fp32 out, Nc=384) in ONE
// launch. First mtiles*2 CTAs -> value; remaining mtiles*3 -> offattn.
// Tail waves of one backfill with the other; one fewer kernel boundary.
// ---------------------------------------------------------------------------
__global__ void __launch_bounds__(256, 2)
dual_gemm(const __nv_bfloat16* __restrict__ srcb, const __nv_bfloat16* __restrict__ qb,
          const __nv_bfloat16* __restrict__ wtv, const __nv_bfloat16* __restrict__ wtoa,
          const float* __restrict__ bv, const float* __restrict__ boa,
          __nv_bfloat16* __restrict__ valbf, float* __restrict__ offattn, int mtiles)
{
    extern __shared__ char smem[];
    const int bid = blockIdx.x;
    const bool is_val = bid < mtiles * 2;
    const int local = is_val ? bid : bid - mtiles * 2;
    const int mt = local % mtiles, nt = local / mtiles;

    const __nv_bfloat16* A  = is_val ? srcb : qb;
    const __nv_bfloat16* Wt = is_val ? wtv : wtoa;
    const float* bias = is_val ? bv : boa;
    const int Nc = is_val ? 256 : 384;

    GemmCtx c;
    gemm_init_ctx(c, smem, mt, nt);
    float acc[4][4][4];
    gemm_mainloop(c, A, Wt, 256, acc);

#pragma unroll
    for (int mf = 0; mf < 4; mf++) {
#pragma unroll
        for (int nf = 0; nf < 4; nf++) {
            int row = c.row0 + c.wm * 64 + mf * 16 + c.g;
            int col = c.col0 + c.wn * 32 + nf * 8 + c.tg * 2;
            float b0 = bias[col], b1 = bias[col + 1];
            float o[4];
            o[0] = acc[mf][nf][0] + b0; o[1] = acc[mf][nf][1] + b1;
            o[2] = acc[mf][nf][2] + b0; o[3] = acc[mf][nf][3] + b1;
            if (is_val) {
                *(__nv_bfloat162*)(&valbf[(size_t)row * 256 + col]) =
                    __float22bfloat162_rn(make_float2(o[0], o[1]));
                *(__nv_bfloat162*)(&valbf[(size_t)(row + 8) * 256 + col]) =
                    __float22bfloat162_rn(make_float2(o[2], o[3]));
            } else {
                *(float2*)(&offattn[(size_t)row * Nc + col]) = make_float2(o[0], o[1]);
                *(float2*)(&offattn[(size_t)(row + 8) * Nc + col]) = make_float2(o[2], o[3]);
            }
        }
    }
}

// ---------------------------------------------------------------------------
// Deformable sampling, plan+gather per warp-token (R10 layout, conflict-free).
// ---------------------------------------------------------------------------
__global__ void __launch_bounds__(256)
sample_kernel(const __nv_bfloat16* __restrict__ valbf,
              const float* __restrict__ offattn,
              const float* __restrict__ ref,
              __nv_bfloat16* __restrict__ sampb)
{
    __shared__ float  sh[8][384];
    __shared__ float4 cws[8][8][17];
    __shared__ int4   ofs[8][8][17];

    const int w = threadIdx.x >> 5;
    const int t = blockIdx.x * 8 + w;
    const int lane = threadIdx.x & 31;
    const int n = t / LQ;

    // Phase 1: stage offattn row (1536B, coalesced).
    {
        const float4* rowp4 = (const float4*)(offattn + (size_t)t * 384);
        float4* sh4 = (float4*)sh[w];
#pragma unroll
        for (int i = 0; i < 3; i++) sh4[i * 32 + lane] = rowp4[i * 32 + lane];
    }
    __syncwarp();

    // Phase 2: plan. lane -> (hh = lane>>2, l = lane&3), 4 points of level l.
    {
        const int hh = lane >> 2;
        const int l  = lane & 3;
        const int Hs_[4] = {64, 32, 16, 8};
        const int St_[4] = {0, 4096, 5120, 5376};
        const float* lp = sh[w] + 256 + hh * 16;

        float myl[4];
#pragma unroll
        for (int k = 0; k < 4; k++) myl[k] = lp[l * 4 + k];
        float mx = fmaxf(fmaxf(myl[0], myl[1]), fmaxf(myl[2], myl[3]));
        mx = fmaxf(mx, __shfl_xor_sync(0xffffffffu, mx, 1));
        mx = fmaxf(mx, __shfl_xor_sync(0xffffffffu, mx, 2));
        float e[4], s = 0.f;
#pragma unroll
        for (int k = 0; k < 4; k++) { e[k] = expf(myl[k] - mx); s += e[k]; }
        s += __shfl_xor_sync(0xffffffffu, s, 1);
        s += __shfl_xor_sync(0xffffffffu, s, 2);
        const float inv = 1.f / s;

        const int HW = Hs_[l];
        const float fHW = (float)HW;
        const float invHW = 1.f / fHW;
        const float refx = ref[((size_t)t * NLVL + l) * 2 + 0];
        const float refy = ref[((size_t)t * NLVL + l) * 2 + 1];
        const float* op = sh[w] + hh * 32 + l * 8;
        const int ebase = (n * LQ + St_[l]) * DIM + hh * HD;

#pragma unroll
        for (int k = 0; k < 4; k++) {
            float ox = op[k * 2 + 0];
            float oy = op[k * 2 + 1];
            float xf = (refx + ox * invHW) * fHW - 0.5f;
            float yf = (refy + oy * invHW) * fHW - 0.5f;
            float x0f = floorf(xf), y0f = floorf(yf);
            int x0 = (int)x0f, y0 = (int)y0f;
            float wx1 = xf - x0f, wy1 = yf - y0f;
            float wx0 = 1.f - wx1, wy0 = 1.f - wy1;
            float wgt = e[k] * inv;

            bool xin0 = (x0 >= 0) & (x0 < HW);
            bool xin1 = (x0 + 1 >= 0) & (x0 + 1 < HW);
            bool yin0 = (y0 >= 0) & (y0 < HW);
            bool yin1 = (y0 + 1 >= 0) & (y0 + 1 < HW);

            float4 cw;
            cw.x = (yin0 && xin0) ? wgt * wy0 * wx0 : 0.f;
            cw.y = (yin0 && xin1) ? wgt * wy0 * wx1 : 0.f;
            cw.z = (yin1 && xin0) ? wgt * wy1 * wx0 : 0.f;
            cw.w = (yin1 && xin1) ? wgt * wy1 * wx1 : 0.f;
            int line = y0 * HW + x0;
            int4 off;
            off.x = (yin0 && xin0) ? (ebase + line * DIM) * 2 : 0;
            off.y = (yin0 && xin1) ? (ebase + (line + 1) * DIM) * 2 : 0;
            off.z = (yin1 && xin0) ? (ebase + (line + HW) * DIM) * 2 : 0;
            off.w = (yin1 && xin1) ? (ebase + (line + HW + 1) * DIM) * 2 : 0;
            cws[w][hh][l * 4 + k] = cw;
            ofs[w][hh][l * 4 + k] = off;
        }
    }
    __syncwarp();

    // Phase 3: gather. lane -> (h = lane>>2, d8 = lane&3).
    const int h = lane >> 2;
    const int d8 = lane & 3;
    const char* vbase = (const char*)valbf + d8 * 16;

    float acc[8];
#pragma unroll
    for (int i = 0; i < 8; i++) acc[i] = 0.f;

#pragma unroll 4
    for (int p = 0; p < 16; p++) {
        float4 cw = cws[w][h][p];
        int4 off = ofs[w][h][p];
        const int o4[4] = { off.x, off.y, off.z, off.w };
        const float c4[4] = { cw.x, cw.y, cw.z, cw.w };
#pragma unroll
        for (int cnr = 0; cnr < 4; cnr++) {
            uint4 u = *(const uint4*)(vbase + o4[cnr]);
            const __nv_bfloat162* q2 = (const __nv_bfloat162*)&u;
            float c = c4[cnr];
#pragma unroll
            for (int j = 0; j < 4; j++) {
                float2 f = __bfloat1622float2(q2[j]);
                acc[2 * j + 0] = fmaf(f.x, c, acc[2 * j + 0]);
                acc[2 * j + 1] = fmaf(f.y, c, acc[2 * j + 1]);
            }
        }
    }
    __nv_bfloat162 ob[4];
#pragma unroll
    for (int j = 0; j < 4; j++)
        ob[j] = __float22bfloat162_rn(make_float2(acc[2 * j], acc[2 * j + 1]));
    *(uint4*)(sampb + (size_t)t * DIM + h * HD + d8 * 8) = *(uint4*)ob;
}

// ---------------------------------------------------------------------------
// LayerNorm over 256: out = LN(a + b) * g + beta. One warp per token.
// b is bf16. Optional bf16 secondary output.
// ---------------------------------------------------------------------------
__global__ void ln_kernel(const float* __restrict__ a, const __nv_bfloat16* __restrict__ b,
                          const float* __restrict__ g, const float* __restrict__ beta,
                          float* __restrict__ out, __nv_bfloat16* __restrict__ out_b)
{
    const int t = blockIdx.x * 4 + (threadIdx.x >> 5);
    const int lane = threadIdx.x & 31;
    const float* pa = a + (size_t)t * DIM;
    const __nv_bfloat16* pb = b + (size_t)t * DIM;

    float v[8];
    float s = 0.f;
#pragma unroll
    for (int i = 0; i < 8; i++) {
        int c = lane + i * 32;
        v[i] = pa[c] + __bfloat162float(pb[c]);
        s += v[i];
    }
#pragma unroll
    for (int o = 16; o; o >>= 1) s += __shfl_xor_sync(0xffffffffu, s, o);
    const float mean = s * (1.f / 256.f);
    float var = 0.f;
#pragma unroll
    for (int i = 0; i < 8; i++) { float dd = v[i] - mean; var += dd * dd; }
#pragma unroll
    for (int o = 16; o; o >>= 1) var += __shfl_xor_sync(0xffffffffu, var, o);
    const float rstd = rsqrtf(var * (1.f / 256.f) + 1e-5f);
#pragma unroll
    for (int i = 0; i < 8; i++) {
        int c = lane + i * 32;
        float y = (v[i] - mean) * rstd * g[c] + beta[c];
        out[(size_t)t * DIM + c] = y;
        if (out_b) out_b[(size_t)t * DIM + c] = __float2bfloat16(y);
    }
}

// ---------------------------------------------------------------------------
extern "C" void kernel_launch(void* const* d_in, const int* in_sizes, int n_in,
                              void* d_out, int out_size)
{
    const float* src  = (const float*)d_in[0];
    const float* pos  = (const float*)d_in[1];
    const float* refp = (const float*)d_in[2];
    const float* Wv   = (const float*)d_in[4];
    const float* bv   = (const float*)d_in[5];
    const float* Wo   = (const float*)d_in[6];
    const float* bo   = (const float*)d_in[7];
    const float* Wa   = (const float*)d_in[8];
    const float* ba   = (const float*)d_in[9];
    const float* Wout = (const float*)d_in[10];
    const float* bout = (const float*)d_in[11];
    const float* g1   = (const float*)d_in[12];
    const float* be1  = (const float*)d_in[13];
    const float* W1   = (const float*)d_in[14];
    const float* b1   = (const float*)d_in[15];
    const float* W2   = (const float*)d_in[16];
    const float* b2   = (const float*)d_in[17];
    const float* g2   = (const float*)d_in[18];
    const float* be2  = (const float*)d_in[19];
    float* out = (float*)d_out;

    __nv_bfloat16 *psrcb, *pqb, *pvb, *psampb, *psrc2b, *pxb, *phidb, *pffnb;
    __nv_bfloat16 *wtv, *wtoa, *wtout, *wt1, *wt2;
    float *poa, *px, *pboa;
    cudaGetSymbolAddress((void**)&psrcb, g_srcb);
    cudaGetSymbolAddress((void**)&pqb,   g_qb);
    cudaGetSymbolAddress((void**)&pvb,   g_valbf);
    cudaGetSymbolAddress((void**)&poa,   g_offattn);
    cudaGetSymbolAddress((void**)&psampb,g_sampb);
    cudaGetSymbolAddress((void**)&psrc2b,g_src2b);
    cudaGetSymbolAddress((void**)&px,    g_x);
    cudaGetSymbolAddress((void**)&pxb,   g_xb);
    cudaGetSymbolAddress((void**)&phidb, g_hidb);
    cudaGetSymbolAddress((void**)&pffnb, g_ffnb);
    cudaGetSymbolAddress((void**)&wtv,   g_wtv);
    cudaGetSymbolAddress((void**)&wtoa,  g_wtoa);
    cudaGetSymbolAddress((void**)&wtout, g_wtout);
    cudaGetSymbolAddress((void**)&wt1,   g_wt1);
    cudaGetSymbolAddress((void**)&wt2,   g_wt2);
    cudaGetSymbolAddress((void**)&pboa,  g_boa);

    const int DSM = 98304;  // 3 stages x (16KB A + 16KB B)
    cudaFuncSetAttribute(mma_gemm<0,0>, cudaFuncAttributeMaxDynamicSharedMemorySize, DSM);
    cudaFuncSetAttribute(mma_gemm<0,1>, cudaFuncAttributeMaxDynamicSharedMemorySize, DSM);
    cudaFuncSetAttribute(mma_gemm<1,1>, cudaFuncAttributeMaxDynamicSharedMemorySize, DSM);
    cudaFuncSetAttribute(dual_gemm,     cudaFuncAttributeMaxDynamicSharedMemorySize, DSM);

    // One-shot prep
    prep_kernel<<<PREP_WBLK + PREP_ABLK + 1, 256>>>(
        Wv, Wo, Wa, Wout, W1, W2, bo, ba,
        (const float4*)src, (const float4*)pos,
        wtv, wtoa, wtout, wt1, wt2, pboa, psrcb, pqb);

    const int MT = TTOK / 128;  // 340 M-tiles

    // value (bf16) + offsets|logits (fp32) fused in ONE launch
    dual_gemm<<<MT * 5, 256, DSM>>>(psrcb, pqb, wtv, wtoa, bv, pboa, pvb, poa, MT);
    // deformable sampling (softmax fused; bf16 out)
    sample_kernel<<<TTOK / 8, 256>>>(pvb, poa, refp, psampb);
    // src2 (bf16) = samp @ Wout + bout
    mma_gemm<0,1><<<MT * 2, 256, DSM>>>(psampb, wtout, bout, nullptr, psrc2b, 256, 256, MT);
    // x = LN1(src + src2)  (fp32 + bf16 copies)
    ln_kernel<<<TTOK / 4, 128>>>(src, psrc2b, g1, be1, px, pxb);
    // hid (bf16) = relu(x @ W1 + b1)
    mma_gemm<1,1><<<MT * 8, 256, DSM>>>(pxb, wt1, b1, nullptr, phidb, 256, 1024, MT);
    // ffn (bf16) = hid @ W2 + b2
    mma_gemm<0,1><<<MT * 2, 256, DSM>>>(phidb, wt2, b2, nullptr, pffnb, 1024, 256, MT);
    // out = LN2(x + ffn)
    ln_kernel<<<TTOK / 4, 128>>>(px, pffnb, g2, be2, out, nullptr);
}

// round 13
// speedup vs baseline: 1.1685x; 1.0153x over previous
#include <cuda_runtime.h>
#include <cuda_bf16.h>
#include <cstdint>
#include <math.h>

// Problem constants (static per reference)
#define NBATCH 8
#define LQ     5440
#define TTOK   (NBATCH*LQ)      // 43520
#define DIM    256
#define NHEAD  8
#define HD     32
#define NLVL   4
#define NPT    4
#define DFF    1024

// Scratch (device globals; no runtime allocation)
__device__ __nv_bfloat16 g_srcb [(size_t)TTOK*DIM];
__device__ __nv_bfloat16 g_qb   [(size_t)TTOK*DIM];
__device__ __nv_bfloat16 g_valbf[(size_t)TTOK*DIM];
__device__ float         g_offattn[(size_t)TTOK*384];
__device__ __nv_bfloat16 g_sampb[(size_t)TTOK*DIM];
__device__ __nv_bfloat16 g_src2b[(size_t)TTOK*DIM];
__device__ float         g_x    [(size_t)TTOK*DIM];
__device__ __nv_bfloat16 g_xb   [(size_t)TTOK*DIM];
__device__ __nv_bfloat16 g_hidb [(size_t)TTOK*DFF];
__device__ __nv_bfloat16 g_ffnb [(size_t)TTOK*DIM];
// Transposed ([N][K]) bf16 weights
__device__ __nv_bfloat16 g_wtv  [256*256];
__device__ __nv_bfloat16 g_wtoa [384*256];
__device__ __nv_bfloat16 g_wtout[256*256];
__device__ __nv_bfloat16 g_wt1  [1024*256];
__device__ __nv_bfloat16 g_wt2  [256*1024];
__device__ float         g_boa  [384];

// ---------------------------------------------------------------------------
// Helpers
// ---------------------------------------------------------------------------
__device__ __forceinline__ uint32_t smem_u32(const void* p) {
    uint32_t a;
    asm("{ .reg .u64 t; cvta.to.shared.u64 t, %1; cvt.u32.u64 %0, t; }" : "=r"(a) : "l"(p));
    return a;
}
__device__ __forceinline__ void cpasync16(uint32_t dst, const void* src) {
    asm volatile("cp.async.cg.shared.global [%0], [%1], 16;" :: "r"(dst), "l"(src));
}
#define CP_COMMIT() asm volatile("cp.async.commit_group;" ::: "memory")
#define CP_WAIT1()  asm volatile("cp.async.wait_group 1;" ::: "memory")

__device__ __forceinline__ void ldmx4(uint32_t& f0, uint32_t& f1, uint32_t& f2, uint32_t& f3,
                                      uint32_t addr) {
    asm volatile("ldmatrix.sync.aligned.m8n8.x4.shared.b16 {%0,%1,%2,%3}, [%4];"
                 : "=r"(f0), "=r"(f1), "=r"(f2), "=r"(f3) : "r"(addr));
}
__device__ __forceinline__ void mma_bf16(float* c, uint32_t a0, uint32_t a1,
                                         uint32_t a2, uint32_t a3,
                                         uint32_t b0, uint32_t b1) {
    asm volatile(
        "mma.sync.aligned.m16n8k16.row.col.f32.bf16.bf16.f32 "
        "{%0,%1,%2,%3}, {%4,%5,%6,%7}, {%8,%9}, {%0,%1,%2,%3};"
        : "+f"(c[0]), "+f"(c[1]), "+f"(c[2]), "+f"(c[3])
        : "r"(a0), "r"(a1), "r"(a2), "r"(a3), "r"(b0), "r"(b1));
}

// ---------------------------------------------------------------------------
// One-shot prep: weight transposes (fp32 [K][N] -> bf16 [N][K]), bias concat,
// src/q bf16 conversion. Single launch.
// ---------------------------------------------------------------------------
#define PREP_WBLK 2944
#define PREP_ABLK 10880
__global__ void prep_kernel(const float* __restrict__ Wv, const float* __restrict__ Wo,
                            const float* __restrict__ Wa, const float* __restrict__ Wout,
                            const float* __restrict__ W1, const float* __restrict__ W2,
                            const float* __restrict__ bo, const float* __restrict__ ba,
                            const float4* __restrict__ src, const float4* __restrict__ pos,
                            __nv_bfloat16* __restrict__ wtv, __nv_bfloat16* __restrict__ wtoa,
                            __nv_bfloat16* __restrict__ wtout, __nv_bfloat16* __restrict__ wt1,
                            __nv_bfloat16* __restrict__ wt2, float* __restrict__ boa,
                            __nv_bfloat16* __restrict__ srcb, __nv_bfloat16* __restrict__ qb)
{
    int b = blockIdx.x;
    if (b < PREP_WBLK) {
        int idx = b * 256 + threadIdx.x;  // 0..753663
        float v; __nv_bfloat16* dst;
        if (idx < 65536) {                       // Wv [256,256]
            int n = idx >> 8, k = idx & 255; v = Wv[k * 256 + n]; dst = wtv + idx;
        } else if (idx < 163840) {               // Woa [384,256] = [Wo|Wa]
            int j = idx - 65536; int n = j >> 8, k = j & 255;
            v = (n < 256) ? Wo[k * 256 + n] : Wa[k * 128 + (n - 256)]; dst = wtoa + j;
        } else if (idx < 229376) {               // Wout [256,256]
            int j = idx - 163840; int n = j >> 8, k = j & 255; v = Wout[k * 256 + n]; dst = wtout + j;
        } else if (idx < 491520) {               // W1 [1024,256]
            int j = idx - 229376; int n = j >> 8, k = j & 255; v = W1[k * 1024 + n]; dst = wt1 + j;
        } else {                                 // W2 [256,1024]
            int j = idx - 491520; int n = j >> 10, k = j & 1023; v = W2[k * 256 + n]; dst = wt2 + j;
        }
        *dst = __float2bfloat16(v);
    } else if (b < PREP_WBLK + PREP_ABLK) {
        int idx = (b - PREP_WBLK) * 256 + threadIdx.x;   // float4 index
        float4 s = src[idx], p = pos[idx];
        __nv_bfloat162 s01 = __float22bfloat162_rn(make_float2(s.x, s.y));
        __nv_bfloat162 s23 = __float22bfloat162_rn(make_float2(s.z, s.w));
        __nv_bfloat162 q01 = __float22bfloat162_rn(make_float2(s.x + p.x, s.y + p.y));
        __nv_bfloat162 q23 = __float22bfloat162_rn(make_float2(s.z + p.z, s.w + p.w));
        ((uint2*)srcb)[idx] = make_uint2(*(uint32_t*)&s01, *(uint32_t*)&s23);
        ((uint2*)qb)[idx]   = make_uint2(*(uint32_t*)&q01, *(uint32_t*)&q23);
    } else {
        int i = threadIdx.x;
        if (i < 384) boa[i] = (i < 256) ? bo[i] : ba[i - 256];
    }
}

// ---------------------------------------------------------------------------
// Shared bf16 GEMM mainloop (128x128 tile, cp.async 3-stage + ldmatrix),
// with register-fragment double buffering: ks+1 fragments are loaded before
// the MMAs of ks, hiding LDSM latency behind the MMA issue burst.
// ---------------------------------------------------------------------------
#define BK 64

struct GemmCtx {
    int tid, wid, lane, g, tg, wm, wn, row0, col0;
    uint32_t sbase;
    int a_r, a_kh, b_r, b_kh;
};

__device__ __forceinline__ void load_frags(
    const GemmCtx& c, uint32_t Ab, uint32_t Bb, int ks,
    uint32_t af[4][4], uint32_t bf[4][2])
{
#pragma unroll
    for (int np = 0; np < 2; np++) {
        int r = c.wn * 32 + np * 16 + c.b_r;
        uint32_t addr = Bb + r * 128 + (((ks * 2 + c.b_kh) ^ (r & 7)) << 4);
        ldmx4(bf[np * 2][0], bf[np * 2][1], bf[np * 2 + 1][0], bf[np * 2 + 1][1], addr);
    }
#pragma unroll
    for (int mf = 0; mf < 4; mf++) {
        int r = c.wm * 64 + mf * 16 + c.a_r;
        uint32_t addr = Ab + r * 128 + (((ks * 2 + c.a_kh) ^ (r & 7)) << 4);
        ldmx4(af[mf][0], af[mf][1], af[mf][2], af[mf][3], addr);
    }
}

__device__ __forceinline__ void gemm_mainloop(
    GemmCtx& c, const __nv_bfloat16* __restrict__ A,
    const __nv_bfloat16* __restrict__ Wt, int K, float acc[4][4][4])
{
#pragma unroll
    for (int i = 0; i < 4; i++)
#pragma unroll
        for (int j = 0; j < 4; j++)
#pragma unroll
            for (int k = 0; k < 4; k++) acc[i][j][k] = 0.f;

    auto load_chunk = [&](int k0, int st) {
#pragma unroll
        for (int i = 0; i < 4; i++) {
            int idx = c.tid + i * 256;
            int r = idx >> 3, gc = idx & 7;
            uint32_t so = (uint32_t)(r * 128 + ((gc ^ (r & 7)) << 4));
            cpasync16(c.sbase + st * 16384 + so, A + (size_t)(c.row0 + r) * K + k0 + gc * 8);
            cpasync16(c.sbase + 49152 + st * 16384 + so, Wt + (size_t)(c.col0 + r) * K + k0 + gc * 8);
        }
    };

    const int nchunk = K / BK;
    load_chunk(0, 0);
    CP_COMMIT();
    if (nchunk > 1) load_chunk(BK, 1);
    CP_COMMIT();

    uint32_t af[2][4][4], bf[2][4][2];

    for (int ch = 0; ch < nchunk; ch++) {
        CP_WAIT1();
        __syncthreads();
        if (ch + 2 < nchunk) load_chunk((ch + 2) * BK, (ch + 2) % 3);
        CP_COMMIT();

        const uint32_t Ab = c.sbase + (ch % 3) * 16384;
        const uint32_t Bb = c.sbase + 49152 + (ch % 3) * 16384;

        load_frags(c, Ab, Bb, 0, af[0], bf[0]);
#pragma unroll
        for (int ks = 0; ks < 4; ks++) {
            const int cur = ks & 1, nx = cur ^ 1;
            if (ks < 3) load_frags(c, Ab, Bb, ks + 1, af[nx], bf[nx]);
#pragma unroll
            for (int mf = 0; mf < 4; mf++)
#pragma unroll
                for (int nf = 0; nf < 4; nf++)
                    mma_bf16(acc[mf][nf], af[cur][mf][0], af[cur][mf][1],
                             af[cur][mf][2], af[cur][mf][3],
                             bf[cur][nf][0], bf[cur][nf][1]);
        }
    }
}

__device__ __forceinline__ void gemm_init_ctx(GemmCtx& c, char* smem, int mt, int nt) {
    c.tid = threadIdx.x;
    c.wid = c.tid >> 5; c.lane = c.tid & 31;
    c.g = c.lane >> 2;  c.tg = c.lane & 3;
    c.wm = c.wid & 1;   c.wn = c.wid >> 1;
    c.row0 = mt * 128;  c.col0 = nt * 128;
    c.sbase = smem_u32(smem);
    c.a_r  = (c.lane & 7) + ((c.lane >> 3) & 1) * 8;
    c.a_kh = (c.lane >> 4) & 1;
    c.b_r  = (c.lane & 7) + ((c.lane >> 4) << 3);
    c.b_kh = (c.lane >> 3) & 1;
}

// ---------------------------------------------------------------------------
// Generic GEMM kernel (template epilogue), used for out-proj / ffn1 / ffn2.
// ---------------------------------------------------------------------------
template<int ACT, int OBF>
__global__ void __launch_bounds__(256, 2)
mma_gemm(const __nv_bfloat16* __restrict__ A, const __nv_bfloat16* __restrict__ Wt,
         const float* __restrict__ bias, float* __restrict__ C,
         __nv_bfloat16* __restrict__ C16, int K, int Nc, int mtiles)
{
    extern __shared__ char smem[];
    GemmCtx c;
    gemm_init_ctx(c, smem, blockIdx.x % mtiles, blockIdx.x / mtiles);
    float acc[4][4][4];
    gemm_mainloop(c, A, Wt, K, acc);

#pragma unroll
    for (int mf = 0; mf < 4; mf++) {
#pragma unroll
        for (int nf = 0; nf < 4; nf++) {
            int row = c.row0 + c.wm * 64 + mf * 16 + c.g;
            int col = c.col0 + c.wn * 32 + nf * 8 + c.tg * 2;
            float b0 = bias[col], b1 = bias[col + 1];
            float o[4];
            o[0] = acc[mf][nf][0] + b0; o[1] = acc[mf][nf][1] + b1;
            o[2] = acc[mf][nf][2] + b0; o[3] = acc[mf][nf][3] + b1;
            if (ACT) {
#pragma unroll
                for (int i = 0; i < 4; i++) o[i] = fmaxf(o[i], 0.f);
            }
            if (OBF) {
                *(__nv_bfloat162*)(&C16[(size_t)row * Nc + col]) =
                    __float22bfloat162_rn(make_float2(o[0], o[1]));
                *(__nv_bfloat162*)(&C16[(size_t)(row + 8) * Nc + col]) =
                    __float22bfloat162_rn(make_float2(o[2], o[3]));
            } else {
                *(float2*)(&C[(size_t)row * Nc + col]) = make_float2(o[0], o[1]);
                *(float2*)(&C[(size_t)(row + 8) * Nc + col]) = make_float2(o[2], o[3]);
            }
        }
    }
}

// ---------------------------------------------------------------------------
// Dual GEMM: value (bf16 out, Nc=256) + offattn (fp32 out, Nc=384) in ONE
// launch.
// ---------------------------------------------------------------------------
__global__ void __launch_bounds__(256, 2)
dual_gemm(const __nv_bfloat16* __restrict__ srcb, const __nv_bfloat16* __restrict__ qb,
          const __nv_bfloat16* __restrict__ wtv, const __nv_bfloat16* __restrict__ wtoa,
          const float* __restrict__ bv, const float* __restrict__ boa,
          __nv_bfloat16* __restrict__ valbf, float* __restrict__ offattn, int mtiles)
{
    extern __shared__ char smem[];
    const int bid = blockIdx.x;
    const bool is_val = bid < mtiles * 2;
    const int local = is_val ? bid : bid - mtiles * 2;
    const int mt = local % mtiles, nt = local / mtiles;

    const __nv_bfloat16* A  = is_val ? srcb : qb;
    const __nv_bfloat16* Wt = is_val ? wtv : wtoa;
    const float* bias = is_val ? bv : boa;
    const int Nc = is_val ? 256 : 384;

    GemmCtx c;
    gemm_init_ctx(c, smem, mt, nt);
    float acc[4][4][4];
    gemm_mainloop(c, A, Wt, 256, acc);

#pragma unroll
    for (int mf = 0; mf < 4; mf++) {
#pragma unroll
        for (int nf = 0; nf < 4; nf++) {
            int row = c.row0 + c.wm * 64 + mf * 16 + c.g;
            int col = c.col0 + c.wn * 32 + nf * 8 + c.tg * 2;
            float b0 = bias[col], b1 = bias[col + 1];
            float o[4];
            o[0] = acc[mf][nf][0] + b0; o[1] = acc[mf][nf][1] + b1;
            o[2] = acc[mf][nf][2] + b0; o[3] = acc[mf][nf][3] + b1;
            if (is_val) {
                *(__nv_bfloat162*)(&valbf[(size_t)row * 256 + col]) =
                    __float22bfloat162_rn(make_float2(o[0], o[1]));
                *(__nv_bfloat162*)(&valbf[(size_t)(row + 8) * 256 + col]) =
                    __float22bfloat162_rn(make_float2(o[2], o[3]));
            } else {
                *(float2*)(&offattn[(size_t)row * Nc + col]) = make_float2(o[0], o[1]);
                *(float2*)(&offattn[(size_t)(row + 8) * Nc + col]) = make_float2(o[2], o[3]);
            }
        }
    }
}

// ---------------------------------------------------------------------------
// Deformable sampling, plan+gather per warp-token (R10 layout, conflict-free).
// ---------------------------------------------------------------------------
__global__ void __launch_bounds__(256)
sample_kernel(const __nv_bfloat16* __restrict__ valbf,
              const float* __restrict__ offattn,
              const float* __restrict__ ref,
              __nv_bfloat16* __restrict__ sampb)
{
    __shared__ float  sh[8][384];
    __shared__ float4 cws[8][8][17];
    __shared__ int4   ofs[8][8][17];

    const int w = threadIdx.x >> 5;
    const int t = blockIdx.x * 8 + w;
    const int lane = threadIdx.x & 31;
    const int n = t / LQ;

    // Phase 1: stage offattn row (1536B, coalesced).
    {
        const float4* rowp4 = (const float4*)(offattn + (size_t)t * 384);
        float4* sh4 = (float4*)sh[w];
#pragma unroll
        for (int i = 0; i < 3; i++) sh4[i * 32 + lane] = rowp4[i * 32 + lane];
    }
    __syncwarp();

    // Phase 2: plan. lane -> (hh = lane>>2, l = lane&3), 4 points of level l.
    {
        const int hh = lane >> 2;
        const int l  = lane & 3;
        const int Hs_[4] = {64, 32, 16, 8};
        const int St_[4] = {0, 4096, 5120, 5376};
        const float* lp = sh[w] + 256 + hh * 16;

        float myl[4];
#pragma unroll
        for (int k = 0; k < 4; k++) myl[k] = lp[l * 4 + k];
        float mx = fmaxf(fmaxf(myl[0], myl[1]), fmaxf(myl[2], myl[3]));
        mx = fmaxf(mx, __shfl_xor_sync(0xffffffffu, mx, 1));
        mx = fmaxf(mx, __shfl_xor_sync(0xffffffffu, mx, 2));
        float e[4], s = 0.f;
#pragma unroll
        for (int k = 0; k < 4; k++) { e[k] = expf(myl[k] - mx); s += e[k]; }
        s += __shfl_xor_sync(0xffffffffu, s, 1);
        s += __shfl_xor_sync(0xffffffffu, s, 2);
        const float inv = 1.f / s;

        const int HW = Hs_[l];
        const float fHW = (float)HW;
        const float invHW = 1.f / fHW;
        const float refx = ref[((size_t)t * NLVL + l) * 2 + 0];
        const float refy = ref[((size_t)t * NLVL + l) * 2 + 1];
        const float* op = sh[w] + hh * 32 + l * 8;
        const int ebase = (n * LQ + St_[l]) * DIM + hh * HD;

#pragma unroll
        for (int k = 0; k < 4; k++) {
            float ox = op[k * 2 + 0];
            float oy = op[k * 2 + 1];
            float xf = (refx + ox * invHW) * fHW - 0.5f;
            float yf = (refy + oy * invHW) * fHW - 0.5f;
            float x0f = floorf(xf), y0f = floorf(yf);
            int x0 = (int)x0f, y0 = (int)y0f;
            float wx1 = xf - x0f, wy1 = yf - y0f;
            float wx0 = 1.f - wx1, wy0 = 1.f - wy1;
            float wgt = e[k] * inv;

            bool xin0 = (x0 >= 0) & (x0 < HW);
            bool xin1 = (x0 + 1 >= 0) & (x0 + 1 < HW);
            bool yin0 = (y0 >= 0) & (y0 < HW);
            bool yin1 = (y0 + 1 >= 0) & (y0 + 1 < HW);

            float4 cw;
            cw.x = (yin0 && xin0) ? wgt * wy0 * wx0 : 0.f;
            cw.y = (yin0 && xin1) ? wgt * wy0 * wx1 : 0.f;
            cw.z = (yin1 && xin0) ? wgt * wy1 * wx0 : 0.f;
            cw.w = (yin1 && xin1) ? wgt * wy1 * wx1 : 0.f;
            int line = y0 * HW + x0;
            int4 off;
            off.x = (yin0 && xin0) ? (ebase + line * DIM) * 2 : 0;
            off.y = (yin0 && xin1) ? (ebase + (line + 1) * DIM) * 2 : 0;
            off.z = (yin1 && xin0) ? (ebase + (line + HW) * DIM) * 2 : 0;
            off.w = (yin1 && xin1) ? (ebase + (line + HW + 1) * DIM) * 2 : 0;
            cws[w][hh][l * 4 + k] = cw;
            ofs[w][hh][l * 4 + k] = off;
        }
    }
    __syncwarp();

    // Phase 3: gather. lane -> (h = lane>>2, d8 = lane&3).
    const int h = lane >> 2;
    const int d8 = lane & 3;
    const char* vbase = (const char*)valbf + d8 * 16;

    float acc[8];
#pragma unroll
    for (int i = 0; i < 8; i++) acc[i] = 0.f;

#pragma unroll 4
    for (int p = 0; p < 16; p++) {
        float4 cw = cws[w][h][p];
        int4 off = ofs[w][h][p];
        const int o4[4] = { off.x, off.y, off.z, off.w };
        const float c4[4] = { cw.x, cw.y, cw.z, cw.w };
#pragma unroll
        for (int cnr = 0; cnr < 4; cnr++) {
            uint4 u = *(const uint4*)(vbase + o4[cnr]);
            const __nv_bfloat162* q2 = (const __nv_bfloat162*)&u;
            float c = c4[cnr];
#pragma unroll
            for (int j = 0; j < 4; j++) {
                float2 f = __bfloat1622float2(q2[j]);
                acc[2 * j + 0] = fmaf(f.x, c, acc[2 * j + 0]);
                acc[2 * j + 1] = fmaf(f.y, c, acc[2 * j + 1]);
            }
        }
    }
    __nv_bfloat162 ob[4];
#pragma unroll
    for (int j = 0; j < 4; j++)
        ob[j] = __float22bfloat162_rn(make_float2(acc[2 * j], acc[2 * j + 1]));
    *(uint4*)(sampb + (size_t)t * DIM + h * HD + d8 * 8) = *(uint4*)ob;
}

// ---------------------------------------------------------------------------
// LayerNorm over 256: out = LN(a + b) * g + beta. One warp per token.
// b is bf16. Optional bf16 secondary output.
// ---------------------------------------------------------------------------
__global__ void ln_kernel(const float* __restrict__ a, const __nv_bfloat16* __restrict__ b,
                          const float* __restrict__ g, const float* __restrict__ beta,
                          float* __restrict__ out, __nv_bfloat16* __restrict__ out_b)
{
    const int t = blockIdx.x * 4 + (threadIdx.x >> 5);
    const int lane = threadIdx.x & 31;
    const float* pa = a + (size_t)t * DIM;
    const __nv_bfloat16* pb = b + (size_t)t * DIM;

    float v[8];
    float s = 0.f;
#pragma unroll
    for (int i = 0; i < 8; i++) {
        int c = lane + i * 32;
        v[i] = pa[c] + __bfloat162float(pb[c]);
        s += v[i];
    }
#pragma unroll
    for (int o = 16; o; o >>= 1) s += __shfl_xor_sync(0xffffffffu, s, o);
    const float mean = s * (1.f / 256.f);
    float var = 0.f;
#pragma unroll
    for (int i = 0; i < 8; i++) { float dd = v[i] - mean; var += dd * dd; }
#pragma unroll
    for (int o = 16; o; o >>= 1) var += __shfl_xor_sync(0xffffffffu, var, o);
    const float rstd = rsqrtf(var * (1.f / 256.f) + 1e-5f);
#pragma unroll
    for (int i = 0; i < 8; i++) {
        int c = lane + i * 32;
        float y = (v[i] - mean) * rstd * g[c] + beta[c];
        out[(size_t)t * DIM + c] = y;
        if (out_b) out_b[(size_t)t * DIM + c] = __float2bfloat16(y);
    }
}

// ---------------------------------------------------------------------------
extern "C" void kernel_launch(void* const* d_in, const int* in_sizes, int n_in,
                              void* d_out, int out_size)
{
    const float* src  = (const float*)d_in[0];
    const float* pos  = (const float*)d_in[1];
    const float* refp = (const float*)d_in[2];
    const float* Wv   = (const float*)d_in[4];
    const float* bv   = (const float*)d_in[5];
    const float* Wo   = (const float*)d_in[6];
    const float* bo   = (const float*)d_in[7];
    const float* Wa   = (const float*)d_in[8];
    const float* ba   = (const float*)d_in[9];
    const float* Wout = (const float*)d_in[10];
    const float* bout = (const float*)d_in[11];
    const float* g1   = (const float*)d_in[12];
    const float* be1  = (const float*)d_in[13];
    const float* W1   = (const float*)d_in[14];
    const float* b1   = (const float*)d_in[15];
    const float* W2   = (const float*)d_in[16];
    const float* b2   = (const float*)d_in[17];
    const float* g2   = (const float*)d_in[18];
    const float* be2  = (const float*)d_in[19];
    float* out = (float*)d_out;

    __nv_bfloat16 *psrcb, *pqb, *pvb, *psampb, *psrc2b, *pxb, *phidb, *pffnb;
    __nv_bfloat16 *wtv, *wtoa, *wtout, *wt1, *wt2;
    float *poa, *px, *pboa;
    cudaGetSymbolAddress((void**)&psrcb, g_srcb);
    cudaGetSymbolAddress((void**)&pqb,   g_qb);
    cudaGetSymbolAddress((void**)&pvb,   g_valbf);
    cudaGetSymbolAddress((void**)&poa,   g_offattn);
    cudaGetSymbolAddress((void**)&psampb,g_sampb);
    cudaGetSymbolAddress((void**)&psrc2b,g_src2b);
    cudaGetSymbolAddress((void**)&px,    g_x);
    cudaGetSymbolAddress((void**)&pxb,   g_xb);
    cudaGetSymbolAddress((void**)&phidb, g_hidb);
    cudaGetSymbolAddress((void**)&pffnb, g_ffnb);
    cudaGetSymbolAddress((void**)&wtv,   g_wtv);
    cudaGetSymbolAddress((void**)&wtoa,  g_wtoa);
    cudaGetSymbolAddress((void**)&wtout, g_wtout);
    cudaGetSymbolAddress((void**)&wt1,   g_wt1);
    cudaGetSymbolAddress((void**)&wt2,   g_wt2);
    cudaGetSymbolAddress((void**)&pboa,  g_boa);

    const int DSM = 98304;  // 3 stages x (16KB A + 16KB B)
    cudaFuncSetAttribute(mma_gemm<0,0>, cudaFuncAttributeMaxDynamicSharedMemorySize, DSM);
    cudaFuncSetAttribute(mma_gemm<0,1>, cudaFuncAttributeMaxDynamicSharedMemorySize, DSM);
    cudaFuncSetAttribute(mma_gemm<1,1>, cudaFuncAttributeMaxDynamicSharedMemorySize, DSM);
    cudaFuncSetAttribute(dual_gemm,     cudaFuncAttributeMaxDynamicSharedMemorySize, DSM);

    // One-shot prep
    prep_kernel<<<PREP_WBLK + PREP_ABLK + 1, 256>>>(
        Wv, Wo, Wa, Wout, W1, W2, bo, ba,
        (const float4*)src, (const float4*)pos,
        wtv, wtoa, wtout, wt1, wt2, pboa, psrcb, pqb);

    const int MT = TTOK / 128;  // 340 M-tiles

    // value (bf16) + offsets|logits (fp32) fused in ONE launch
    dual_gemm<<<MT * 5, 256, DSM>>>(psrcb, pqb, wtv, wtoa, bv, pboa, pvb, poa, MT);
    // deformable sampling (softmax fused; bf16 out)
    sample_kernel<<<TTOK / 8, 256>>>(pvb, poa, refp, psampb);
    // src2 (bf16) = samp @ Wout + bout
    mma_gemm<0,1><<<MT * 2, 256, DSM>>>(psampb, wtout, bout, nullptr, psrc2b, 256, 256, MT);
    // x = LN1(src + src2)  (fp32 + bf16 copies)
    ln_kernel<<<TTOK / 4, 128>>>(src, psrc2b, g1, be1, px, pxb);
    // hid (bf16) = relu(x @ W1 + b1)
    mma_gemm<1,1><<<MT * 8, 256, DSM>>>(pxb, wt1, b1, nullptr, phidb, 256, 1024, MT);
    // ffn (bf16) = hid @ W2 + b2
    mma_gemm<0,1><<<MT * 2, 256, DSM>>>(phidb, wt2, b2, nullptr, pffnb, 1024, 256, MT);
    // out = LN2(x + ffn)
    ln_kernel<<<TTOK / 4, 128>>>(px, pffnb, g2, be2, out, nullptr);
}

// round 14
// speedup vs baseline: 1.2146x; 1.0394x over previous
#include <cuda_runtime.h>
#include <cuda_bf16.h>
#include <cstdint>
#include <math.h>

// Problem constants (static per reference)
#define NBATCH 8
#define LQ     5440
#define TTOK   (NBATCH*LQ)      // 43520
#define DIM    256
#define NHEAD  8
#define HD     32
#define NLVL   4
#define NPT    4
#define DFF    1024

// Scratch (device globals; no runtime allocation)
__device__ __nv_bfloat16 g_srcb [(size_t)TTOK*DIM];
__device__ __nv_bfloat16 g_qb   [(size_t)TTOK*DIM];
__device__ __nv_bfloat16 g_valbf[(size_t)TTOK*DIM];
__device__ float         g_offattn[(size_t)TTOK*384];
__device__ __nv_bfloat16 g_sampb[(size_t)TTOK*DIM];
__device__ __nv_bfloat16 g_src2b[(size_t)TTOK*DIM];
__device__ float         g_x    [(size_t)TTOK*DIM];
__device__ __nv_bfloat16 g_xb   [(size_t)TTOK*DIM];
__device__ __nv_bfloat16 g_hidb [(size_t)TTOK*DFF];
__device__ __nv_bfloat16 g_ffnb [(size_t)TTOK*DIM];
// Transposed ([N][K]) bf16 weights
__device__ __nv_bfloat16 g_wtv  [256*256];
__device__ __nv_bfloat16 g_wtoa [384*256];
__device__ __nv_bfloat16 g_wtout[256*256];
__device__ __nv_bfloat16 g_wt1  [1024*256];
__device__ __nv_bfloat16 g_wt2  [256*1024];
__device__ float         g_boa  [384];

// ---------------------------------------------------------------------------
// Helpers
// ---------------------------------------------------------------------------
__device__ __forceinline__ uint32_t smem_u32(const void* p) {
    uint32_t a;
    asm("{ .reg .u64 t; cvta.to.shared.u64 t, %1; cvt.u32.u64 %0, t; }" : "=r"(a) : "l"(p));
    return a;
}
__device__ __forceinline__ void cpasync16(uint32_t dst, const void* src) {
    asm volatile("cp.async.cg.shared.global [%0], [%1], 16;" :: "r"(dst), "l"(src));
}
#define CP_COMMIT() asm volatile("cp.async.commit_group;" ::: "memory")
#define CP_WAIT1()  asm volatile("cp.async.wait_group 1;" ::: "memory")

__device__ __forceinline__ void ldmx4(uint32_t& f0, uint32_t& f1, uint32_t& f2, uint32_t& f3,
                                      uint32_t addr) {
    asm volatile("ldmatrix.sync.aligned.m8n8.x4.shared.b16 {%0,%1,%2,%3}, [%4];"
                 : "=r"(f0), "=r"(f1), "=r"(f2), "=r"(f3) : "r"(addr));
}
__device__ __forceinline__ void mma_bf16(float* c, uint32_t a0, uint32_t a1,
                                         uint32_t a2, uint32_t a3,
                                         uint32_t b0, uint32_t b1) {
    asm volatile(
        "mma.sync.aligned.m16n8k16.row.col.f32.bf16.bf16.f32 "
        "{%0,%1,%2,%3}, {%4,%5,%6,%7}, {%8,%9}, {%0,%1,%2,%3};"
        : "+f"(c[0]), "+f"(c[1]), "+f"(c[2]), "+f"(c[3])
        : "r"(a0), "r"(a1), "r"(a2), "r"(a3), "r"(b0), "r"(b1));
}

// ---------------------------------------------------------------------------
// One-shot prep: weight transposes (fp32 [K][N] -> bf16 [N][K]), bias concat,
// src/q bf16 conversion. Single launch.
// ---------------------------------------------------------------------------
#define PREP_WBLK 2944
#define PREP_ABLK 10880
__global__ void prep_kernel(const float* __restrict__ Wv, const float* __restrict__ Wo,
                            const float* __restrict__ Wa, const float* __restrict__ Wout,
                            const float* __restrict__ W1, const float* __restrict__ W2,
                            const float* __restrict__ bo, const float* __restrict__ ba,
                            const float4* __restrict__ src, const float4* __restrict__ pos,
                            __nv_bfloat16* __restrict__ wtv, __nv_bfloat16* __restrict__ wtoa,
                            __nv_bfloat16* __restrict__ wtout, __nv_bfloat16* __restrict__ wt1,
                            __nv_bfloat16* __restrict__ wt2, float* __restrict__ boa,
                            __nv_bfloat16* __restrict__ srcb, __nv_bfloat16* __restrict__ qb)
{
    int b = blockIdx.x;
    if (b < PREP_WBLK) {
        int idx = b * 256 + threadIdx.x;  // 0..753663
        float v; __nv_bfloat16* dst;
        if (idx < 65536) {                       // Wv [256,256]
            int n = idx >> 8, k = idx & 255; v = Wv[k * 256 + n]; dst = wtv + idx;
        } else if (idx < 163840) {               // Woa [384,256] = [Wo|Wa]
            int j = idx - 65536; int n = j >> 8, k = j & 255;
            v = (n < 256) ? Wo[k * 256 + n] : Wa[k * 128 + (n - 256)]; dst = wtoa + j;
        } else if (idx < 229376) {               // Wout [256,256]
            int j = idx - 163840; int n = j >> 8, k = j & 255; v = Wout[k * 256 + n]; dst = wtout + j;
        } else if (idx < 491520) {               // W1 [1024,256]
            int j = idx - 229376; int n = j >> 8, k = j & 255; v = W1[k * 1024 + n]; dst = wt1 + j;
        } else {                                 // W2 [256,1024]
            int j = idx - 491520; int n = j >> 10, k = j & 1023; v = W2[k * 256 + n]; dst = wt2 + j;
        }
        *dst = __float2bfloat16(v);
    } else if (b < PREP_WBLK + PREP_ABLK) {
        int idx = (b - PREP_WBLK) * 256 + threadIdx.x;   // float4 index
        float4 s = src[idx], p = pos[idx];
        __nv_bfloat162 s01 = __float22bfloat162_rn(make_float2(s.x, s.y));
        __nv_bfloat162 s23 = __float22bfloat162_rn(make_float2(s.z, s.w));
        __nv_bfloat162 q01 = __float22bfloat162_rn(make_float2(s.x + p.x, s.y + p.y));
        __nv_bfloat162 q23 = __float22bfloat162_rn(make_float2(s.z + p.z, s.w + p.w));
        ((uint2*)srcb)[idx] = make_uint2(*(uint32_t*)&s01, *(uint32_t*)&s23);
        ((uint2*)qb)[idx]   = make_uint2(*(uint32_t*)&q01, *(uint32_t*)&q23);
    } else {
        int i = threadIdx.x;
        if (i < 384) boa[i] = (i < 256) ? bo[i] : ba[i - 256];
    }
}

// ---------------------------------------------------------------------------
// Shared bf16 GEMM mainloop (128x128 tile, cp.async 3-stage + ldmatrix),
// compile-time K for full unroll; register-fragment double buffering.
// ---------------------------------------------------------------------------
#define BK 64

struct GemmCtx {
    int tid, wid, lane, g, tg, wm, wn, row0, col0;
    uint32_t sbase;
    int a_r, a_kh, b_r, b_kh;
};

__device__ __forceinline__ void load_frags(
    const GemmCtx& c, uint32_t Ab, uint32_t Bb, int ks,
    uint32_t af[4][4], uint32_t bf[4][2])
{
#pragma unroll
    for (int np = 0; np < 2; np++) {
        int r = c.wn * 32 + np * 16 + c.b_r;
        uint32_t addr = Bb + r * 128 + (((ks * 2 + c.b_kh) ^ (r & 7)) << 4);
        ldmx4(bf[np * 2][0], bf[np * 2][1], bf[np * 2 + 1][0], bf[np * 2 + 1][1], addr);
    }
#pragma unroll
    for (int mf = 0; mf < 4; mf++) {
        int r = c.wm * 64 + mf * 16 + c.a_r;
        uint32_t addr = Ab + r * 128 + (((ks * 2 + c.a_kh) ^ (r & 7)) << 4);
        ldmx4(af[mf][0], af[mf][1], af[mf][2], af[mf][3], addr);
    }
}

template<int K>
__device__ __forceinline__ void gemm_mainloop(
    GemmCtx& c, const __nv_bfloat16* __restrict__ A,
    const __nv_bfloat16* __restrict__ Wt, float acc[4][4][4])
{
#pragma unroll
    for (int i = 0; i < 4; i++)
#pragma unroll
        for (int j = 0; j < 4; j++)
#pragma unroll
            for (int k = 0; k < 4; k++) acc[i][j][k] = 0.f;

    auto load_chunk = [&](int k0, int st) {
#pragma unroll
        for (int i = 0; i < 4; i++) {
            int idx = c.tid + i * 256;
            int r = idx >> 3, gc = idx & 7;
            uint32_t so = (uint32_t)(r * 128 + ((gc ^ (r & 7)) << 4));
            cpasync16(c.sbase + st * 16384 + so, A + (size_t)(c.row0 + r) * K + k0 + gc * 8);
            cpasync16(c.sbase + 49152 + st * 16384 + so, Wt + (size_t)(c.col0 + r) * K + k0 + gc * 8);
        }
    };

    constexpr int nchunk = K / BK;
    load_chunk(0, 0);
    CP_COMMIT();
    if (nchunk > 1) load_chunk(BK, 1);
    CP_COMMIT();

    uint32_t af[2][4][4], bf[2][4][2];

#pragma unroll
    for (int ch = 0; ch < nchunk; ch++) {
        CP_WAIT1();
        __syncthreads();
        if (ch + 2 < nchunk) load_chunk((ch + 2) * BK, (ch + 2) % 3);
        CP_COMMIT();

        const uint32_t Ab = c.sbase + (ch % 3) * 16384;
        const uint32_t Bb = c.sbase + 49152 + (ch % 3) * 16384;

        load_frags(c, Ab, Bb, 0, af[0], bf[0]);
#pragma unroll
        for (int ks = 0; ks < 4; ks++) {
            const int cur = ks & 1, nx = cur ^ 1;
            if (ks < 3) load_frags(c, Ab, Bb, ks + 1, af[nx], bf[nx]);
#pragma unroll
            for (int mf = 0; mf < 4; mf++)
#pragma unroll
                for (int nf = 0; nf < 4; nf++)
                    mma_bf16(acc[mf][nf], af[cur][mf][0], af[cur][mf][1],
                             af[cur][mf][2], af[cur][mf][3],
                             bf[cur][nf][0], bf[cur][nf][1]);
        }
    }
}

__device__ __forceinline__ void gemm_init_ctx(GemmCtx& c, char* smem, int mt, int nt) {
    c.tid = threadIdx.x;
    c.wid = c.tid >> 5; c.lane = c.tid & 31;
    c.g = c.lane >> 2;  c.tg = c.lane & 3;
    c.wm = c.wid & 1;   c.wn = c.wid >> 1;
    c.row0 = mt * 128;  c.col0 = nt * 128;
    c.sbase = smem_u32(smem);
    c.a_r  = (c.lane & 7) + ((c.lane >> 3) & 1) * 8;
    c.a_kh = (c.lane >> 4) & 1;
    c.b_r  = (c.lane & 7) + ((c.lane >> 4) << 3);
    c.b_kh = (c.lane >> 3) & 1;
}

// ---------------------------------------------------------------------------
// Generic GEMM kernel (template epilogue + compile-time K).
// ---------------------------------------------------------------------------
template<int ACT, int OBF, int K>
__global__ void __launch_bounds__(256, 2)
mma_gemm(const __nv_bfloat16* __restrict__ A, const __nv_bfloat16* __restrict__ Wt,
         const float* __restrict__ bias, float* __restrict__ C,
         __nv_bfloat16* __restrict__ C16, int Nc, int mtiles)
{
    extern __shared__ char smem[];
    GemmCtx c;
    gemm_init_ctx(c, smem, blockIdx.x % mtiles, blockIdx.x / mtiles);
    float acc[4][4][4];
    gemm_mainloop<K>(c, A, Wt, acc);

#pragma unroll
    for (int mf = 0; mf < 4; mf++) {
#pragma unroll
        for (int nf = 0; nf < 4; nf++) {
            int row = c.row0 + c.wm * 64 + mf * 16 + c.g;
            int col = c.col0 + c.wn * 32 + nf * 8 + c.tg * 2;
            float b0 = bias[col], b1 = bias[col + 1];
            float o[4];
            o[0] = acc[mf][nf][0] + b0; o[1] = acc[mf][nf][1] + b1;
            o[2] = acc[mf][nf][2] + b0; o[3] = acc[mf][nf][3] + b1;
            if (ACT) {
#pragma unroll
                for (int i = 0; i < 4; i++) o[i] = fmaxf(o[i], 0.f);
            }
            if (OBF) {
                *(__nv_bfloat162*)(&C16[(size_t)row * Nc + col]) =
                    __float22bfloat162_rn(make_float2(o[0], o[1]));
                *(__nv_bfloat162*)(&C16[(size_t)(row + 8) * Nc + col]) =
                    __float22bfloat162_rn(make_float2(o[2], o[3]));
            } else {
                *(float2*)(&C[(size_t)row * Nc + col]) = make_float2(o[0], o[1]);
                *(float2*)(&C[(size_t)(row + 8) * Nc + col]) = make_float2(o[2], o[3]);
            }
        }
    }
}

// ---------------------------------------------------------------------------
// Dual GEMM: value (bf16 out, Nc=256) + offattn (fp32 out, Nc=384), K=256.
// ---------------------------------------------------------------------------
__global__ void __launch_bounds__(256, 2)
dual_gemm(const __nv_bfloat16* __restrict__ srcb, const __nv_bfloat16* __restrict__ qb,
          const __nv_bfloat16* __restrict__ wtv, const __nv_bfloat16* __restrict__ wtoa,
          const float* __restrict__ bv, const float* __restrict__ boa,
          __nv_bfloat16* __restrict__ valbf, float* __restrict__ offattn, int mtiles)
{
    extern __shared__ char smem[];
    const int bid = blockIdx.x;
    const bool is_val = bid < mtiles * 2;
    const int local = is_val ? bid : bid - mtiles * 2;
    const int mt = local % mtiles, nt = local / mtiles;

    const __nv_bfloat16* A  = is_val ? srcb : qb;
    const __nv_bfloat16* Wt = is_val ? wtv : wtoa;
    const float* bias = is_val ? bv : boa;
    const int Nc = is_val ? 256 : 384;

    GemmCtx c;
    gemm_init_ctx(c, smem, mt, nt);
    float acc[4][4][4];
    gemm_mainloop<256>(c, A, Wt, acc);

#pragma unroll
    for (int mf = 0; mf < 4; mf++) {
#pragma unroll
        for (int nf = 0; nf < 4; nf++) {
            int row = c.row0 + c.wm * 64 + mf * 16 + c.g;
            int col = c.col0 + c.wn * 32 + nf * 8 + c.tg * 2;
            float b0 = bias[col], b1 = bias[col + 1];
            float o[4];
            o[0] = acc[mf][nf][0] + b0; o[1] = acc[mf][nf][1] + b1;
            o[2] = acc[mf][nf][2] + b0; o[3] = acc[mf][nf][3] + b1;
            if (is_val) {
                *(__nv_bfloat162*)(&valbf[(size_t)row * 256 + col]) =
                    __float22bfloat162_rn(make_float2(o[0], o[1]));
                *(__nv_bfloat162*)(&valbf[(size_t)(row + 8) * 256 + col]) =
                    __float22bfloat162_rn(make_float2(o[2], o[3]));
            } else {
                *(float2*)(&offattn[(size_t)row * Nc + col]) = make_float2(o[0], o[1]);
                *(float2*)(&offattn[(size_t)(row + 8) * Nc + col]) = make_float2(o[2], o[3]);
            }
        }
    }
}

// ---------------------------------------------------------------------------
// Deformable sampling, plan+gather per warp-token (R10 layout, conflict-free).
// ---------------------------------------------------------------------------
__global__ void __launch_bounds__(256)
sample_kernel(const __nv_bfloat16* __restrict__ valbf,
              const float* __restrict__ offattn,
              const float* __restrict__ ref,
              __nv_bfloat16* __restrict__ sampb)
{
    __shared__ float  sh[8][384];
    __shared__ float4 cws[8][8][17];
    __shared__ int4   ofs[8][8][17];

    const int w = threadIdx.x >> 5;
    const int t = blockIdx.x * 8 + w;
    const int lane = threadIdx.x & 31;
    const int n = t / LQ;

    // Phase 1: stage offattn row (1536B, coalesced).
    {
        const float4* rowp4 = (const float4*)(offattn + (size_t)t * 384);
        float4* sh4 = (float4*)sh[w];
#pragma unroll
        for (int i = 0; i < 3; i++) sh4[i * 32 + lane] = rowp4[i * 32 + lane];
    }
    __syncwarp();

    // Phase 2: plan. lane -> (hh = lane>>2, l = lane&3), 4 points of level l.
    {
        const int hh = lane >> 2;
        const int l  = lane & 3;
        const int Hs_[4] = {64, 32, 16, 8};
        const int St_[4] = {0, 4096, 5120, 5376};
        const float* lp = sh[w] + 256 + hh * 16;

        float myl[4];
#pragma unroll
        for (int k = 0; k < 4; k++) myl[k] = lp[l * 4 + k];
        float mx = fmaxf(fmaxf(myl[0], myl[1]), fmaxf(myl[2], myl[3]));
        mx = fmaxf(mx, __shfl_xor_sync(0xffffffffu, mx, 1));
        mx = fmaxf(mx, __shfl_xor_sync(0xffffffffu, mx, 2));
        float e[4], s = 0.f;
#pragma unroll
        for (int k = 0; k < 4; k++) { e[k] = expf(myl[k] - mx); s += e[k]; }
        s += __shfl_xor_sync(0xffffffffu, s, 1);
        s += __shfl_xor_sync(0xffffffffu, s, 2);
        const float inv = 1.f / s;

        const int HW = Hs_[l];
        const float fHW = (float)HW;
        const float invHW = 1.f / fHW;
        const float refx = ref[((size_t)t * NLVL + l) * 2 + 0];
        const float refy = ref[((size_t)t * NLVL + l) * 2 + 1];
        const float* op = sh[w] + hh * 32 + l * 8;
        const int ebase = (n * LQ + St_[l]) * DIM + hh * HD;

#pragma unroll
        for (int k = 0; k < 4; k++) {
            float ox = op[k * 2 + 0];
            float oy = op[k * 2 + 1];
            float xf = (refx + ox * invHW) * fHW - 0.5f;
            float yf = (refy + oy * invHW) * fHW - 0.5f;
            float x0f = floorf(xf), y0f = floorf(yf);
            int x0 = (int)x0f, y0 = (int)y0f;
            float wx1 = xf - x0f, wy1 = yf - y0f;
            float wx0 = 1.f - wx1, wy0 = 1.f - wy1;
            float wgt = e[k] * inv;

            bool xin0 = (x0 >= 0) & (x0 < HW);
            bool xin1 = (x0 + 1 >= 0) & (x0 + 1 < HW);
            bool yin0 = (y0 >= 0) & (y0 < HW);
            bool yin1 = (y0 + 1 >= 0) & (y0 + 1 < HW);

            float4 cw;
            cw.x = (yin0 && xin0) ? wgt * wy0 * wx0 : 0.f;
            cw.y = (yin0 && xin1) ? wgt * wy0 * wx1 : 0.f;
            cw.z = (yin1 && xin0) ? wgt * wy1 * wx0 : 0.f;
            cw.w = (yin1 && xin1) ? wgt * wy1 * wx1 : 0.f;
            int line = y0 * HW + x0;
            int4 off;
            off.x = (yin0 && xin0) ? (ebase + line * DIM) * 2 : 0;
            off.y = (yin0 && xin1) ? (ebase + (line + 1) * DIM) * 2 : 0;
            off.z = (yin1 && xin0) ? (ebase + (line + HW) * DIM) * 2 : 0;
            off.w = (yin1 && xin1) ? (ebase + (line + HW + 1) * DIM) * 2 : 0;
            cws[w][hh][l * 4 + k] = cw;
            ofs[w][hh][l * 4 + k] = off;
        }
    }
    __syncwarp();

    // Phase 3: gather. lane -> (h = lane>>2, d8 = lane&3).
    const int h = lane >> 2;
    const int d8 = lane & 3;
    const char* vbase = (const char*)valbf + d8 * 16;

    float acc[8];
#pragma unroll
    for (int i = 0; i < 8; i++) acc[i] = 0.f;

#pragma unroll 4
    for (int p = 0; p < 16; p++) {
        float4 cw = cws[w][h][p];
        int4 off = ofs[w][h][p];
        const int o4[4] = { off.x, off.y, off.z, off.w };
        const float c4[4] = { cw.x, cw.y, cw.z, cw.w };
#pragma unroll
        for (int cnr = 0; cnr < 4; cnr++) {
            uint4 u = *(const uint4*)(vbase + o4[cnr]);
            const __nv_bfloat162* q2 = (const __nv_bfloat162*)&u;
            float c = c4[cnr];
#pragma unroll
            for (int j = 0; j < 4; j++) {
                float2 f = __bfloat1622float2(q2[j]);
                acc[2 * j + 0] = fmaf(f.x, c, acc[2 * j + 0]);
                acc[2 * j + 1] = fmaf(f.y, c, acc[2 * j + 1]);
            }
        }
    }
    __nv_bfloat162 ob[4];
#pragma unroll
    for (int j = 0; j < 4; j++)
        ob[j] = __float22bfloat162_rn(make_float2(acc[2 * j], acc[2 * j + 1]));
    *(uint4*)(sampb + (size_t)t * DIM + h * HD + d8 * 8) = *(uint4*)ob;
}

// ---------------------------------------------------------------------------
// LayerNorm over 256 (vectorized): out = LN(a + b) * g + beta.
// One warp per token; lane owns 8 CONTIGUOUS elems (2xfloat4 + 1xuint4 bf16).
// ---------------------------------------------------------------------------
__global__ void ln_kernel(const float* __restrict__ a, const __nv_bfloat16* __restrict__ b,
                          const float* __restrict__ g, const float* __restrict__ beta,
                          float* __restrict__ out, __nv_bfloat16* __restrict__ out_b)
{
    const int t = blockIdx.x * 4 + (threadIdx.x >> 5);
    const int lane = threadIdx.x & 31;
    const int c0 = lane * 8;
    const float4* pa = (const float4*)(a + (size_t)t * DIM + c0);
    const uint4   ub = *(const uint4*)(b + (size_t)t * DIM + c0);

    float4 a0 = pa[0], a1 = pa[1];
    const __nv_bfloat162* b2 = (const __nv_bfloat162*)&ub;
    float v[8];
    {
        float2 f0 = __bfloat1622float2(b2[0]);
        float2 f1 = __bfloat1622float2(b2[1]);
        float2 f2 = __bfloat1622float2(b2[2]);
        float2 f3 = __bfloat1622float2(b2[3]);
        v[0] = a0.x + f0.x; v[1] = a0.y + f0.y;
        v[2] = a0.z + f1.x; v[3] = a0.w + f1.y;
        v[4] = a1.x + f2.x; v[5] = a1.y + f2.y;
        v[6] = a1.z + f3.x; v[7] = a1.w + f3.y;
    }
    float s = 0.f;
#pragma unroll
    for (int i = 0; i < 8; i++) s += v[i];
#pragma unroll
    for (int o = 16; o; o >>= 1) s += __shfl_xor_sync(0xffffffffu, s, o);
    const float mean = s * (1.f / 256.f);
    float var = 0.f;
#pragma unroll
    for (int i = 0; i < 8; i++) { float dd = v[i] - mean; var += dd * dd; }
#pragma unroll
    for (int o = 16; o; o >>= 1) var += __shfl_xor_sync(0xffffffffu, var, o);
    const float rstd = rsqrtf(var * (1.f / 256.f) + 1e-5f);

    const float4* pg = (const float4*)(g + c0);
    const float4* pe = (const float4*)(beta + c0);
    float4 g0 = pg[0], g1 = pg[1], e0 = pe[0], e1 = pe[1];
    float y[8];
    y[0] = (v[0] - mean) * rstd * g0.x + e0.x;
    y[1] = (v[1] - mean) * rstd * g0.y + e0.y;
    y[2] = (v[2] - mean) * rstd * g0.z + e0.z;
    y[3] = (v[3] - mean) * rstd * g0.w + e0.w;
    y[4] = (v[4] - mean) * rstd * g1.x + e1.x;
    y[5] = (v[5] - mean) * rstd * g1.y + e1.y;
    y[6] = (v[6] - mean) * rstd * g1.z + e1.z;
    y[7] = (v[7] - mean) * rstd * g1.w + e1.w;

    float4* po = (float4*)(out + (size_t)t * DIM + c0);
    po[0] = make_float4(y[0], y[1], y[2], y[3]);
    po[1] = make_float4(y[4], y[5], y[6], y[7]);
    if (out_b) {
        __nv_bfloat162 ob[4];
        ob[0] = __float22bfloat162_rn(make_float2(y[0], y[1]));
        ob[1] = __float22bfloat162_rn(make_float2(y[2], y[3]));
        ob[2] = __float22bfloat162_rn(make_float2(y[4], y[5]));
        ob[3] = __float22bfloat162_rn(make_float2(y[6], y[7]));
        *(uint4*)(out_b + (size_t)t * DIM + c0) = *(uint4*)ob;
    }
}

// ---------------------------------------------------------------------------
extern "C" void kernel_launch(void* const* d_in, const int* in_sizes, int n_in,
                              void* d_out, int out_size)
{
    const float* src  = (const float*)d_in[0];
    const float* pos  = (const float*)d_in[1];
    const float* refp = (const float*)d_in[2];
    const float* Wv   = (const float*)d_in[4];
    const float* bv   = (const float*)d_in[5];
    const float* Wo   = (const float*)d_in[6];
    const float* bo   = (const float*)d_in[7];
    const float* Wa   = (const float*)d_in[8];
    const float* ba   = (const float*)d_in[9];
    const float* Wout = (const float*)d_in[10];
    const float* bout = (const float*)d_in[11];
    const float* g1   = (const float*)d_in[12];
    const float* be1  = (const float*)d_in[13];
    const float* W1   = (const float*)d_in[14];
    const float* b1   = (const float*)d_in[15];
    const float* W2   = (const float*)d_in[16];
    const float* b2   = (const float*)d_in[17];
    const float* g2   = (const float*)d_in[18];
    const float* be2  = (const float*)d_in[19];
    float* out = (float*)d_out;

    __nv_bfloat16 *psrcb, *pqb, *pvb, *psampb, *psrc2b, *pxb, *phidb, *pffnb;
    __nv_bfloat16 *wtv, *wtoa, *wtout, *wt1, *wt2;
    float *poa, *px, *pboa;
    cudaGetSymbolAddress((void**)&psrcb, g_srcb);
    cudaGetSymbolAddress((void**)&pqb,   g_qb);
    cudaGetSymbolAddress((void**)&pvb,   g_valbf);
    cudaGetSymbolAddress((void**)&poa,   g_offattn);
    cudaGetSymbolAddress((void**)&psampb,g_sampb);
    cudaGetSymbolAddress((void**)&psrc2b,g_src2b);
    cudaGetSymbolAddress((void**)&px,    g_x);
    cudaGetSymbolAddress((void**)&pxb,   g_xb);
    cudaGetSymbolAddress((void**)&phidb, g_hidb);
    cudaGetSymbolAddress((void**)&pffnb, g_ffnb);
    cudaGetSymbolAddress((void**)&wtv,   g_wtv);
    cudaGetSymbolAddress((void**)&wtoa,  g_wtoa);
    cudaGetSymbolAddress((void**)&wtout, g_wtout);
    cudaGetSymbolAddress((void**)&wt1,   g_wt1);
    cudaGetSymbolAddress((void**)&wt2,   g_wt2);
    cudaGetSymbolAddress((void**)&pboa,  g_boa);

    const int DSM = 98304;  // 3 stages x (16KB A + 16KB B)
    cudaFuncSetAttribute(mma_gemm<0,1,256>,  cudaFuncAttributeMaxDynamicSharedMemorySize, DSM);
    cudaFuncSetAttribute(mma_gemm<1,1,256>,  cudaFuncAttributeMaxDynamicSharedMemorySize, DSM);
    cudaFuncSetAttribute(mma_gemm<0,1,1024>, cudaFuncAttributeMaxDynamicSharedMemorySize, DSM);
    cudaFuncSetAttribute(dual_gemm,          cudaFuncAttributeMaxDynamicSharedMemorySize, DSM);

    // One-shot prep
    prep_kernel<<<PREP_WBLK + PREP_ABLK + 1, 256>>>(
        Wv, Wo, Wa, Wout, W1, W2, bo, ba,
        (const float4*)src, (const float4*)pos,
        wtv, wtoa, wtout, wt1, wt2, pboa, psrcb, pqb);

    const int MT = TTOK / 128;  // 340 M-tiles

    // value (bf16) + offsets|logits (fp32) fused in ONE launch
    dual_gemm<<<MT * 5, 256, DSM>>>(psrcb, pqb, wtv, wtoa, bv, pboa, pvb, poa, MT);
    // deformable sampling (softmax fused; bf16 out)
    sample_kernel<<<TTOK / 8, 256>>>(pvb, poa, refp, psampb);
    // src2 (bf16) = samp @ Wout + bout
    mma_gemm<0,1,256><<<MT * 2, 256, DSM>>>(psampb, wtout, bout, nullptr, psrc2b, 256, MT);
    // x = LN1(src + src2)  (fp32 + bf16 copies)
    ln_kernel<<<TTOK / 4, 128>>>(src, psrc2b, g1, be1, px, pxb);
    // hid (bf16) = relu(x @ W1 + b1)
    mma_gemm<1,1,256><<<MT * 8, 256, DSM>>>(pxb, wt1, b1, nullptr, phidb, 1024, MT);
    // ffn (bf16) = hid @ W2 + b2
    mma_gemm<0,1,1024><<<MT * 2, 256, DSM>>>(phidb, wt2, b2, nullptr, pffnb, 256, MT);
    // out = LN2(x + ffn)
    ln_kernel<<<TTOK / 4, 128>>>(px, pffnb, g2, be2, out, nullptr);
}

// round 15
// speedup vs baseline: 1.2205x; 1.0049x over previous
#include <cuda_runtime.h>
#include <cuda_bf16.h>
#include <cstdint>
#include <math.h>

// Problem constants (static per reference)
#define NBATCH 8
#define LQ     5440
#define TTOK   (NBATCH*LQ)      // 43520
#define DIM    256
#define NHEAD  8
#define HD     32
#define NLVL   4
#define NPT    4
#define DFF    1024

// Scratch (device globals; no runtime allocation)
__device__ __nv_bfloat16 g_srcb [(size_t)TTOK*DIM];
__device__ __nv_bfloat16 g_qb   [(size_t)TTOK*DIM];
__device__ __nv_bfloat16 g_valbf[(size_t)TTOK*DIM];
__device__ __nv_bfloat16 g_offattnb[(size_t)TTOK*384];
__device__ __nv_bfloat16 g_sampb[(size_t)TTOK*DIM];
__device__ __nv_bfloat16 g_src2b[(size_t)TTOK*DIM];
__device__ float         g_x    [(size_t)TTOK*DIM];
__device__ __nv_bfloat16 g_xb   [(size_t)TTOK*DIM];
__device__ __nv_bfloat16 g_hidb [(size_t)TTOK*DFF];
__device__ __nv_bfloat16 g_ffnb [(size_t)TTOK*DIM];
// Transposed ([N][K]) bf16 weights
__device__ __nv_bfloat16 g_wtv  [256*256];
__device__ __nv_bfloat16 g_wtoa [384*256];
__device__ __nv_bfloat16 g_wtout[256*256];
__device__ __nv_bfloat16 g_wt1  [1024*256];
__device__ __nv_bfloat16 g_wt2  [256*1024];
__device__ float         g_boa  [384];

// ---------------------------------------------------------------------------
// Helpers
// ---------------------------------------------------------------------------
__device__ __forceinline__ uint32_t smem_u32(const void* p) {
    uint32_t a;
    asm("{ .reg .u64 t; cvta.to.shared.u64 t, %1; cvt.u32.u64 %0, t; }" : "=r"(a) : "l"(p));
    return a;
}
__device__ __forceinline__ void cpasync16(uint32_t dst, const void* src) {
    asm volatile("cp.async.cg.shared.global [%0], [%1], 16;" :: "r"(dst), "l"(src));
}
#define CP_COMMIT() asm volatile("cp.async.commit_group;" ::: "memory")
#define CP_WAIT1()  asm volatile("cp.async.wait_group 1;" ::: "memory")

__device__ __forceinline__ void ldmx4(uint32_t& f0, uint32_t& f1, uint32_t& f2, uint32_t& f3,
                                      uint32_t addr) {
    asm volatile("ldmatrix.sync.aligned.m8n8.x4.shared.b16 {%0,%1,%2,%3}, [%4];"
                 : "=r"(f0), "=r"(f1), "=r"(f2), "=r"(f3) : "r"(addr));
}
__device__ __forceinline__ void mma_bf16(float* c, uint32_t a0, uint32_t a1,
                                         uint32_t a2, uint32_t a3,
                                         uint32_t b0, uint32_t b1) {
    asm volatile(
        "mma.sync.aligned.m16n8k16.row.col.f32.bf16.bf16.f32 "
        "{%0,%1,%2,%3}, {%4,%5,%6,%7}, {%8,%9}, {%0,%1,%2,%3};"
        : "+f"(c[0]), "+f"(c[1]), "+f"(c[2]), "+f"(c[3])
        : "r"(a0), "r"(a1), "r"(a2), "r"(a3), "r"(b0), "r"(b1));
}

// ---------------------------------------------------------------------------
// One-shot prep: weight transposes (fp32 [K][N] -> bf16 [N][K]), bias concat,
// src/q bf16 conversion. Single launch.
// ---------------------------------------------------------------------------
#define PREP_WBLK 2944
#define PREP_ABLK 10880
__global__ void prep_kernel(const float* __restrict__ Wv, const float* __restrict__ Wo,
                            const float* __restrict__ Wa, const float* __restrict__ Wout,
                            const float* __restrict__ W1, const float* __restrict__ W2,
                            const float* __restrict__ bo, const float* __restrict__ ba,
                            const float4* __restrict__ src, const float4* __restrict__ pos,
                            __nv_bfloat16* __restrict__ wtv, __nv_bfloat16* __restrict__ wtoa,
                            __nv_bfloat16* __restrict__ wtout, __nv_bfloat16* __restrict__ wt1,
                            __nv_bfloat16* __restrict__ wt2, float* __restrict__ boa,
                            __nv_bfloat16* __restrict__ srcb, __nv_bfloat16* __restrict__ qb)
{
    int b = blockIdx.x;
    if (b < PREP_WBLK) {
        int idx = b * 256 + threadIdx.x;  // 0..753663
        float v; __nv_bfloat16* dst;
        if (idx < 65536) {                       // Wv [256,256]
            int n = idx >> 8, k = idx & 255; v = Wv[k * 256 + n]; dst = wtv + idx;
        } else if (idx < 163840) {               // Woa [384,256] = [Wo|Wa]
            int j = idx - 65536; int n = j >> 8, k = j & 255;
            v = (n < 256) ? Wo[k * 256 + n] : Wa[k * 128 + (n - 256)]; dst = wtoa + j;
        } else if (idx < 229376) {               // Wout [256,256]
            int j = idx - 163840; int n = j >> 8, k = j & 255; v = Wout[k * 256 + n]; dst = wtout + j;
        } else if (idx < 491520) {               // W1 [1024,256]
            int j = idx - 229376; int n = j >> 8, k = j & 255; v = W1[k * 1024 + n]; dst = wt1 + j;
        } else {                                 // W2 [256,1024]
            int j = idx - 491520; int n = j >> 10, k = j & 1023; v = W2[k * 256 + n]; dst = wt2 + j;
        }
        *dst = __float2bfloat16(v);
    } else if (b < PREP_WBLK + PREP_ABLK) {
        int idx = (b - PREP_WBLK) * 256 + threadIdx.x;   // float4 index
        float4 s = src[idx], p = pos[idx];
        __nv_bfloat162 s01 = __float22bfloat162_rn(make_float2(s.x, s.y));
        __nv_bfloat162 s23 = __float22bfloat162_rn(make_float2(s.z, s.w));
        __nv_bfloat162 q01 = __float22bfloat162_rn(make_float2(s.x + p.x, s.y + p.y));
        __nv_bfloat162 q23 = __float22bfloat162_rn(make_float2(s.z + p.z, s.w + p.w));
        ((uint2*)srcb)[idx] = make_uint2(*(uint32_t*)&s01, *(uint32_t*)&s23);
        ((uint2*)qb)[idx]   = make_uint2(*(uint32_t*)&q01, *(uint32_t*)&q23);
    } else {
        int i = threadIdx.x;
        if (i < 384) boa[i] = (i < 256) ? bo[i] : ba[i - 256];
    }
}

// ---------------------------------------------------------------------------
// Shared bf16 GEMM mainloop (128x128 tile, cp.async 3-stage + ldmatrix),
// compile-time K for full unroll; register-fragment double buffering.
// ---------------------------------------------------------------------------
#define BK 64

struct GemmCtx {
    int tid, wid, lane, g, tg, wm, wn, row0, col0;
    uint32_t sbase;
    int a_r, a_kh, b_r, b_kh;
};

__device__ __forceinline__ void load_frags(
    const GemmCtx& c, uint32_t Ab, uint32_t Bb, int ks,
    uint32_t af[4][4], uint32_t bf[4][2])
{
#pragma unroll
    for (int np = 0; np < 2; np++) {
        int r = c.wn * 32 + np * 16 + c.b_r;
        uint32_t addr = Bb + r * 128 + (((ks * 2 + c.b_kh) ^ (r & 7)) << 4);
        ldmx4(bf[np * 2][0], bf[np * 2][1], bf[np * 2 + 1][0], bf[np * 2 + 1][1], addr);
    }
#pragma unroll
    for (int mf = 0; mf < 4; mf++) {
        int r = c.wm * 64 + mf * 16 + c.a_r;
        uint32_t addr = Ab + r * 128 + (((ks * 2 + c.a_kh) ^ (r & 7)) << 4);
        ldmx4(af[mf][0], af[mf][1], af[mf][2], af[mf][3], addr);
    }
}

template<int K>
__device__ __forceinline__ void gemm_mainloop(
    GemmCtx& c, const __nv_bfloat16* __restrict__ A,
    const __nv_bfloat16* __restrict__ Wt, float acc[4][4][4])
{
#pragma unroll
    for (int i = 0; i < 4; i++)
#pragma unroll
        for (int j = 0; j < 4; j++)
#pragma unroll
            for (int k = 0; k < 4; k++) acc[i][j][k] = 0.f;

    auto load_chunk = [&](int k0, int st) {
#pragma unroll
        for (int i = 0; i < 4; i++) {
            int idx = c.tid + i * 256;
            int r = idx >> 3, gc = idx & 7;
            uint32_t so = (uint32_t)(r * 128 + ((gc ^ (r & 7)) << 4));
            cpasync16(c.sbase + st * 16384 + so, A + (size_t)(c.row0 + r) * K + k0 + gc * 8);
            cpasync16(c.sbase + 49152 + st * 16384 + so, Wt + (size_t)(c.col0 + r) * K + k0 + gc * 8);
        }
    };

    constexpr int nchunk = K / BK;
    load_chunk(0, 0);
    CP_COMMIT();
    if (nchunk > 1) load_chunk(BK, 1);
    CP_COMMIT();

    uint32_t af[2][4][4], bf[2][4][2];

#pragma unroll
    for (int ch = 0; ch < nchunk; ch++) {
        CP_WAIT1();
        __syncthreads();
        if (ch + 2 < nchunk) load_chunk((ch + 2) * BK, (ch + 2) % 3);
        CP_COMMIT();

        const uint32_t Ab = c.sbase + (ch % 3) * 16384;
        const uint32_t Bb = c.sbase + 49152 + (ch % 3) * 16384;

        load_frags(c, Ab, Bb, 0, af[0], bf[0]);
#pragma unroll
        for (int ks = 0; ks < 4; ks++) {
            const int cur = ks & 1, nx = cur ^ 1;
            if (ks < 3) load_frags(c, Ab, Bb, ks + 1, af[nx], bf[nx]);
#pragma unroll
            for (int mf = 0; mf < 4; mf++)
#pragma unroll
                for (int nf = 0; nf < 4; nf++)
                    mma_bf16(acc[mf][nf], af[cur][mf][0], af[cur][mf][1],
                             af[cur][mf][2], af[cur][mf][3],
                             bf[cur][nf][0], bf[cur][nf][1]);
        }
    }
}

__device__ __forceinline__ void gemm_init_ctx(GemmCtx& c, char* smem, int mt, int nt) {
    c.tid = threadIdx.x;
    c.wid = c.tid >> 5; c.lane = c.tid & 31;
    c.g = c.lane >> 2;  c.tg = c.lane & 3;
    c.wm = c.wid & 1;   c.wn = c.wid >> 1;
    c.row0 = mt * 128;  c.col0 = nt * 128;
    c.sbase = smem_u32(smem);
    c.a_r  = (c.lane & 7) + ((c.lane >> 3) & 1) * 8;
    c.a_kh = (c.lane >> 4) & 1;
    c.b_r  = (c.lane & 7) + ((c.lane >> 4) << 3);
    c.b_kh = (c.lane >> 3) & 1;
}

// ---------------------------------------------------------------------------
// Generic GEMM kernel (template epilogue + compile-time K).
// ---------------------------------------------------------------------------
template<int ACT, int OBF, int K>
__global__ void __launch_bounds__(256, 2)
mma_gemm(const __nv_bfloat16* __restrict__ A, const __nv_bfloat16* __restrict__ Wt,
         const float* __restrict__ bias, float* __restrict__ C,
         __nv_bfloat16* __restrict__ C16, int Nc, int mtiles)
{
    extern __shared__ char smem[];
    GemmCtx c;
    gemm_init_ctx(c, smem, blockIdx.x % mtiles, blockIdx.x / mtiles);
    float acc[4][4][4];
    gemm_mainloop<K>(c, A, Wt, acc);

#pragma unroll
    for (int mf = 0; mf < 4; mf++) {
#pragma unroll
        for (int nf = 0; nf < 4; nf++) {
            int row = c.row0 + c.wm * 64 + mf * 16 + c.g;
            int col = c.col0 + c.wn * 32 + nf * 8 + c.tg * 2;
            float b0 = bias[col], b1 = bias[col + 1];
            float o[4];
            o[0] = acc[mf][nf][0] + b0; o[1] = acc[mf][nf][1] + b1;
            o[2] = acc[mf][nf][2] + b0; o[3] = acc[mf][nf][3] + b1;
            if (ACT) {
#pragma unroll
                for (int i = 0; i < 4; i++) o[i] = fmaxf(o[i], 0.f);
            }
            if (OBF) {
                *(__nv_bfloat162*)(&C16[(size_t)row * Nc + col]) =
                    __float22bfloat162_rn(make_float2(o[0], o[1]));
                *(__nv_bfloat162*)(&C16[(size_t)(row + 8) * Nc + col]) =
                    __float22bfloat162_rn(make_float2(o[2], o[3]));
            } else {
                *(float2*)(&C[(size_t)row * Nc + col]) = make_float2(o[0], o[1]);
                *(float2*)(&C[(size_t)(row + 8) * Nc + col]) = make_float2(o[2], o[3]);
            }
        }
    }
}

// ---------------------------------------------------------------------------
// Dual GEMM: value + offsets|logits, both bf16 out, in ONE launch. K=256.
// ---------------------------------------------------------------------------
__global__ void __launch_bounds__(256, 2)
dual_gemm(const __nv_bfloat16* __restrict__ srcb, const __nv_bfloat16* __restrict__ qb,
          const __nv_bfloat16* __restrict__ wtv, const __nv_bfloat16* __restrict__ wtoa,
          const float* __restrict__ bv, const float* __restrict__ boa,
          __nv_bfloat16* __restrict__ valbf, __nv_bfloat16* __restrict__ offattnb, int mtiles)
{
    extern __shared__ char smem[];
    const int bid = blockIdx.x;
    const bool is_val = bid < mtiles * 2;
    const int local = is_val ? bid : bid - mtiles * 2;
    const int mt = local % mtiles, nt = local / mtiles;

    const __nv_bfloat16* A  = is_val ? srcb : qb;
    const __nv_bfloat16* Wt = is_val ? wtv : wtoa;
    const float* bias = is_val ? bv : boa;
    const int Nc = is_val ? 256 : 384;
    __nv_bfloat16* O = is_val ? valbf : offattnb;

    GemmCtx c;
    gemm_init_ctx(c, smem, mt, nt);
    float acc[4][4][4];
    gemm_mainloop<256>(c, A, Wt, acc);

#pragma unroll
    for (int mf = 0; mf < 4; mf++) {
#pragma unroll
        for (int nf = 0; nf < 4; nf++) {
            int row = c.row0 + c.wm * 64 + mf * 16 + c.g;
            int col = c.col0 + c.wn * 32 + nf * 8 + c.tg * 2;
            float b0 = bias[col], b1 = bias[col + 1];
            float o[4];
            o[0] = acc[mf][nf][0] + b0; o[1] = acc[mf][nf][1] + b1;
            o[2] = acc[mf][nf][2] + b0; o[3] = acc[mf][nf][3] + b1;
            *(__nv_bfloat162*)(&O[(size_t)row * Nc + col]) =
                __float22bfloat162_rn(make_float2(o[0], o[1]));
            *(__nv_bfloat162*)(&O[(size_t)(row + 8) * Nc + col]) =
                __float22bfloat162_rn(make_float2(o[2], o[3]));
        }
    }
}

// ---------------------------------------------------------------------------
// Deformable sampling, plan+gather per warp-token (R10 layout, conflict-free).
// offattn now bf16 (768B/token staged, converted to fp32 smem row).
// ---------------------------------------------------------------------------
__global__ void __launch_bounds__(256)
sample_kernel(const __nv_bfloat16* __restrict__ valbf,
              const __nv_bfloat16* __restrict__ offattnb,
              const float* __restrict__ ref,
              __nv_bfloat16* __restrict__ sampb)
{
    __shared__ float  sh[8][384];
    __shared__ float4 cws[8][8][17];
    __shared__ int4   ofs[8][8][17];

    const int w = threadIdx.x >> 5;
    const int t = blockIdx.x * 8 + w;
    const int lane = threadIdx.x & 31;
    const int n = t / LQ;

    // Phase 1: stage offattn row (768B bf16, coalesced) -> fp32 smem.
    {
        const uint4* rowp4 = (const uint4*)(offattnb + (size_t)t * 384);  // 48 x uint4
#pragma unroll
        for (int i = 0; i < 2; i++) {
            int idx = lane + i * 32;
            if (idx < 48) {
                uint4 u = rowp4[idx];
                const __nv_bfloat162* q2 = (const __nv_bfloat162*)&u;
                float* dst = sh[w] + idx * 8;
#pragma unroll
                for (int j = 0; j < 4; j++) {
                    float2 f = __bfloat1622float2(q2[j]);
                    dst[2 * j] = f.x; dst[2 * j + 1] = f.y;
                }
            }
        }
    }
    __syncwarp();

    // Phase 2: plan. lane -> (hh = lane>>2, l = lane&3), 4 points of level l.
    {
        const int hh = lane >> 2;
        const int l  = lane & 3;
        const int Hs_[4] = {64, 32, 16, 8};
        const int St_[4] = {0, 4096, 5120, 5376};
        const float* lp = sh[w] + 256 + hh * 16;

        float myl[4];
#pragma unroll
        for (int k = 0; k < 4; k++) myl[k] = lp[l * 4 + k];
        float mx = fmaxf(fmaxf(myl[0], myl[1]), fmaxf(myl[2], myl[3]));
        mx = fmaxf(mx, __shfl_xor_sync(0xffffffffu, mx, 1));
        mx = fmaxf(mx, __shfl_xor_sync(0xffffffffu, mx, 2));
        float e[4], s = 0.f;
#pragma unroll
        for (int k = 0; k < 4; k++) { e[k] = __expf(myl[k] - mx); s += e[k]; }
        s += __shfl_xor_sync(0xffffffffu, s, 1);
        s += __shfl_xor_sync(0xffffffffu, s, 2);
        const float inv = 1.f / s;

        const int HW = Hs_[l];
        const float fHW = (float)HW;
        const float invHW = 1.f / fHW;
        const float refx = ref[((size_t)t * NLVL + l) * 2 + 0];
        const float refy = ref[((size_t)t * NLVL + l) * 2 + 1];
        const float* op = sh[w] + hh * 32 + l * 8;
        const int ebase = (n * LQ + St_[l]) * DIM + hh * HD;

#pragma unroll
        for (int k = 0; k < 4; k++) {
            float ox = op[k * 2 + 0];
            float oy = op[k * 2 + 1];
            float xf = (refx + ox * invHW) * fHW - 0.5f;
            float yf = (refy + oy * invHW) * fHW - 0.5f;
            float x0f = floorf(xf), y0f = floorf(yf);
            int x0 = (int)x0f, y0 = (int)y0f;
            float wx1 = xf - x0f, wy1 = yf - y0f;
            float wx0 = 1.f - wx1, wy0 = 1.f - wy1;
            float wgt = e[k] * inv;

            bool xin0 = (x0 >= 0) & (x0 < HW);
            bool xin1 = (x0 + 1 >= 0) & (x0 + 1 < HW);
            bool yin0 = (y0 >= 0) & (y0 < HW);
            bool yin1 = (y0 + 1 >= 0) & (y0 + 1 < HW);

            float4 cw;
            cw.x = (yin0 && xin0) ? wgt * wy0 * wx0 : 0.f;
            cw.y = (yin0 && xin1) ? wgt * wy0 * wx1 : 0.f;
            cw.z = (yin1 && xin0) ? wgt * wy1 * wx0 : 0.f;
            cw.w = (yin1 && xin1) ? wgt * wy1 * wx1 : 0.f;
            int line = y0 * HW + x0;
            int4 off;
            off.x = (yin0 && xin0) ? (ebase + line * DIM) * 2 : 0;
            off.y = (yin0 && xin1) ? (ebase + (line + 1) * DIM) * 2 : 0;
            off.z = (yin1 && xin0) ? (ebase + (line + HW) * DIM) * 2 : 0;
            off.w = (yin1 && xin1) ? (ebase + (line + HW + 1) * DIM) * 2 : 0;
            cws[w][hh][l * 4 + k] = cw;
            ofs[w][hh][l * 4 + k] = off;
        }
    }
    __syncwarp();

    // Phase 3: gather. lane -> (h = lane>>2, d8 = lane&3).
    const int h = lane >> 2;
    const int d8 = lane & 3;
    const char* vbase = (const char*)valbf + d8 * 16;

    float acc[8];
#pragma unroll
    for (int i = 0; i < 8; i++) acc[i] = 0.f;

#pragma unroll 4
    for (int p = 0; p < 16; p++) {
        float4 cw = cws[w][h][p];
        int4 off = ofs[w][h][p];
        const int o4[4] = { off.x, off.y, off.z, off.w };
        const float c4[4] = { cw.x, cw.y, cw.z, cw.w };
#pragma unroll
        for (int cnr = 0; cnr < 4; cnr++) {
            uint4 u = *(const uint4*)(vbase + o4[cnr]);
            const __nv_bfloat162* q2 = (const __nv_bfloat162*)&u;
            float c = c4[cnr];
#pragma unroll
            for (int j = 0; j < 4; j++) {
                float2 f = __bfloat1622float2(q2[j]);
                acc[2 * j + 0] = fmaf(f.x, c, acc[2 * j + 0]);
                acc[2 * j + 1] = fmaf(f.y, c, acc[2 * j + 1]);
            }
        }
    }
    __nv_bfloat162 ob[4];
#pragma unroll
    for (int j = 0; j < 4; j++)
        ob[j] = __float22bfloat162_rn(make_float2(acc[2 * j], acc[2 * j + 1]));
    *(uint4*)(sampb + (size_t)t * DIM + h * HD + d8 * 8) = *(uint4*)ob;
}

// ---------------------------------------------------------------------------
// LayerNorm over 256 (vectorized): out = LN(a + b) * g + beta.
// One warp per token; 8 tokens per 256-thread block.
// ---------------------------------------------------------------------------
__global__ void __launch_bounds__(256)
ln_kernel(const float* __restrict__ a, const __nv_bfloat16* __restrict__ b,
          const float* __restrict__ g, const float* __restrict__ beta,
          float* __restrict__ out, __nv_bfloat16* __restrict__ out_b)
{
    const int t = blockIdx.x * 8 + (threadIdx.x >> 5);
    const int lane = threadIdx.x & 31;
    const int c0 = lane * 8;
    const float4* pa = (const float4*)(a + (size_t)t * DIM + c0);
    const uint4   ub = *(const uint4*)(b + (size_t)t * DIM + c0);

    float4 a0 = pa[0], a1 = pa[1];
    const __nv_bfloat162* b2 = (const __nv_bfloat162*)&ub;
    float v[8];
    {
        float2 f0 = __bfloat1622float2(b2[0]);
        float2 f1 = __bfloat1622float2(b2[1]);
        float2 f2 = __bfloat1622float2(b2[2]);
        float2 f3 = __bfloat1622float2(b2[3]);
        v[0] = a0.x + f0.x; v[1] = a0.y + f0.y;
        v[2] = a0.z + f1.x; v[3] = a0.w + f1.y;
        v[4] = a1.x + f2.x; v[5] = a1.y + f2.y;
        v[6] = a1.z + f3.x; v[7] = a1.w + f3.y;
    }
    float s = 0.f;
#pragma unroll
    for (int i = 0; i < 8; i++) s += v[i];
#pragma unroll
    for (int o = 16; o; o >>= 1) s += __shfl_xor_sync(0xffffffffu, s, o);
    const float mean = s * (1.f / 256.f);
    float var = 0.f;
#pragma unroll
    for (int i = 0; i < 8; i++) { float dd = v[i] - mean; var += dd * dd; }
#pragma unroll
    for (int o = 16; o; o >>= 1) var += __shfl_xor_sync(0xffffffffu, var, o);
    const float rstd = rsqrtf(var * (1.f / 256.f) + 1e-5f);

    const float4* pg = (const float4*)(g + c0);
    const float4* pe = (const float4*)(beta + c0);
    float4 g0 = pg[0], g1 = pg[1], e0 = pe[0], e1 = pe[1];
    float y[8];
    y[0] = (v[0] - mean) * rstd * g0.x + e0.x;
    y[1] = (v[1] - mean) * rstd * g0.y + e0.y;
    y[2] = (v[2] - mean) * rstd * g0.z + e0.z;
    y[3] = (v[3] - mean) * rstd * g0.w + e0.w;
    y[4] = (v[4] - mean) * rstd * g1.x + e1.x;
    y[5] = (v[5] - mean) * rstd * g1.y + e1.y;
    y[6] = (v[6] - mean) * rstd * g1.z + e1.z;
    y[7] = (v[7] - mean) * rstd * g1.w + e1.w;

    float4* po = (float4*)(out + (size_t)t * DIM + c0);
    po[0] = make_float4(y[0], y[1], y[2], y[3]);
    po[1] = make_float4(y[4], y[5], y[6], y[7]);
    if (out_b) {
        __nv_bfloat162 ob[4];
        ob[0] = __float22bfloat162_rn(make_float2(y[0], y[1]));
        ob[1] = __float22bfloat162_rn(make_float2(y[2], y[3]));
        ob[2] = __float22bfloat162_rn(make_float2(y[4], y[5]));
        ob[3] = __float22bfloat162_rn(make_float2(y[6], y[7]));
        *(uint4*)(out_b + (size_t)t * DIM + c0) = *(uint4*)ob;
    }
}

// ---------------------------------------------------------------------------
extern "C" void kernel_launch(void* const* d_in, const int* in_sizes, int n_in,
                              void* d_out, int out_size)
{
    const float* src  = (const float*)d_in[0];
    const float* pos  = (const float*)d_in[1];
    const float* refp = (const float*)d_in[2];
    const float* Wv   = (const float*)d_in[4];
    const float* bv   = (const float*)d_in[5];
    const float* Wo   = (const float*)d_in[6];
    const float* bo   = (const float*)d_in[7];
    const float* Wa   = (const float*)d_in[8];
    const float* ba   = (const float*)d_in[9];
    const float* Wout = (const float*)d_in[10];
    const float* bout = (const float*)d_in[11];
    const float* g1   = (const float*)d_in[12];
    const float* be1  = (const float*)d_in[13];
    const float* W1   = (const float*)d_in[14];
    const float* b1   = (const float*)d_in[15];
    const float* W2   = (const float*)d_in[16];
    const float* b2   = (const float*)d_in[17];
    const float* g2   = (const float*)d_in[18];
    const float* be2  = (const float*)d_in[19];
    float* out = (float*)d_out;

    __nv_bfloat16 *psrcb, *pqb, *pvb, *poab, *psampb, *psrc2b, *pxb, *phidb, *pffnb;
    __nv_bfloat16 *wtv, *wtoa, *wtout, *wt1, *wt2;
    float *px, *pboa;
    cudaGetSymbolAddress((void**)&psrcb, g_srcb);
    cudaGetSymbolAddress((void**)&pqb,   g_qb);
    cudaGetSymbolAddress((void**)&pvb,   g_valbf);
    cudaGetSymbolAddress((void**)&poab,  g_offattnb);
    cudaGetSymbolAddress((void**)&psampb,g_sampb);
    cudaGetSymbolAddress((void**)&psrc2b,g_src2b);
    cudaGetSymbolAddress((void**)&px,    g_x);
    cudaGetSymbolAddress((void**)&pxb,   g_xb);
    cudaGetSymbolAddress((void**)&phidb, g_hidb);
    cudaGetSymbolAddress((void**)&pffnb, g_ffnb);
    cudaGetSymbolAddress((void**)&wtv,   g_wtv);
    cudaGetSymbolAddress((void**)&wtoa,  g_wtoa);
    cudaGetSymbolAddress((void**)&wtout, g_wtout);
    cudaGetSymbolAddress((void**)&wt1,   g_wt1);
    cudaGetSymbolAddress((void**)&wt2,   g_wt2);
    cudaGetSymbolAddress((void**)&pboa,  g_boa);

    const int DSM = 98304;  // 3 stages x (16KB A + 16KB B)
    cudaFuncSetAttribute(mma_gemm<0,1,256>,  cudaFuncAttributeMaxDynamicSharedMemorySize, DSM);
    cudaFuncSetAttribute(mma_gemm<1,1,256>,  cudaFuncAttributeMaxDynamicSharedMemorySize, DSM);
    cudaFuncSetAttribute(mma_gemm<0,1,1024>, cudaFuncAttributeMaxDynamicSharedMemorySize, DSM);
    cudaFuncSetAttribute(dual_gemm,          cudaFuncAttributeMaxDynamicSharedMemorySize, DSM);

    // One-shot prep
    prep_kernel<<<PREP_WBLK + PREP_ABLK + 1, 256>>>(
        Wv, Wo, Wa, Wout, W1, W2, bo, ba,
        (const float4*)src, (const float4*)pos,
        wtv, wtoa, wtout, wt1, wt2, pboa, psrcb, pqb);

    const int MT = TTOK / 128;  // 340 M-tiles

    // value (bf16) + offsets|logits (bf16) fused in ONE launch
    dual_gemm<<<MT * 5, 256, DSM>>>(psrcb, pqb, wtv, wtoa, bv, pboa, pvb, poab, MT);
    // deformable sampling (softmax fused; bf16 out)
    sample_kernel<<<TTOK / 8, 256>>>(pvb, poab, refp, psampb);
    // src2 (bf16) = samp @ Wout + bout
    mma_gemm<0,1,256><<<MT * 2, 256, DSM>>>(psampb, wtout, bout, nullptr, psrc2b, 256, MT);
    // x = LN1(src + src2)  (fp32 + bf16 copies)
    ln_kernel<<<TTOK / 8, 256>>>(src, psrc2b, g1, be1, px, pxb);
    // hid (bf16) = relu(x @ W1 + b1)
    mma_gemm<1,1,256><<<MT * 8, 256, DSM>>>(pxb, wt1, b1, nullptr, phidb, 1024, MT);
    // ffn (bf16) = hid @ W2 + b2
    mma_gemm<0,1,1024><<<MT * 2, 256, DSM>>>(phidb, wt2, b2, nullptr, pffnb, 256, MT);
    // out = LN2(x + ffn)
    ln_kernel<<<TTOK / 8, 256>>>(px, pffnb, g2, be2, out, nullptr);
}

// round 16
// speedup vs baseline: 1.2520x; 1.0258x over previous
#include <cuda_runtime.h>
#include <cuda_bf16.h>
#include <cstdint>
#include <math.h>

// Problem constants (static per reference)
#define NBATCH 8
#define LQ     5440
#define TTOK   (NBATCH*LQ)      // 43520
#define DIM    256
#define NHEAD  8
#define HD     32
#define NLVL   4
#define NPT    4
#define DFF    1024

// Scratch (device globals; no runtime allocation)
__device__ __nv_bfloat16 g_srcb [(size_t)TTOK*DIM];
__device__ __nv_bfloat16 g_qb   [(size_t)TTOK*DIM];
__device__ __nv_bfloat16 g_valbf[(size_t)TTOK*DIM];
__device__ __nv_bfloat16 g_offattnb[(size_t)TTOK*384];
__device__ __nv_bfloat16 g_sampb[(size_t)TTOK*DIM];
__device__ __nv_bfloat16 g_src2b[(size_t)TTOK*DIM];
__device__ float         g_x    [(size_t)TTOK*DIM];
__device__ __nv_bfloat16 g_xb   [(size_t)TTOK*DIM];
__device__ __nv_bfloat16 g_hidb [(size_t)TTOK*DFF];
__device__ __nv_bfloat16 g_ffnb [(size_t)TTOK*DIM];
// Transposed ([N][K]) bf16 weights
__device__ __nv_bfloat16 g_wtv  [256*256];
__device__ __nv_bfloat16 g_wtoa [384*256];
__device__ __nv_bfloat16 g_wtout[256*256];
__device__ __nv_bfloat16 g_wt1  [1024*256];
__device__ __nv_bfloat16 g_wt2  [256*1024];
__device__ float         g_boa  [384];

// ---------------------------------------------------------------------------
// Helpers
// ---------------------------------------------------------------------------
__device__ __forceinline__ uint32_t smem_u32(const void* p) {
    uint32_t a;
    asm("{ .reg .u64 t; cvta.to.shared.u64 t, %1; cvt.u32.u64 %0, t; }" : "=r"(a) : "l"(p));
    return a;
}
__device__ __forceinline__ void cpasync16(uint32_t dst, const void* src) {
    asm volatile("cp.async.cg.shared.global [%0], [%1], 16;" :: "r"(dst), "l"(src));
}
#define CP_COMMIT() asm volatile("cp.async.commit_group;" ::: "memory")
#define CP_WAIT1()  asm volatile("cp.async.wait_group 1;" ::: "memory")

__device__ __forceinline__ void ldmx4(uint32_t& f0, uint32_t& f1, uint32_t& f2, uint32_t& f3,
                                      uint32_t addr) {
    asm volatile("ldmatrix.sync.aligned.m8n8.x4.shared.b16 {%0,%1,%2,%3}, [%4];"
                 : "=r"(f0), "=r"(f1), "=r"(f2), "=r"(f3) : "r"(addr));
}
__device__ __forceinline__ void mma_bf16(float* c, uint32_t a0, uint32_t a1,
                                         uint32_t a2, uint32_t a3,
                                         uint32_t b0, uint32_t b1) {
    asm volatile(
        "mma.sync.aligned.m16n8k16.row.col.f32.bf16.bf16.f32 "
        "{%0,%1,%2,%3}, {%4,%5,%6,%7}, {%8,%9}, {%0,%1,%2,%3};"
        : "+f"(c[0]), "+f"(c[1]), "+f"(c[2]), "+f"(c[3])
        : "r"(a0), "r"(a1), "r"(a2), "r"(a3), "r"(b0), "r"(b1));
}

// ---------------------------------------------------------------------------
// One-shot prep: weight transposes (fp32 [K][N] -> bf16 [N][K]), bias concat,
// src/q bf16 conversion. Single launch.
// ---------------------------------------------------------------------------
#define PREP_WBLK 2944
#define PREP_ABLK 10880
__global__ void prep_kernel(const float* __restrict__ Wv, const float* __restrict__ Wo,
                            const float* __restrict__ Wa, const float* __restrict__ Wout,
                            const float* __restrict__ W1, const float* __restrict__ W2,
                            const float* __restrict__ bo, const float* __restrict__ ba,
                            const float4* __restrict__ src, const float4* __restrict__ pos,
                            __nv_bfloat16* __restrict__ wtv, __nv_bfloat16* __restrict__ wtoa,
                            __nv_bfloat16* __restrict__ wtout, __nv_bfloat16* __restrict__ wt1,
                            __nv_bfloat16* __restrict__ wt2, float* __restrict__ boa,
                            __nv_bfloat16* __restrict__ srcb, __nv_bfloat16* __restrict__ qb)
{
    int b = blockIdx.x;
    if (b < PREP_WBLK) {
        int idx = b * 256 + threadIdx.x;  // 0..753663
        float v; __nv_bfloat16* dst;
        if (idx < 65536) {                       // Wv [256,256]
            int n = idx >> 8, k = idx & 255; v = Wv[k * 256 + n]; dst = wtv + idx;
        } else if (idx < 163840) {               // Woa [384,256] = [Wo|Wa]
            int j = idx - 65536; int n = j >> 8, k = j & 255;
            v = (n < 256) ? Wo[k * 256 + n] : Wa[k * 128 + (n - 256)]; dst = wtoa + j;
        } else if (idx < 229376) {               // Wout [256,256]
            int j = idx - 163840; int n = j >> 8, k = j & 255; v = Wout[k * 256 + n]; dst = wtout + j;
        } else if (idx < 491520) {               // W1 [1024,256]
            int j = idx - 229376; int n = j >> 8, k = j & 255; v = W1[k * 1024 + n]; dst = wt1 + j;
        } else {                                 // W2 [256,1024]
            int j = idx - 491520; int n = j >> 10, k = j & 1023; v = W2[k * 256 + n]; dst = wt2 + j;
        }
        *dst = __float2bfloat16(v);
    } else if (b < PREP_WBLK + PREP_ABLK) {
        int idx = (b - PREP_WBLK) * 256 + threadIdx.x;   // float4 index
        float4 s = src[idx], p = pos[idx];
        __nv_bfloat162 s01 = __float22bfloat162_rn(make_float2(s.x, s.y));
        __nv_bfloat162 s23 = __float22bfloat162_rn(make_float2(s.z, s.w));
        __nv_bfloat162 q01 = __float22bfloat162_rn(make_float2(s.x + p.x, s.y + p.y));
        __nv_bfloat162 q23 = __float22bfloat162_rn(make_float2(s.z + p.z, s.w + p.w));
        ((uint2*)srcb)[idx] = make_uint2(*(uint32_t*)&s01, *(uint32_t*)&s23);
        ((uint2*)qb)[idx]   = make_uint2(*(uint32_t*)&q01, *(uint32_t*)&q23);
    } else {
        int i = threadIdx.x;
        if (i < 384) boa[i] = (i < 256) ? bo[i] : ba[i - 256];
    }
}

// ---------------------------------------------------------------------------
// Shared bf16 GEMM mainloop (128x128 tile, cp.async 3-stage + ldmatrix),
// compile-time K for full unroll; register-fragment double buffering.
// ---------------------------------------------------------------------------
#define BK 64

struct GemmCtx {
    int tid, wid, lane, g, tg, wm, wn, row0, col0;
    uint32_t sbase;
    int a_r, a_kh, b_r, b_kh;
};

__device__ __forceinline__ void load_frags(
    const GemmCtx& c, uint32_t Ab, uint32_t Bb, int ks,
    uint32_t af[4][4], uint32_t bf[4][2])
{
#pragma unroll
    for (int np = 0; np < 2; np++) {
        int r = c.wn * 32 + np * 16 + c.b_r;
        uint32_t addr = Bb + r * 128 + (((ks * 2 + c.b_kh) ^ (r & 7)) << 4);
        ldmx4(bf[np * 2][0], bf[np * 2][1], bf[np * 2 + 1][0], bf[np * 2 + 1][1], addr);
    }
#pragma unroll
    for (int mf = 0; mf < 4; mf++) {
        int r = c.wm * 64 + mf * 16 + c.a_r;
        uint32_t addr = Ab + r * 128 + (((ks * 2 + c.a_kh) ^ (r & 7)) << 4);
        ldmx4(af[mf][0], af[mf][1], af[mf][2], af[mf][3], addr);
    }
}

template<int K>
__device__ __forceinline__ void gemm_mainloop(
    GemmCtx& c, const __nv_bfloat16* __restrict__ A,
    const __nv_bfloat16* __restrict__ Wt, float acc[4][4][4])
{
#pragma unroll
    for (int i = 0; i < 4; i++)
#pragma unroll
        for (int j = 0; j < 4; j++)
#pragma unroll
            for (int k = 0; k < 4; k++) acc[i][j][k] = 0.f;

    auto load_chunk = [&](int k0, int st) {
#pragma unroll
        for (int i = 0; i < 4; i++) {
            int idx = c.tid + i * 256;
            int r = idx >> 3, gc = idx & 7;
            uint32_t so = (uint32_t)(r * 128 + ((gc ^ (r & 7)) << 4));
            cpasync16(c.sbase + st * 16384 + so, A + (size_t)(c.row0 + r) * K + k0 + gc * 8);
            cpasync16(c.sbase + 49152 + st * 16384 + so, Wt + (size_t)(c.col0 + r) * K + k0 + gc * 8);
        }
    };

    constexpr int nchunk = K / BK;
    load_chunk(0, 0);
    CP_COMMIT();
    if (nchunk > 1) load_chunk(BK, 1);
    CP_COMMIT();

    uint32_t af[2][4][4], bf[2][4][2];

#pragma unroll
    for (int ch = 0; ch < nchunk; ch++) {
        CP_WAIT1();
        __syncthreads();
        if (ch + 2 < nchunk) load_chunk((ch + 2) * BK, (ch + 2) % 3);
        CP_COMMIT();

        const uint32_t Ab = c.sbase + (ch % 3) * 16384;
        const uint32_t Bb = c.sbase + 49152 + (ch % 3) * 16384;

        load_frags(c, Ab, Bb, 0, af[0], bf[0]);
#pragma unroll
        for (int ks = 0; ks < 4; ks++) {
            const int cur = ks & 1, nx = cur ^ 1;
            if (ks < 3) load_frags(c, Ab, Bb, ks + 1, af[nx], bf[nx]);
#pragma unroll
            for (int mf = 0; mf < 4; mf++)
#pragma unroll
                for (int nf = 0; nf < 4; nf++)
                    mma_bf16(acc[mf][nf], af[cur][mf][0], af[cur][mf][1],
                             af[cur][mf][2], af[cur][mf][3],
                             bf[cur][nf][0], bf[cur][nf][1]);
        }
    }
}

__device__ __forceinline__ void gemm_init_ctx(GemmCtx& c, char* smem, int mt, int nt) {
    c.tid = threadIdx.x;
    c.wid = c.tid >> 5; c.lane = c.tid & 31;
    c.g = c.lane >> 2;  c.tg = c.lane & 3;
    c.wm = c.wid & 1;   c.wn = c.wid >> 1;
    c.row0 = mt * 128;  c.col0 = nt * 128;
    c.sbase = smem_u32(smem);
    c.a_r  = (c.lane & 7) + ((c.lane >> 3) & 1) * 8;
    c.a_kh = (c.lane >> 4) & 1;
    c.b_r  = (c.lane & 7) + ((c.lane >> 4) << 3);
    c.b_kh = (c.lane >> 3) & 1;
}

// ---------------------------------------------------------------------------
// Generic GEMM kernel (template epilogue + compile-time K).
// ---------------------------------------------------------------------------
template<int ACT, int OBF, int K>
__global__ void __launch_bounds__(256, 2)
mma_gemm(const __nv_bfloat16* __restrict__ A, const __nv_bfloat16* __restrict__ Wt,
         const float* __restrict__ bias, float* __restrict__ C,
         __nv_bfloat16* __restrict__ C16, int Nc, int mtiles)
{
    extern __shared__ char smem[];
    GemmCtx c;
    gemm_init_ctx(c, smem, blockIdx.x % mtiles, blockIdx.x / mtiles);
    float acc[4][4][4];
    gemm_mainloop<K>(c, A, Wt, acc);

#pragma unroll
    for (int mf = 0; mf < 4; mf++) {
#pragma unroll
        for (int nf = 0; nf < 4; nf++) {
            int row = c.row0 + c.wm * 64 + mf * 16 + c.g;
            int col = c.col0 + c.wn * 32 + nf * 8 + c.tg * 2;
            float b0 = bias[col], b1 = bias[col + 1];
            float o[4];
            o[0] = acc[mf][nf][0] + b0; o[1] = acc[mf][nf][1] + b1;
            o[2] = acc[mf][nf][2] + b0; o[3] = acc[mf][nf][3] + b1;
            if (ACT) {
#pragma unroll
                for (int i = 0; i < 4; i++) o[i] = fmaxf(o[i], 0.f);
            }
            if (OBF) {
                *(__nv_bfloat162*)(&C16[(size_t)row * Nc + col]) =
                    __float22bfloat162_rn(make_float2(o[0], o[1]));
                *(__nv_bfloat162*)(&C16[(size_t)(row + 8) * Nc + col]) =
                    __float22bfloat162_rn(make_float2(o[2], o[3]));
            } else {
                *(float2*)(&C[(size_t)row * Nc + col]) = make_float2(o[0], o[1]);
                *(float2*)(&C[(size_t)(row + 8) * Nc + col]) = make_float2(o[2], o[3]);
            }
        }
    }
}

// ---------------------------------------------------------------------------
// Dual GEMM: value + offsets|logits, both bf16 out, in ONE launch. K=256.
// ---------------------------------------------------------------------------
__global__ void __launch_bounds__(256, 2)
dual_gemm(const __nv_bfloat16* __restrict__ srcb, const __nv_bfloat16* __restrict__ qb,
          const __nv_bfloat16* __restrict__ wtv, const __nv_bfloat16* __restrict__ wtoa,
          const float* __restrict__ bv, const float* __restrict__ boa,
          __nv_bfloat16* __restrict__ valbf, __nv_bfloat16* __restrict__ offattnb, int mtiles)
{
    extern __shared__ char smem[];
    const int bid = blockIdx.x;
    const bool is_val = bid < mtiles * 2;
    const int local = is_val ? bid : bid - mtiles * 2;
    const int mt = local % mtiles, nt = local / mtiles;

    const __nv_bfloat16* A  = is_val ? srcb : qb;
    const __nv_bfloat16* Wt = is_val ? wtv : wtoa;
    const float* bias = is_val ? bv : boa;
    const int Nc = is_val ? 256 : 384;
    __nv_bfloat16* O = is_val ? valbf : offattnb;

    GemmCtx c;
    gemm_init_ctx(c, smem, mt, nt);
    float acc[4][4][4];
    gemm_mainloop<256>(c, A, Wt, acc);

#pragma unroll
    for (int mf = 0; mf < 4; mf++) {
#pragma unroll
        for (int nf = 0; nf < 4; nf++) {
            int row = c.row0 + c.wm * 64 + mf * 16 + c.g;
            int col = c.col0 + c.wn * 32 + nf * 8 + c.tg * 2;
            float b0 = bias[col], b1 = bias[col + 1];
            float o[4];
            o[0] = acc[mf][nf][0] + b0; o[1] = acc[mf][nf][1] + b1;
            o[2] = acc[mf][nf][2] + b0; o[3] = acc[mf][nf][3] + b1;
            *(__nv_bfloat162*)(&O[(size_t)row * Nc + col]) =
                __float22bfloat162_rn(make_float2(o[0], o[1]));
            *(__nv_bfloat162*)(&O[(size_t)(row + 8) * Nc + col]) =
                __float22bfloat162_rn(make_float2(o[2], o[3]));
        }
    }
}

// ---------------------------------------------------------------------------
// Deformable sampling, plan+gather per warp-token. Slim smem (~31.5KB/block):
// per-warp region = bf16 stage (768B) + off plan int4[8][17] (2176B) +
// cw plan bf16x4 uint2[8][17] (1088B) = 4032B. 7 blocks/SM (occ ~87%).
// ---------------------------------------------------------------------------
#define WBUF_BYTES 4032
#define WOFF_OFF   768
#define WCW_OFF    (768 + 2176)
__global__ void __launch_bounds__(256)
sample_kernel(const __nv_bfloat16* __restrict__ valbf,
              const __nv_bfloat16* __restrict__ offattnb,
              const float* __restrict__ ref,
              __nv_bfloat16* __restrict__ sampb)
{
    __shared__ __align__(16) char wbuf[8][WBUF_BYTES];

    const int w = threadIdx.x >> 5;
    const int t = blockIdx.x * 8 + w;
    const int lane = threadIdx.x & 31;
    const int n = t / LQ;

    char* base = wbuf[w];
    __nv_bfloat16* stage = (__nv_bfloat16*)base;            // 384 bf16
    int4* offp = (int4*)(base + WOFF_OFF);                  // [h*17+p]
    uint2* cwp = (uint2*)(base + WCW_OFF);                  // [h*17+p]

    // Phase 1: stage offattn row (768B bf16, coalesced).
    {
        const uint4* row = (const uint4*)(offattnb + (size_t)t * 384);   // 48 uint4
#pragma unroll
        for (int i = 0; i < 2; i++) {
            int idx = lane + i * 32;
            if (idx < 48) ((uint4*)stage)[idx] = row[idx];
        }
    }
    __syncwarp();

    // Phase 2: plan. lane -> (hh = lane>>2, l = lane&3), 4 points of level l.
    {
        const int hh = lane >> 2;
        const int l  = lane & 3;
        const int Hs_[4] = {64, 32, 16, 8};
        const int St_[4] = {0, 4096, 5120, 5376};
        const __nv_bfloat16* lp = stage + 256 + hh * 16;

        float myl[4];
#pragma unroll
        for (int k = 0; k < 4; k++) myl[k] = __bfloat162float(lp[l * 4 + k]);
        float mx = fmaxf(fmaxf(myl[0], myl[1]), fmaxf(myl[2], myl[3]));
        mx = fmaxf(mx, __shfl_xor_sync(0xffffffffu, mx, 1));
        mx = fmaxf(mx, __shfl_xor_sync(0xffffffffu, mx, 2));
        float e[4], s = 0.f;
#pragma unroll
        for (int k = 0; k < 4; k++) { e[k] = __expf(myl[k] - mx); s += e[k]; }
        s += __shfl_xor_sync(0xffffffffu, s, 1);
        s += __shfl_xor_sync(0xffffffffu, s, 2);
        const float inv = 1.f / s;

        const int HW = Hs_[l];
        const float fHW = (float)HW;
        const float invHW = 1.f / fHW;
        const float refx = ref[((size_t)t * NLVL + l) * 2 + 0];
        const float refy = ref[((size_t)t * NLVL + l) * 2 + 1];
        const __nv_bfloat16* op = stage + hh * 32 + l * 8;
        const int ebase = (n * LQ + St_[l]) * DIM + hh * HD;

#pragma unroll
        for (int k = 0; k < 4; k++) {
            float ox = __bfloat162float(op[k * 2 + 0]);
            float oy = __bfloat162float(op[k * 2 + 1]);
            float xf = (refx + ox * invHW) * fHW - 0.5f;
            float yf = (refy + oy * invHW) * fHW - 0.5f;
            float x0f = floorf(xf), y0f = floorf(yf);
            int x0 = (int)x0f, y0 = (int)y0f;
            float wx1 = xf - x0f, wy1 = yf - y0f;
            float wx0 = 1.f - wx1, wy0 = 1.f - wy1;
            float wgt = e[k] * inv;

            bool xin0 = (x0 >= 0) & (x0 < HW);
            bool xin1 = (x0 + 1 >= 0) & (x0 + 1 < HW);
            bool yin0 = (y0 >= 0) & (y0 < HW);
            bool yin1 = (y0 + 1 >= 0) & (y0 + 1 < HW);

            float c00 = (yin0 && xin0) ? wgt * wy0 * wx0 : 0.f;
            float c01 = (yin0 && xin1) ? wgt * wy0 * wx1 : 0.f;
            float c10 = (yin1 && xin0) ? wgt * wy1 * wx0 : 0.f;
            float c11 = (yin1 && xin1) ? wgt * wy1 * wx1 : 0.f;
            int line = y0 * HW + x0;
            int4 off;
            off.x = (yin0 && xin0) ? (ebase + line * DIM) * 2 : 0;
            off.y = (yin0 && xin1) ? (ebase + (line + 1) * DIM) * 2 : 0;
            off.z = (yin1 && xin0) ? (ebase + (line + HW) * DIM) * 2 : 0;
            off.w = (yin1 && xin1) ? (ebase + (line + HW + 1) * DIM) * 2 : 0;

            __nv_bfloat162 cb0 = __float22bfloat162_rn(make_float2(c00, c01));
            __nv_bfloat162 cb1 = __float22bfloat162_rn(make_float2(c10, c11));
            offp[hh * 17 + l * 4 + k] = off;
            cwp[hh * 17 + l * 4 + k] = make_uint2(*(uint32_t*)&cb0, *(uint32_t*)&cb1);
        }
    }
    __syncwarp();

    // Phase 3: gather. lane -> (h = lane>>2, d8 = lane&3).
    const int h = lane >> 2;
    const int d8 = lane & 3;
    const char* vbase = (const char*)valbf + d8 * 16;

    float acc[8];
#pragma unroll
    for (int i = 0; i < 8; i++) acc[i] = 0.f;

#pragma unroll 4
    for (int p = 0; p < 16; p++) {
        int4 off = offp[h * 17 + p];
        uint2 cwu = cwp[h * 17 + p];
        float2 cA = __bfloat1622float2(*(__nv_bfloat162*)&cwu.x);
        float2 cB = __bfloat1622float2(*(__nv_bfloat162*)&cwu.y);
        const int o4[4] = { off.x, off.y, off.z, off.w };
        const float c4[4] = { cA.x, cA.y, cB.x, cB.y };
#pragma unroll
        for (int cnr = 0; cnr < 4; cnr++) {
            uint4 u = *(const uint4*)(vbase + o4[cnr]);
            const __nv_bfloat162* q2 = (const __nv_bfloat162*)&u;
            float cc = c4[cnr];
#pragma unroll
            for (int j = 0; j < 4; j++) {
                float2 f = __bfloat1622float2(q2[j]);
                acc[2 * j + 0] = fmaf(f.x, cc, acc[2 * j + 0]);
                acc[2 * j + 1] = fmaf(f.y, cc, acc[2 * j + 1]);
            }
        }
    }
    __nv_bfloat162 ob[4];
#pragma unroll
    for (int j = 0; j < 4; j++)
        ob[j] = __float22bfloat162_rn(make_float2(acc[2 * j], acc[2 * j + 1]));
    *(uint4*)(sampb + (size_t)t * DIM + h * HD + d8 * 8) = *(uint4*)ob;
}

// ---------------------------------------------------------------------------
// LayerNorm over 256 (vectorized): out = LN(a + b) * g + beta.
// One warp per token; 8 tokens per 256-thread block.
// ---------------------------------------------------------------------------
__global__ void __launch_bounds__(256)
ln_kernel(const float* __restrict__ a, const __nv_bfloat16* __restrict__ b,
          const float* __restrict__ g, const float* __restrict__ beta,
          float* __restrict__ out, __nv_bfloat16* __restrict__ out_b)
{
    const int t = blockIdx.x * 8 + (threadIdx.x >> 5);
    const int lane = threadIdx.x & 31;
    const int c0 = lane * 8;
    const float4* pa = (const float4*)(a + (size_t)t * DIM + c0);
    const uint4   ub = *(const uint4*)(b + (size_t)t * DIM + c0);

    float4 a0 = pa[0], a1 = pa[1];
    const __nv_bfloat162* b2 = (const __nv_bfloat162*)&ub;
    float v[8];
    {
        float2 f0 = __bfloat1622float2(b2[0]);
        float2 f1 = __bfloat1622float2(b2[1]);
        float2 f2 = __bfloat1622float2(b2[2]);
        float2 f3 = __bfloat1622float2(b2[3]);
        v[0] = a0.x + f0.x; v[1] = a0.y + f0.y;
        v[2] = a0.z + f1.x; v[3] = a0.w + f1.y;
        v[4] = a1.x + f2.x; v[5] = a1.y + f2.y;
        v[6] = a1.z + f3.x; v[7] = a1.w + f3.y;
    }
    float s = 0.f;
#pragma unroll
    for (int i = 0; i < 8; i++) s += v[i];
#pragma unroll
    for (int o = 16; o; o >>= 1) s += __shfl_xor_sync(0xffffffffu, s, o);
    const float mean = s * (1.f / 256.f);
    float var = 0.f;
#pragma unroll
    for (int i = 0; i < 8; i++) { float dd = v[i] - mean; var += dd * dd; }
#pragma unroll
    for (int o = 16; o; o >>= 1) var += __shfl_xor_sync(0xffffffffu, var, o);
    const float rstd = rsqrtf(var * (1.f / 256.f) + 1e-5f);

    const float4* pg = (const float4*)(g + c0);
    const float4* pe = (const float4*)(beta + c0);
    float4 g0 = pg[0], g1 = pg[1], e0 = pe[0], e1 = pe[1];
    float y[8];
    y[0] = (v[0] - mean) * rstd * g0.x + e0.x;
    y[1] = (v[1] - mean) * rstd * g0.y + e0.y;
    y[2] = (v[2] - mean) * rstd * g0.z + e0.z;
    y[3] = (v[3] - mean) * rstd * g0.w + e0.w;
    y[4] = (v[4] - mean) * rstd * g1.x + e1.x;
    y[5] = (v[5] - mean) * rstd * g1.y + e1.y;
    y[6] = (v[6] - mean) * rstd * g1.z + e1.z;
    y[7] = (v[7] - mean) * rstd * g1.w + e1.w;

    float4* po = (float4*)(out + (size_t)t * DIM + c0);
    po[0] = make_float4(y[0], y[1], y[2], y[3]);
    po[1] = make_float4(y[4], y[5], y[6], y[7]);
    if (out_b) {
        __nv_bfloat162 ob[4];
        ob[0] = __float22bfloat162_rn(make_float2(y[0], y[1]));
        ob[1] = __float22bfloat162_rn(make_float2(y[2], y[3]));
        ob[2] = __float22bfloat162_rn(make_float2(y[4], y[5]));
        ob[3] = __float22bfloat162_rn(make_float2(y[6], y[7]));
        *(uint4*)(out_b + (size_t)t * DIM + c0) = *(uint4*)ob;
    }
}

// ---------------------------------------------------------------------------
extern "C" void kernel_launch(void* const* d_in, const int* in_sizes, int n_in,
                              void* d_out, int out_size)
{
    const float* src  = (const float*)d_in[0];
    const float* pos  = (const float*)d_in[1];
    const float* refp = (const float*)d_in[2];
    const float* Wv   = (const float*)d_in[4];
    const float* bv   = (const float*)d_in[5];
    const float* Wo   = (const float*)d_in[6];
    const float* bo   = (const float*)d_in[7];
    const float* Wa   = (const float*)d_in[8];
    const float* ba   = (const float*)d_in[9];
    const float* Wout = (const float*)d_in[10];
    const float* bout = (const float*)d_in[11];
    const float* g1   = (const float*)d_in[12];
    const float* be1  = (const float*)d_in[13];
    const float* W1   = (const float*)d_in[14];
    const float* b1   = (const float*)d_in[15];
    const float* W2   = (const float*)d_in[16];
    const float* b2   = (const float*)d_in[17];
    const float* g2   = (const float*)d_in[18];
    const float* be2  = (const float*)d_in[19];
    float* out = (float*)d_out;

    __nv_bfloat16 *psrcb, *pqb, *pvb, *poab, *psampb, *psrc2b, *pxb, *phidb, *pffnb;
    __nv_bfloat16 *wtv, *wtoa, *wtout, *wt1, *wt2;
    float *px, *pboa;
    cudaGetSymbolAddress((void**)&psrcb, g_srcb);
    cudaGetSymbolAddress((void**)&pqb,   g_qb);
    cudaGetSymbolAddress((void**)&pvb,   g_valbf);
    cudaGetSymbolAddress((void**)&poab,  g_offattnb);
    cudaGetSymbolAddress((void**)&psampb,g_sampb);
    cudaGetSymbolAddress((void**)&psrc2b,g_src2b);
    cudaGetSymbolAddress((void**)&px,    g_x);
    cudaGetSymbolAddress((void**)&pxb,   g_xb);
    cudaGetSymbolAddress((void**)&phidb, g_hidb);
    cudaGetSymbolAddress((void**)&pffnb, g_ffnb);
    cudaGetSymbolAddress((void**)&wtv,   g_wtv);
    cudaGetSymbolAddress((void**)&wtoa,  g_wtoa);
    cudaGetSymbolAddress((void**)&wtout, g_wtout);
    cudaGetSymbolAddress((void**)&wt1,   g_wt1);
    cudaGetSymbolAddress((void**)&wt2,   g_wt2);
    cudaGetSymbolAddress((void**)&pboa,  g_boa);

    const int DSM = 98304;  // 3 stages x (16KB A + 16KB B)
    cudaFuncSetAttribute(mma_gemm<0,1,256>,  cudaFuncAttributeMaxDynamicSharedMemorySize, DSM);
    cudaFuncSetAttribute(mma_gemm<1,1,256>,  cudaFuncAttributeMaxDynamicSharedMemorySize, DSM);
    cudaFuncSetAttribute(mma_gemm<0,1,1024>, cudaFuncAttributeMaxDynamicSharedMemorySize, DSM);
    cudaFuncSetAttribute(dual_gemm,          cudaFuncAttributeMaxDynamicSharedMemorySize, DSM);

    // One-shot prep
    prep_kernel<<<PREP_WBLK + PREP_ABLK + 1, 256>>>(
        Wv, Wo, Wa, Wout, W1, W2, bo, ba,
        (const float4*)src, (const float4*)pos,
        wtv, wtoa, wtout, wt1, wt2, pboa, psrcb, pqb);

    const int MT = TTOK / 128;  // 340 M-tiles

    // value (bf16) + offsets|logits (bf16) fused in ONE launch
    dual_gemm<<<MT * 5, 256, DSM>>>(psrcb, pqb, wtv, wtoa, bv, pboa, pvb, poab, MT);
    // deformable sampling (softmax fused; bf16 out)
    sample_kernel<<<TTOK / 8, 256>>>(pvb, poab, refp, psampb);
    // src2 (bf16) = samp @ Wout + bout
    mma_gemm<0,1,256><<<MT * 2, 256, DSM>>>(psampb, wtout, bout, nullptr, psrc2b, 256, MT);
    // x = LN1(src + src2)  (fp32 + bf16 copies)
    ln_kernel<<<TTOK / 8, 256>>>(src, psrc2b, g1, be1, px, pxb);
    // hid (bf16) = relu(x @ W1 + b1)
    mma_gemm<1,1,256><<<MT * 8, 256, DSM>>>(pxb, wt1, b1, nullptr, phidb, 1024, MT);
    // ffn (bf16) = hid @ W2 + b2
    mma_gemm<0,1,1024><<<MT * 2, 256, DSM>>>(phidb, wt2, b2, nullptr, pffnb, 256, MT);
    // out = LN2(x + ffn)
    ln_kernel<<<TTOK / 8, 256>>>(px, pffnb, g2, be2, out, nullptr);
}